// round 6
// baseline (speedup 1.0000x reference)
#include <cuda_runtime.h>
#include <cuda_bf16.h>
#include <math.h>
#include <stdint.h>

#define BB  2
#define SS  2048
#define HH  4096
#define NH  32
#define NKV 8
#define HD  128
#define MR  (BB * SS)      // 4096 rows
#define QD  (NH * HD)      // 4096
#define KVD (NKV * HD)     // 1024

// ---------------- scratch (device globals; no runtime allocation) ----------
__device__ float g_q[MR * QD];
__device__ float g_k[MR * KVD];
__device__ float g_v[MR * KVD];

__device__ __nv_bfloat16 g_hs_h[MR * HH];
__device__ __nv_bfloat16 g_hs_l[MR * HH];
__device__ __nv_bfloat16 g_wqT_h[QD * HH];
__device__ __nv_bfloat16 g_wqT_l[QD * HH];
__device__ __nv_bfloat16 g_wkT_h[KVD * HH];
__device__ __nv_bfloat16 g_wkT_l[KVD * HH];
__device__ __nv_bfloat16 g_wvT_h[KVD * HH];
__device__ __nv_bfloat16 g_wvT_l[KVD * HH];
__device__ __nv_bfloat16 g_woT_h[HH * QD];
__device__ __nv_bfloat16 g_woT_l[HH * QD];
__device__ __nv_bfloat16 g_att_h[MR * QD];
__device__ __nv_bfloat16 g_att_l[MR * QD];

// attention operands (post-RoPE, hi/lo split)
__device__ __nv_bfloat16 g_qr_h[MR * QD];
__device__ __nv_bfloat16 g_qr_l[MR * QD];
__device__ __nv_bfloat16 g_kr_h[MR * KVD];
__device__ __nv_bfloat16 g_kr_l[MR * KVD];
__device__ __nv_bfloat16 g_vr_h[MR * KVD];
__device__ __nv_bfloat16 g_vr_l[MR * KVD];

// ---------------- PTX helpers ----------------------------------------------
__device__ __forceinline__ uint32_t smem_u32(const void* p) {
    uint32_t a;
    asm("{ .reg .u64 t; cvta.to.shared.u64 t, %1; cvt.u32.u64 %0, t; }"
        : "=r"(a) : "l"(p));
    return a;
}
__device__ __forceinline__ void cpasync16(uint32_t dst, const void* src) {
    asm volatile("cp.async.cg.shared.global [%0], [%1], 16;"
                 :: "r"(dst), "l"(src));
}
#define CP_COMMIT() asm volatile("cp.async.commit_group;" ::: "memory")
#define CP_WAIT0()  asm volatile("cp.async.wait_group 0;" ::: "memory")
#define CP_WAIT1()  asm volatile("cp.async.wait_group 1;" ::: "memory")

#define LDSM4(r0, r1, r2, r3, addr) \
    asm volatile("ldmatrix.sync.aligned.m8n8.x4.shared.b16 {%0,%1,%2,%3}, [%4];" \
                 : "=r"(r0), "=r"(r1), "=r"(r2), "=r"(r3) : "r"(addr))

#define LDSM4T(r0, r1, r2, r3, addr) \
    asm volatile("ldmatrix.sync.aligned.m8n8.x4.trans.shared.b16 {%0,%1,%2,%3}, [%4];" \
                 : "=r"(r0), "=r"(r1), "=r"(r2), "=r"(r3) : "r"(addr))

#define MMA_BF16(c, a, b) \
    asm volatile("mma.sync.aligned.m16n8k16.row.col.f32.bf16.bf16.f32 " \
                 "{%0,%1,%2,%3}, {%4,%5,%6,%7}, {%8,%9}, {%0,%1,%2,%3};" \
                 : "+f"((c)[0]), "+f"((c)[1]), "+f"((c)[2]), "+f"((c)[3]) \
                 : "r"((a)[0]), "r"((a)[1]), "r"((a)[2]), "r"((a)[3]), \
                   "r"((b)[0]), "r"((b)[1]))

__device__ __forceinline__ void split2(float x, float y, uint32_t& h, uint32_t& l) {
    __nv_bfloat162 hb = __floats2bfloat162_rn(x, y);
    float2 hf = __bfloat1622float2(hb);
    __nv_bfloat162 lb = __floats2bfloat162_rn(x - hf.x, y - hf.y);
    h = *reinterpret_cast<uint32_t*>(&hb);
    l = *reinterpret_cast<uint32_t*>(&lb);
}

// ---------------------------------------------------------------------------
// fp32 -> bf16 hi/lo split (elementwise, vectorized by 4)
// ---------------------------------------------------------------------------
__global__ void split_kernel(const float* __restrict__ src,
                             __nv_bfloat16* __restrict__ hi,
                             __nv_bfloat16* __restrict__ lo, int n4) {
    int i = blockIdx.x * blockDim.x + threadIdx.x;
    if (i >= n4) return;
    float4 s = ((const float4*)src)[i];
    __nv_bfloat162 h01 = __floats2bfloat162_rn(s.x, s.y);
    __nv_bfloat162 h23 = __floats2bfloat162_rn(s.z, s.w);
    float2 f01 = __bfloat1622float2(h01);
    float2 f23 = __bfloat1622float2(h23);
    __nv_bfloat162 l01 = __floats2bfloat162_rn(s.x - f01.x, s.y - f01.y);
    __nv_bfloat162 l23 = __floats2bfloat162_rn(s.z - f23.x, s.w - f23.y);
    ((__nv_bfloat162*)hi)[2 * i]     = h01;
    ((__nv_bfloat162*)hi)[2 * i + 1] = h23;
    ((__nv_bfloat162*)lo)[2 * i]     = l01;
    ((__nv_bfloat162*)lo)[2 * i + 1] = l23;
}

// ---------------------------------------------------------------------------
// Weight transpose + split: W[K,N] fp32 -> hiT/loT [N,K] bf16
// ---------------------------------------------------------------------------
__global__ void split_transpose(const float* __restrict__ W,
                                __nv_bfloat16* __restrict__ hiT,
                                __nv_bfloat16* __restrict__ loT, int K, int N) {
    __shared__ float t[32][33];
    int n0 = blockIdx.x * 32, k0 = blockIdx.y * 32;
    int tx = threadIdx.x, ty = threadIdx.y;
#pragma unroll
    for (int i = 0; i < 32; i += 8)
        t[ty + i][tx] = W[(size_t)(k0 + ty + i) * N + n0 + tx];
    __syncthreads();
#pragma unroll
    for (int i = 0; i < 32; i += 8) {
        float v = t[tx][ty + i];
        __nv_bfloat16 h = __float2bfloat16_rn(v);
        __nv_bfloat16 l = __float2bfloat16_rn(v - __bfloat162float(h));
        size_t o = (size_t)(n0 + ty + i) * K + k0 + tx;
        hiT[o] = h;
        loT[o] = l;
    }
}

// ---------------------------------------------------------------------------
// mma.sync bf16x3 GEMM: C[M,N] = A[M,K] @ BT[N,K]^T  (fp32-accurate)
// ---------------------------------------------------------------------------
#define TILE_B   10240
#define STAGE_B  (4 * TILE_B)
#define GEMM_SMEM (2 * STAGE_B)

__global__ __launch_bounds__(256, 1)
void mma_gemm(const __nv_bfloat16* __restrict__ Ahi,
              const __nv_bfloat16* __restrict__ Alo,
              const __nv_bfloat16* __restrict__ Bhi,
              const __nv_bfloat16* __restrict__ Blo,
              float* __restrict__ C, int Nd, int Kd) {
    extern __shared__ char smem[];
    const uint32_t sb = smem_u32(smem);
    const int tid = threadIdx.x;
    const int wid = tid >> 5, lid = tid & 31;
    const int wm = wid >> 2, wn = wid & 3;
    const int bn = blockIdx.x * 128, bm = blockIdx.y * 128;

    float c[4][4][4];
#pragma unroll
    for (int i = 0; i < 4; i++)
#pragma unroll
        for (int j = 0; j < 4; j++)
#pragma unroll
            for (int q = 0; q < 4; q++) c[i][j][q] = 0.f;

    const int rowA = lid & 15;
    const int khA  = (lid >> 4) << 3;
    const int nB   = ((lid >> 4) << 3) + (lid & 7);
    const int khB  = ((lid >> 3) & 1) << 3;

#define LOAD_STAGE(s, k0)                                                     \
    do {                                                                      \
        _Pragma("unroll")                                                     \
        for (int li = 0; li < 2; li++) {                                      \
            int id  = li * 256 + tid;                                         \
            int row = id >> 2, seg = id & 3;                                  \
            uint32_t so = sb + (s) * STAGE_B + row * 80 + seg * 16;           \
            size_t ga = (size_t)(bm + row) * Kd + (k0) + seg * 8;             \
            size_t gb = (size_t)(bn + row) * Kd + (k0) + seg * 8;             \
            cpasync16(so,              Ahi + ga);                             \
            cpasync16(so + TILE_B,     Alo + ga);                             \
            cpasync16(so + 2 * TILE_B, Bhi + gb);                             \
            cpasync16(so + 3 * TILE_B, Blo + gb);                             \
        }                                                                     \
        CP_COMMIT();                                                          \
    } while (0)

    const int nk = Kd >> 5;
    LOAD_STAGE(0, 0);

    for (int kt = 0; kt < nk; kt++) {
        CP_WAIT0();
        __syncthreads();
        if (kt + 1 < nk) LOAD_STAGE((kt + 1) & 1, (kt + 1) << 5);

        const uint32_t abase = sb + (kt & 1) * STAGE_B;
        const uint32_t bbase = abase + 2 * TILE_B;
#pragma unroll
        for (int kk = 0; kk < 32; kk += 16) {
            uint32_t bh[4][2], bl[4][2];
#pragma unroll
            for (int j2 = 0; j2 < 2; j2++) {
                uint32_t ba = bbase + (wn * 32 + j2 * 16 + nB) * 80 +
                              (kk + khB) * 2;
                LDSM4(bh[j2 * 2][0], bh[j2 * 2][1],
                      bh[j2 * 2 + 1][0], bh[j2 * 2 + 1][1], ba);
                LDSM4(bl[j2 * 2][0], bl[j2 * 2][1],
                      bl[j2 * 2 + 1][0], bl[j2 * 2 + 1][1], ba + TILE_B);
            }
#pragma unroll
            for (int i = 0; i < 4; i++) {
                uint32_t aa = abase + (wm * 64 + i * 16 + rowA) * 80 +
                              (kk + khA) * 2;
                uint32_t ah[4], al[4];
                LDSM4(ah[0], ah[1], ah[2], ah[3], aa);
                LDSM4(al[0], al[1], al[2], al[3], aa + TILE_B);
#pragma unroll
                for (int j = 0; j < 4; j++) {
                    MMA_BF16(c[i][j], ah, bh[j]);
                    MMA_BF16(c[i][j], ah, bl[j]);
                    MMA_BF16(c[i][j], al, bh[j]);
                }
            }
        }
        __syncthreads();
    }
#undef LOAD_STAGE

    const int g = lid >> 2, t4 = lid & 3;
#pragma unroll
    for (int i = 0; i < 4; i++) {
        int r0 = bm + wm * 64 + i * 16 + g;
#pragma unroll
        for (int j = 0; j < 4; j++) {
            int col = bn + wn * 32 + j * 8 + t4 * 2;
            *(float2*)&C[(size_t)r0 * Nd + col] =
                make_float2(c[i][j][0], c[i][j][1]);
            *(float2*)&C[(size_t)(r0 + 8) * Nd + col] =
                make_float2(c[i][j][2], c[i][j][3]);
        }
    }
}

// ---------------------------------------------------------------------------
// Fused RoPE + bf16 hi/lo split. pos = row % SS.
// ---------------------------------------------------------------------------
__global__ void rope_split(const float* __restrict__ buf,
                           __nv_bfloat16* __restrict__ oh,
                           __nv_bfloat16* __restrict__ ol, int nheads) {
    int idx = blockIdx.x * blockDim.x + threadIdx.x;
    int total = MR * nheads * 64;
    if (idx >= total) return;
    int i    = idx & 63;
    int head = (idx >> 6) % nheads;
    int row  = idx / (nheads << 6);

    float p    = (float)(row % SS);
    float invf = expf(-(float)i * 0.14391156831212787f);
    float ang  = p * invf;
    float c, s;
    sincosf(ang, &s, &c);

    size_t base = (size_t)row * (nheads * HD) + head * HD + i;
    float x0 = buf[base];
    float x1 = buf[base + 64];
    float y0 = x0 * c - x1 * s;
    float y1 = x1 * c + x0 * s;

    __nv_bfloat16 h0 = __float2bfloat16_rn(y0);
    __nv_bfloat16 h1 = __float2bfloat16_rn(y1);
    oh[base]      = h0;
    oh[base + 64] = h1;
    ol[base]      = __float2bfloat16_rn(y0 - __bfloat162float(h0));
    ol[base + 64] = __float2bfloat16_rn(y1 - __bfloat162float(h1));
}

// ---------------------------------------------------------------------------
// Tensor-core causal flash attention, bf16x3, fp32 softmax.
// CTA: 128 q-rows x 1 head, 256 threads = 8 warps x 16 rows.
// K/V double-buffered (64-row tiles) to overlap loads with HMMA.
// Epilogue writes bf16 hi/lo directly (fused output split).
// ---------------------------------------------------------------------------
#define APITCH 272
#define ATQ   (128 * APITCH)         // 34816: one 128-row tile
#define ATK   (64 * APITCH)          // 17408: one 64-row tile
#define SKV   (4 * ATK)              // Kh Kl Vh Vl per stage
#define ATTN_SMEM (2 * ATQ + 2 * SKV)  // 208896

__global__ __launch_bounds__(256, 1)
void attn_mma(const __nv_bfloat16* __restrict__ Qh, const __nv_bfloat16* __restrict__ Ql,
              const __nv_bfloat16* __restrict__ Kh, const __nv_bfloat16* __restrict__ Kl,
              const __nv_bfloat16* __restrict__ Vh, const __nv_bfloat16* __restrict__ Vl,
              __nv_bfloat16* __restrict__ Oh, __nv_bfloat16* __restrict__ Ol) {
    extern __shared__ char smem[];
    const uint32_t sb = smem_u32(smem);
    const int tid = threadIdx.x;
    const int wid = tid >> 5, lid = tid & 31;
    const int g = lid >> 2, t4 = lid & 3;
    const int qb = gridDim.x - 1 - blockIdx.x;   // big tiles first
    const int h = blockIdx.y, b = blockIdx.z;
    const int kvh = h >> 2;
    const int q0 = qb * 128;

    const uint32_t sQh = sb, sQl = sb + ATQ;
    const uint32_t kvbase = sb + 2 * ATQ;

    // Q tile load (once): 128 rows x 16 segs, hi+lo
#pragma unroll
    for (int t = 0; t < 8; t++) {
        int id = t * 256 + tid;
        int row = id >> 4, seg = id & 15;
        uint32_t so = row * APITCH + seg * 16;
        size_t gq = (size_t)(b * SS + q0 + row) * QD + h * HD + seg * 8;
        cpasync16(sQh + so, Qh + gq);
        cpasync16(sQl + so, Ql + gq);
    }
    CP_COMMIT();

#define LOAD_KV(s, kt)                                                        \
    do {                                                                      \
        _Pragma("unroll")                                                     \
        for (int t = 0; t < 4; t++) {                                         \
            int id = t * 256 + tid;                                           \
            int row = id >> 4, seg = id & 15;                                 \
            uint32_t so = kvbase + (s) * SKV + row * APITCH + seg * 16;       \
            size_t gk = (size_t)(b * SS + (kt) * 64 + row) * KVD +            \
                        kvh * HD + seg * 8;                                   \
            cpasync16(so,           Kh + gk);                                 \
            cpasync16(so + ATK,     Kl + gk);                                 \
            cpasync16(so + 2 * ATK, Vh + gk);                                 \
            cpasync16(so + 3 * ATK, Vl + gk);                                 \
        }                                                                     \
        CP_COMMIT();                                                          \
    } while (0)

    float o[16][4];
#pragma unroll
    for (int n = 0; n < 16; n++)
#pragma unroll
        for (int q = 0; q < 4; q++) o[n][q] = 0.f;
    float m[2] = {-1e30f, -1e30f}, l[2] = {0.f, 0.f};

    const int rowA = lid & 15, khA = (lid >> 4) << 3;
    const int nB = ((lid >> 4) << 3) + (lid & 7);
    const int khB = ((lid >> 3) & 1) << 3;
    const int kV = (((lid >> 3) & 1) << 3) + (lid & 7);
    const int nVo = (lid >> 4) << 3;
    const int q0w = q0 + wid * 16;

    const float scale = 0.08838834764831845f;
    const int nkt = 2 * qb + 2;

    LOAD_KV(0, 0);

    for (int kt = 0; kt < nkt; kt++) {
        if (kt + 1 < nkt) {
            LOAD_KV((kt + 1) & 1, kt + 1);
            CP_WAIT1();
        } else {
            CP_WAIT0();
        }
        __syncthreads();

        const uint32_t sKh = kvbase + (kt & 1) * SKV;
        const uint32_t sKl = sKh + ATK;
        const uint32_t sVh = sKh + 2 * ATK;
        const uint32_t sVl = sKh + 3 * ATK;
        const int k0t = kt * 64;

        // ---- S = Q K^T (bf16x3) ----
        float sc[8][4];
#pragma unroll
        for (int j = 0; j < 8; j++)
#pragma unroll
            for (int q = 0; q < 4; q++) sc[j][q] = 0.f;

#pragma unroll
        for (int kk = 0; kk < 8; kk++) {
            uint32_t qhf[4], qlf[4];
            uint32_t qa = sQh + (wid * 16 + rowA) * APITCH + (kk * 16 + khA) * 2;
            LDSM4(qhf[0], qhf[1], qhf[2], qhf[3], qa);
            LDSM4(qlf[0], qlf[1], qlf[2], qlf[3], qa + ATQ);
#pragma unroll
            for (int jp = 0; jp < 4; jp++) {
                uint32_t kh0[2], kh1[2], kl0[2], kl1[2];
                uint32_t ka = sKh + (jp * 16 + nB) * APITCH + (kk * 16 + khB) * 2;
                LDSM4(kh0[0], kh0[1], kh1[0], kh1[1], ka);
                LDSM4(kl0[0], kl0[1], kl1[0], kl1[1], ka + ATK);
                MMA_BF16(sc[2 * jp],     qhf, kh0);
                MMA_BF16(sc[2 * jp + 1], qhf, kh1);
                MMA_BF16(sc[2 * jp],     qhf, kl0);
                MMA_BF16(sc[2 * jp + 1], qhf, kl1);
                MMA_BF16(sc[2 * jp],     qlf, kh0);
                MMA_BF16(sc[2 * jp + 1], qlf, kh1);
            }
        }

        // scale + causal mask
#pragma unroll
        for (int j = 0; j < 8; j++)
#pragma unroll
            for (int q = 0; q < 4; q++) sc[j][q] *= scale;
        if (k0t + 63 > q0w) {
            int r0 = q0w + g, r1 = r0 + 8;
#pragma unroll
            for (int j = 0; j < 8; j++) {
                int c0 = k0t + j * 8 + 2 * t4, c1 = c0 + 1;
                if (c0 > r0) sc[j][0] = -1e30f;
                if (c1 > r0) sc[j][1] = -1e30f;
                if (c0 > r1) sc[j][2] = -1e30f;
                if (c1 > r1) sc[j][3] = -1e30f;
            }
        }

        // ---- online softmax ----
#pragma unroll
        for (int r = 0; r < 2; r++) {
            float mx = -1e30f;
#pragma unroll
            for (int j = 0; j < 8; j++)
                mx = fmaxf(mx, fmaxf(sc[j][2 * r], sc[j][2 * r + 1]));
            mx = fmaxf(mx, __shfl_xor_sync(0xffffffffu, mx, 1));
            mx = fmaxf(mx, __shfl_xor_sync(0xffffffffu, mx, 2));
            float mn = fmaxf(m[r], mx);
            float corr = __expf(m[r] - mn);
            float rs = 0.f;
#pragma unroll
            for (int j = 0; j < 8; j++) {
                float p0 = __expf(sc[j][2 * r] - mn);
                float p1 = __expf(sc[j][2 * r + 1] - mn);
                sc[j][2 * r] = p0;
                sc[j][2 * r + 1] = p1;
                rs += p0 + p1;
            }
            rs += __shfl_xor_sync(0xffffffffu, rs, 1);
            rs += __shfl_xor_sync(0xffffffffu, rs, 2);
            l[r] = l[r] * corr + rs;
            m[r] = mn;
#pragma unroll
            for (int n = 0; n < 16; n++) {
                o[n][2 * r] *= corr;
                o[n][2 * r + 1] *= corr;
            }
        }

        // ---- O += P V (bf16x3, P in registers) ----
#pragma unroll
        for (int j2 = 0; j2 < 4; j2++) {
            uint32_t ah[4], al[4];
            split2(sc[2 * j2][0],     sc[2 * j2][1],     ah[0], al[0]);
            split2(sc[2 * j2][2],     sc[2 * j2][3],     ah[1], al[1]);
            split2(sc[2 * j2 + 1][0], sc[2 * j2 + 1][1], ah[2], al[2]);
            split2(sc[2 * j2 + 1][2], sc[2 * j2 + 1][3], ah[3], al[3]);
#pragma unroll
            for (int np = 0; np < 8; np++) {
                uint32_t vh0[2], vh1[2], vl0[2], vl1[2];
                uint32_t va = sVh + (j2 * 16 + kV) * APITCH + (np * 16 + nVo) * 2;
                LDSM4T(vh0[0], vh0[1], vh1[0], vh1[1], va);
                LDSM4T(vl0[0], vl0[1], vl1[0], vl1[1], va + ATK);
                MMA_BF16(o[2 * np],     ah, vh0);
                MMA_BF16(o[2 * np + 1], ah, vh1);
                MMA_BF16(o[2 * np],     ah, vl0);
                MMA_BF16(o[2 * np + 1], ah, vl1);
                MMA_BF16(o[2 * np],     al, vh0);
                MMA_BF16(o[2 * np + 1], al, vh1);
            }
        }
        __syncthreads();
    }
#undef LOAD_KV

    // ---- finalize: normalize + hi/lo split + store ----
    float inv0 = 1.f / l[0], inv1 = 1.f / l[1];
    size_t r0g = (size_t)(b * SS + q0 + wid * 16 + g) * QD + h * HD;
    size_t r1g = r0g + 8 * QD;
#pragma unroll
    for (int n = 0; n < 16; n++) {
        int col = n * 8 + 2 * t4;
        uint32_t hh, ll;
        split2(o[n][0] * inv0, o[n][1] * inv0, hh, ll);
        *(uint32_t*)&Oh[r0g + col] = hh;
        *(uint32_t*)&Ol[r0g + col] = ll;
        split2(o[n][2] * inv1, o[n][3] * inv1, hh, ll);
        *(uint32_t*)&Oh[r1g + col] = hh;
        *(uint32_t*)&Ol[r1g + col] = ll;
    }
}

// ---------------------------------------------------------------------------
extern "C" void kernel_launch(void* const* d_in, const int* in_sizes, int n_in,
                              void* d_out, int out_size) {
    const float* hs  = (const float*)d_in[0];
    const float* Wq  = (const float*)d_in[2];
    const float* Wk  = (const float*)d_in[3];
    const float* Wv  = (const float*)d_in[4];
    const float* Wo  = (const float*)d_in[5];
    float*       out = (float*)d_out;

    float *qb, *kb, *vb;
    cudaGetSymbolAddress((void**)&qb, g_q);
    cudaGetSymbolAddress((void**)&kb, g_k);
    cudaGetSymbolAddress((void**)&vb, g_v);

    __nv_bfloat16 *hsh, *hsl, *wqh, *wql, *wkh, *wkl, *wvh, *wvl, *woh, *wol, *ath, *atl;
    __nv_bfloat16 *qrh, *qrl, *krh, *krl, *vrh, *vrl;
    cudaGetSymbolAddress((void**)&hsh, g_hs_h);
    cudaGetSymbolAddress((void**)&hsl, g_hs_l);
    cudaGetSymbolAddress((void**)&wqh, g_wqT_h);
    cudaGetSymbolAddress((void**)&wql, g_wqT_l);
    cudaGetSymbolAddress((void**)&wkh, g_wkT_h);
    cudaGetSymbolAddress((void**)&wkl, g_wkT_l);
    cudaGetSymbolAddress((void**)&wvh, g_wvT_h);
    cudaGetSymbolAddress((void**)&wvl, g_wvT_l);
    cudaGetSymbolAddress((void**)&woh, g_woT_h);
    cudaGetSymbolAddress((void**)&wol, g_woT_l);
    cudaGetSymbolAddress((void**)&ath, g_att_h);
    cudaGetSymbolAddress((void**)&atl, g_att_l);
    cudaGetSymbolAddress((void**)&qrh, g_qr_h);
    cudaGetSymbolAddress((void**)&qrl, g_qr_l);
    cudaGetSymbolAddress((void**)&krh, g_kr_h);
    cudaGetSymbolAddress((void**)&krl, g_kr_l);
    cudaGetSymbolAddress((void**)&vrh, g_vr_h);
    cudaGetSymbolAddress((void**)&vrl, g_vr_l);

    cudaFuncSetAttribute(mma_gemm, cudaFuncAttributeMaxDynamicSharedMemorySize, GEMM_SMEM);
    cudaFuncSetAttribute(attn_mma, cudaFuncAttributeMaxDynamicSharedMemorySize, ATTN_SMEM);

    // split inputs to bf16 hi/lo
    split_kernel<<<(MR * HH / 4 + 255) / 256, 256>>>(hs, hsh, hsl, MR * HH / 4);
    split_transpose<<<dim3(QD / 32, HH / 32), dim3(32, 8)>>>(Wq, wqh, wql, HH, QD);
    split_transpose<<<dim3(KVD / 32, HH / 32), dim3(32, 8)>>>(Wk, wkh, wkl, HH, KVD);
    split_transpose<<<dim3(KVD / 32, HH / 32), dim3(32, 8)>>>(Wv, wvh, wvl, HH, KVD);
    split_transpose<<<dim3(HH / 32, QD / 32), dim3(32, 8)>>>(Wo, woh, wol, QD, HH);

    // QKV projections (tensor cores, bf16x3)
    mma_gemm<<<dim3(QD / 128, MR / 128), 256, GEMM_SMEM>>>(hsh, hsl, wqh, wql, qb, QD, HH);
    mma_gemm<<<dim3(KVD / 128, MR / 128), 256, GEMM_SMEM>>>(hsh, hsl, wkh, wkl, kb, KVD, HH);
    mma_gemm<<<dim3(KVD / 128, MR / 128), 256, GEMM_SMEM>>>(hsh, hsl, wvh, wvl, vb, KVD, HH);

    // RoPE fused with hi/lo split; V split
    rope_split<<<(MR * NH * 64 + 255) / 256, 256>>>(qb, qrh, qrl, NH);
    rope_split<<<(MR * NKV * 64 + 255) / 256, 256>>>(kb, krh, krl, NKV);
    split_kernel<<<(MR * KVD / 4 + 255) / 256, 256>>>(vb, vrh, vrl, MR * KVD / 4);

    // causal GQA attention (tensor cores, bf16x3, fused output split)
    attn_mma<<<dim3(SS / 128, NH, BB), 256, ATTN_SMEM>>>(qrh, qrl, krh, krl,
                                                          vrh, vrl, ath, atl);

    // O projection (tensor cores)
    mma_gemm<<<dim3(HH / 128, MR / 128), 256, GEMM_SMEM>>>(ath, atl, woh, wol, out, HH, QD);
}

// round 10
// speedup vs baseline: 1.5179x; 1.5179x over previous
#include <cuda_runtime.h>
#include <cuda_bf16.h>
#include <math.h>
#include <stdint.h>

#define BB  2
#define SS  2048
#define HH  4096
#define NH  32
#define NKV 8
#define HD  128
#define MR  (BB * SS)      // 4096 rows
#define QD  (NH * HD)      // 4096
#define KVD (NKV * HD)     // 1024

// ---------------- scratch (device globals; no runtime allocation) ----------
__device__ float g_q[MR * QD];
__device__ float g_k[MR * KVD];
__device__ float g_v[MR * KVD];

__device__ __nv_bfloat16 g_hs_h[MR * HH];
__device__ __nv_bfloat16 g_hs_l[MR * HH];
__device__ __nv_bfloat16 g_wqT_h[QD * HH];
__device__ __nv_bfloat16 g_wqT_l[QD * HH];
__device__ __nv_bfloat16 g_wkT_h[KVD * HH];
__device__ __nv_bfloat16 g_wkT_l[KVD * HH];
__device__ __nv_bfloat16 g_wvT_h[KVD * HH];
__device__ __nv_bfloat16 g_wvT_l[KVD * HH];
__device__ __nv_bfloat16 g_woT_h[HH * QD];
__device__ __nv_bfloat16 g_woT_l[HH * QD];
__device__ __nv_bfloat16 g_att_h[MR * QD];
__device__ __nv_bfloat16 g_att_l[MR * QD];

// attention operands (post-RoPE, hi/lo split)
__device__ __nv_bfloat16 g_qr_h[MR * QD];
__device__ __nv_bfloat16 g_qr_l[MR * QD];
__device__ __nv_bfloat16 g_kr_h[MR * KVD];
__device__ __nv_bfloat16 g_kr_l[MR * KVD];
__device__ __nv_bfloat16 g_vr_h[MR * KVD];
__device__ __nv_bfloat16 g_vr_l[MR * KVD];

// ---------------- PTX helpers ----------------------------------------------
__device__ __forceinline__ uint32_t smem_u32(const void* p) {
    uint32_t a;
    asm("{ .reg .u64 t; cvta.to.shared.u64 t, %1; cvt.u32.u64 %0, t; }"
        : "=r"(a) : "l"(p));
    return a;
}
__device__ __forceinline__ void cpasync16(uint32_t dst, const void* src) {
    asm volatile("cp.async.cg.shared.global [%0], [%1], 16;"
                 :: "r"(dst), "l"(src));
}
#define CP_COMMIT() asm volatile("cp.async.commit_group;" ::: "memory")
#define CP_WAIT0()  asm volatile("cp.async.wait_group 0;" ::: "memory")
#define CP_WAIT1()  asm volatile("cp.async.wait_group 1;" ::: "memory")

#define LDSM4(r0, r1, r2, r3, addr) \
    asm volatile("ldmatrix.sync.aligned.m8n8.x4.shared.b16 {%0,%1,%2,%3}, [%4];" \
                 : "=r"(r0), "=r"(r1), "=r"(r2), "=r"(r3) : "r"(addr))

#define LDSM4T(r0, r1, r2, r3, addr) \
    asm volatile("ldmatrix.sync.aligned.m8n8.x4.trans.shared.b16 {%0,%1,%2,%3}, [%4];" \
                 : "=r"(r0), "=r"(r1), "=r"(r2), "=r"(r3) : "r"(addr))

#define MMA_BF16(c, a, b) \
    asm volatile("mma.sync.aligned.m16n8k16.row.col.f32.bf16.bf16.f32 " \
                 "{%0,%1,%2,%3}, {%4,%5,%6,%7}, {%8,%9}, {%0,%1,%2,%3};" \
                 : "+f"((c)[0]), "+f"((c)[1]), "+f"((c)[2]), "+f"((c)[3]) \
                 : "r"((a)[0]), "r"((a)[1]), "r"((a)[2]), "r"((a)[3]), \
                   "r"((b)[0]), "r"((b)[1]))

__device__ __forceinline__ void split2(float x, float y, uint32_t& h, uint32_t& l) {
    __nv_bfloat162 hb = __floats2bfloat162_rn(x, y);
    float2 hf = __bfloat1622float2(hb);
    __nv_bfloat162 lb = __floats2bfloat162_rn(x - hf.x, y - hf.y);
    h = *reinterpret_cast<uint32_t*>(&hb);
    l = *reinterpret_cast<uint32_t*>(&lb);
}

// ---------------------------------------------------------------------------
// prep_all: z=0 hs hi/lo split; z=1..4 weight transpose+split
// ---------------------------------------------------------------------------
__global__ void prep_all(const float* __restrict__ hs,
                         const float* __restrict__ Wq, const float* __restrict__ Wk,
                         const float* __restrict__ Wv, const float* __restrict__ Wo,
                         __nv_bfloat16* __restrict__ hsh, __nv_bfloat16* __restrict__ hsl,
                         __nv_bfloat16* __restrict__ wqh, __nv_bfloat16* __restrict__ wql,
                         __nv_bfloat16* __restrict__ wkh, __nv_bfloat16* __restrict__ wkl,
                         __nv_bfloat16* __restrict__ wvh, __nv_bfloat16* __restrict__ wvl,
                         __nv_bfloat16* __restrict__ woh, __nv_bfloat16* __restrict__ wol) {
    int z = blockIdx.z;
    int tx = threadIdx.x, ty = threadIdx.y;
    if (z == 0) {
        int i = (blockIdx.y * 128 + blockIdx.x) * 256 + ty * 32 + tx;
        float4 s = ((const float4*)hs)[i];
        __nv_bfloat162 h01 = __floats2bfloat162_rn(s.x, s.y);
        __nv_bfloat162 h23 = __floats2bfloat162_rn(s.z, s.w);
        float2 f01 = __bfloat1622float2(h01);
        float2 f23 = __bfloat1622float2(h23);
        __nv_bfloat162 l01 = __floats2bfloat162_rn(s.x - f01.x, s.y - f01.y);
        __nv_bfloat162 l23 = __floats2bfloat162_rn(s.z - f23.x, s.w - f23.y);
        ((__nv_bfloat162*)hsh)[2 * i]     = h01;
        ((__nv_bfloat162*)hsh)[2 * i + 1] = h23;
        ((__nv_bfloat162*)hsl)[2 * i]     = l01;
        ((__nv_bfloat162*)hsl)[2 * i + 1] = l23;
        return;
    }
    const float* W;
    __nv_bfloat16 *hiT, *loT;
    int K, N;
    if (z == 1)      { W = Wq; hiT = wqh; loT = wql; K = HH; N = QD; }
    else if (z == 2) { W = Wk; hiT = wkh; loT = wkl; K = HH; N = KVD; }
    else if (z == 3) { W = Wv; hiT = wvh; loT = wvl; K = HH; N = KVD; }
    else             { W = Wo; hiT = woh; loT = wol; K = QD; N = HH; }
    if (blockIdx.x * 32 >= N || blockIdx.y * 32 >= K) return;

    __shared__ float t[32][33];
    int n0 = blockIdx.x * 32, k0 = blockIdx.y * 32;
#pragma unroll
    for (int i = 0; i < 32; i += 8)
        t[ty + i][tx] = W[(size_t)(k0 + ty + i) * N + n0 + tx];
    __syncthreads();
#pragma unroll
    for (int i = 0; i < 32; i += 8) {
        float v = t[tx][ty + i];
        __nv_bfloat16 h = __float2bfloat16_rn(v);
        __nv_bfloat16 l = __float2bfloat16_rn(v - __bfloat162float(h));
        size_t o = (size_t)(n0 + ty + i) * K + k0 + tx;
        hiT[o] = h;
        loT[o] = l;
    }
}

// ---------------------------------------------------------------------------
// mma.sync bf16x3 GEMM: C[M,N] = A[M,K] @ BT[N,K]^T  (fp32-accurate)
// ---------------------------------------------------------------------------
#define TILE_B   10240
#define STAGE_B  (4 * TILE_B)
#define GEMM_SMEM (2 * STAGE_B)

__global__ __launch_bounds__(256, 1)
void mma_gemm(const __nv_bfloat16* __restrict__ Ahi,
              const __nv_bfloat16* __restrict__ Alo,
              const __nv_bfloat16* __restrict__ Bhi,
              const __nv_bfloat16* __restrict__ Blo,
              float* __restrict__ C, int Nd, int Kd) {
    extern __shared__ char smem[];
    const uint32_t sb = smem_u32(smem);
    const int tid = threadIdx.x;
    const int wid = tid >> 5, lid = tid & 31;
    const int wm = wid >> 2, wn = wid & 3;
    const int bn = blockIdx.x * 128, bm = blockIdx.y * 128;

    float c[4][4][4];
#pragma unroll
    for (int i = 0; i < 4; i++)
#pragma unroll
        for (int j = 0; j < 4; j++)
#pragma unroll
            for (int q = 0; q < 4; q++) c[i][j][q] = 0.f;

    const int rowA = lid & 15;
    const int khA  = (lid >> 4) << 3;
    const int nB   = ((lid >> 4) << 3) + (lid & 7);
    const int khB  = ((lid >> 3) & 1) << 3;

#define LOAD_STAGE(s, k0)                                                     \
    do {                                                                      \
        _Pragma("unroll")                                                     \
        for (int li = 0; li < 2; li++) {                                      \
            int id  = li * 256 + tid;                                         \
            int row = id >> 2, seg = id & 3;                                  \
            uint32_t so = sb + (s) * STAGE_B + row * 80 + seg * 16;           \
            size_t ga = (size_t)(bm + row) * Kd + (k0) + seg * 8;             \
            size_t gb = (size_t)(bn + row) * Kd + (k0) + seg * 8;             \
            cpasync16(so,              Ahi + ga);                             \
            cpasync16(so + TILE_B,     Alo + ga);                             \
            cpasync16(so + 2 * TILE_B, Bhi + gb);                             \
            cpasync16(so + 3 * TILE_B, Blo + gb);                             \
        }                                                                     \
        CP_COMMIT();                                                          \
    } while (0)

    const int nk = Kd >> 5;
    LOAD_STAGE(0, 0);

    for (int kt = 0; kt < nk; kt++) {
        CP_WAIT0();
        __syncthreads();
        if (kt + 1 < nk) LOAD_STAGE((kt + 1) & 1, (kt + 1) << 5);

        const uint32_t abase = sb + (kt & 1) * STAGE_B;
        const uint32_t bbase = abase + 2 * TILE_B;
#pragma unroll
        for (int kk = 0; kk < 32; kk += 16) {
            uint32_t bh[4][2], bl[4][2];
#pragma unroll
            for (int j2 = 0; j2 < 2; j2++) {
                uint32_t ba = bbase + (wn * 32 + j2 * 16 + nB) * 80 +
                              (kk + khB) * 2;
                LDSM4(bh[j2 * 2][0], bh[j2 * 2][1],
                      bh[j2 * 2 + 1][0], bh[j2 * 2 + 1][1], ba);
                LDSM4(bl[j2 * 2][0], bl[j2 * 2][1],
                      bl[j2 * 2 + 1][0], bl[j2 * 2 + 1][1], ba + TILE_B);
            }
#pragma unroll
            for (int i = 0; i < 4; i++) {
                uint32_t aa = abase + (wm * 64 + i * 16 + rowA) * 80 +
                              (kk + khA) * 2;
                uint32_t ah[4], al[4];
                LDSM4(ah[0], ah[1], ah[2], ah[3], aa);
                LDSM4(al[0], al[1], al[2], al[3], aa + TILE_B);
#pragma unroll
                for (int j = 0; j < 4; j++) {
                    MMA_BF16(c[i][j], ah, bh[j]);
                    MMA_BF16(c[i][j], ah, bl[j]);
                    MMA_BF16(c[i][j], al, bh[j]);
                }
            }
        }
        __syncthreads();
    }
#undef LOAD_STAGE

    const int g = lid >> 2, t4 = lid & 3;
#pragma unroll
    for (int i = 0; i < 4; i++) {
        int r0 = bm + wm * 64 + i * 16 + g;
#pragma unroll
        for (int j = 0; j < 4; j++) {
            int col = bn + wn * 32 + j * 8 + t4 * 2;
            *(float2*)&C[(size_t)r0 * Nd + col] =
                make_float2(c[i][j][0], c[i][j][1]);
            *(float2*)&C[(size_t)(r0 + 8) * Nd + col] =
                make_float2(c[i][j][2], c[i][j][3]);
        }
    }
}

// ---------------------------------------------------------------------------
// rope_all: RoPE+split for Q and K, plain split for V — one launch.
// ---------------------------------------------------------------------------
#define NQR (MR * NH * 64)
#define NKR (MR * NKV * 64)
#define NV4 (MR * KVD / 4)

__global__ void rope_all(const float* __restrict__ qs, const float* __restrict__ ks,
                         const float* __restrict__ vs,
                         __nv_bfloat16* __restrict__ qh, __nv_bfloat16* __restrict__ ql,
                         __nv_bfloat16* __restrict__ kh, __nv_bfloat16* __restrict__ kl,
                         __nv_bfloat16* __restrict__ vh, __nv_bfloat16* __restrict__ vl) {
    int idx = blockIdx.x * blockDim.x + threadIdx.x;
    if (idx < NQR + NKR) {
        const float* buf;
        __nv_bfloat16 *oh, *ol;
        int nheads;
        if (idx < NQR) { buf = qs; oh = qh; ol = ql; nheads = NH; }
        else { idx -= NQR; buf = ks; oh = kh; ol = kl; nheads = NKV; }
        int i    = idx & 63;
        int head = (idx >> 6) % nheads;
        int row  = idx / (nheads << 6);
        float p    = (float)(row % SS);
        float invf = expf(-(float)i * 0.14391156831212787f);
        float ang  = p * invf;
        float c, s;
        sincosf(ang, &s, &c);
        size_t base = (size_t)row * (nheads * HD) + head * HD + i;
        float x0 = buf[base];
        float x1 = buf[base + 64];
        float y0 = x0 * c - x1 * s;
        float y1 = x1 * c + x0 * s;
        __nv_bfloat16 h0 = __float2bfloat16_rn(y0);
        __nv_bfloat16 h1 = __float2bfloat16_rn(y1);
        oh[base]      = h0;
        oh[base + 64] = h1;
        ol[base]      = __float2bfloat16_rn(y0 - __bfloat162float(h0));
        ol[base + 64] = __float2bfloat16_rn(y1 - __bfloat162float(h1));
        return;
    }
    idx -= NQR + NKR;
    if (idx >= NV4) return;
    float4 s = ((const float4*)vs)[idx];
    __nv_bfloat162 h01 = __floats2bfloat162_rn(s.x, s.y);
    __nv_bfloat162 h23 = __floats2bfloat162_rn(s.z, s.w);
    float2 f01 = __bfloat1622float2(h01);
    float2 f23 = __bfloat1622float2(h23);
    ((__nv_bfloat162*)vh)[2 * idx]     = h01;
    ((__nv_bfloat162*)vh)[2 * idx + 1] = h23;
    ((__nv_bfloat162*)vl)[2 * idx]     = __floats2bfloat162_rn(s.x - f01.x, s.y - f01.y);
    ((__nv_bfloat162*)vl)[2 * idx + 1] = __floats2bfloat162_rn(s.z - f23.x, s.w - f23.y);
}

// ---------------------------------------------------------------------------
// Tensor-core causal flash attention, bf16x3, low register pressure.
// CTA: 64 q-rows, 256 threads = 8 warps. Warp w: row slab (w&3)*16,
// half = w>>2: S computes kv-col half (sc[4][4]); P via smem;
// PV computes HD half (o[8][4]). K/V double-buffered.
// All direct smem ld/st go through the generic `smem` pointer;
// only ldmatrix/cp.async use the cvta'd 32-bit shared address.
// ---------------------------------------------------------------------------
#define APITCH 272
#define ATK   (64 * APITCH)            // 17408
#define SKV   (4 * ATK)
#define PPITCH 144
#define PTILE (64 * PPITCH)            // 9216
#define OFF_KV (2 * ATK)
#define OFF_P  (OFF_KV + 2 * SKV)
#define OFF_MX (OFF_P + 2 * PTILE)
#define OFF_SM (OFF_MX + 2 * 64 * 4)
#define ATTN_SMEM (OFF_SM + 2 * 64 * 4)

__global__ __launch_bounds__(256, 1)
void attn_mma(const __nv_bfloat16* __restrict__ Qh, const __nv_bfloat16* __restrict__ Ql,
              const __nv_bfloat16* __restrict__ Kh, const __nv_bfloat16* __restrict__ Kl,
              const __nv_bfloat16* __restrict__ Vh, const __nv_bfloat16* __restrict__ Vl,
              __nv_bfloat16* __restrict__ Oh, __nv_bfloat16* __restrict__ Ol) {
    extern __shared__ char smem[];
    const uint32_t sb = smem_u32(smem);
    const int tid = threadIdx.x;
    const int wid = tid >> 5, lid = tid & 31;
    const int g = lid >> 2, t4 = lid & 3;
    const int half = wid >> 2, rw = wid & 3;
    const int qb = gridDim.x - 1 - blockIdx.x;   // big tiles first
    const int h = blockIdx.y, b = blockIdx.z;
    const int kvh = h >> 2;
    const int q0 = qb * 64;

    const uint32_t sQh = sb, sQl = sb + ATK;
    const uint32_t kvb = sb + OFF_KV;
    const uint32_t sPh = sb + OFF_P;

    // Q tile (64 rows), hi+lo
#pragma unroll
    for (int t = 0; t < 4; t++) {
        int id = t * 256 + tid;
        int row = id >> 4, seg = id & 15;
        uint32_t so = row * APITCH + seg * 16;
        size_t gq = (size_t)(b * SS + q0 + row) * QD + h * HD + seg * 8;
        cpasync16(sQh + so, Qh + gq);
        cpasync16(sQl + so, Ql + gq);
    }
    CP_COMMIT();

#define LOAD_KV(s, kt)                                                        \
    do {                                                                      \
        _Pragma("unroll")                                                     \
        for (int t = 0; t < 4; t++) {                                         \
            int id = t * 256 + tid;                                           \
            int row = id >> 4, seg = id & 15;                                 \
            uint32_t so = kvb + (s) * SKV + row * APITCH + seg * 16;          \
            size_t gk = (size_t)(b * SS + (kt) * 64 + row) * KVD +            \
                        kvh * HD + seg * 8;                                   \
            cpasync16(so,           Kh + gk);                                 \
            cpasync16(so + ATK,     Kl + gk);                                 \
            cpasync16(so + 2 * ATK, Vh + gk);                                 \
            cpasync16(so + 3 * ATK, Vl + gk);                                 \
        }                                                                     \
        CP_COMMIT();                                                          \
    } while (0)

    float o[8][4];
#pragma unroll
    for (int n = 0; n < 8; n++)
#pragma unroll
        for (int q = 0; q < 4; q++) o[n][q] = 0.f;
    float m[2] = {-1e30f, -1e30f}, l[2] = {0.f, 0.f};

    const int rowA = lid & 15, khA = (lid >> 4) << 3;
    const int nB = ((lid >> 4) << 3) + (lid & 7);
    const int khB = ((lid >> 3) & 1) << 3;
    const int kV = (((lid >> 3) & 1) << 3) + (lid & 7);
    const int nVo = (lid >> 4) << 3;

    const float scale = 0.08838834764831845f;
    const int nkt = qb + 1;

    LOAD_KV(0, 0);

    for (int kt = 0; kt < nkt; kt++) {
        if (kt + 1 < nkt) {
            LOAD_KV((kt + 1) & 1, kt + 1);
            CP_WAIT1();
        } else {
            CP_WAIT0();
        }
        __syncthreads();

        const uint32_t sKh = kvb + (kt & 1) * SKV;
        const uint32_t sVh = sKh + 2 * ATK;
        const int k0t = kt * 64;

        // ---- S (this warp: 32 kv cols at half*32) ----
        float sc[4][4];
#pragma unroll
        for (int j = 0; j < 4; j++)
#pragma unroll
            for (int q = 0; q < 4; q++) sc[j][q] = 0.f;

#pragma unroll
        for (int kk = 0; kk < 8; kk++) {
            uint32_t qhf[4], qlf[4];
            uint32_t qa = sQh + (rw * 16 + rowA) * APITCH + (kk * 16 + khA) * 2;
            LDSM4(qhf[0], qhf[1], qhf[2], qhf[3], qa);
            LDSM4(qlf[0], qlf[1], qlf[2], qlf[3], qa + ATK);
#pragma unroll
            for (int jp = 0; jp < 2; jp++) {
                uint32_t kh0[2], kh1[2], kl0[2], kl1[2];
                uint32_t ka = sKh + (half * 32 + jp * 16 + nB) * APITCH +
                              (kk * 16 + khB) * 2;
                LDSM4(kh0[0], kh0[1], kh1[0], kh1[1], ka);
                LDSM4(kl0[0], kl0[1], kl1[0], kl1[1], ka + ATK);
                MMA_BF16(sc[2 * jp],     qhf, kh0);
                MMA_BF16(sc[2 * jp + 1], qhf, kh1);
                MMA_BF16(sc[2 * jp],     qhf, kl0);
                MMA_BF16(sc[2 * jp + 1], qhf, kl1);
                MMA_BF16(sc[2 * jp],     qlf, kh0);
                MMA_BF16(sc[2 * jp + 1], qlf, kh1);
            }
        }

        // scale + causal mask (diagonal tile only)
#pragma unroll
        for (int j = 0; j < 4; j++)
#pragma unroll
            for (int q = 0; q < 4; q++) sc[j][q] *= scale;
        if (kt == qb) {
            int r0 = q0 + rw * 16 + g, r1 = r0 + 8;
#pragma unroll
            for (int j = 0; j < 4; j++) {
                int c0 = k0t + half * 32 + j * 8 + 2 * t4, c1 = c0 + 1;
                if (c0 > r0) sc[j][0] = -1e30f;
                if (c1 > r0) sc[j][1] = -1e30f;
                if (c0 > r1) sc[j][2] = -1e30f;
                if (c1 > r1) sc[j][3] = -1e30f;
            }
        }

        // ---- partial row max -> smem (generic pointer) ----
        float pm[2];
#pragma unroll
        for (int r = 0; r < 2; r++) {
            float mx = -1e30f;
#pragma unroll
            for (int j = 0; j < 4; j++)
                mx = fmaxf(mx, fmaxf(sc[j][2 * r], sc[j][2 * r + 1]));
            mx = fmaxf(mx, __shfl_xor_sync(0xffffffffu, mx, 1));
            mx = fmaxf(mx, __shfl_xor_sync(0xffffffffu, mx, 2));
            pm[r] = mx;
            if (t4 == 0)
                *(float*)(smem + OFF_MX + (half * 64 + rw * 16 + g + 8 * r) * 4) = mx;
        }
        __syncthreads();   // bar1: partial maxima visible

        // ---- combine max; P = exp; partial sums; P->smem ----
        float corr[2];
#pragma unroll
        for (int r = 0; r < 2; r++) {
            int row = rw * 16 + g + 8 * r;
            float po = *(float*)(smem + OFF_MX + ((1 - half) * 64 + row) * 4);
            float mn = fmaxf(m[r], fmaxf(pm[r], po));
            corr[r] = __expf(m[r] - mn);
            m[r] = mn;
            float rs = 0.f;
#pragma unroll
            for (int j = 0; j < 4; j++) {
                float p0 = __expf(sc[j][2 * r] - mn);
                float p1 = __expf(sc[j][2 * r + 1] - mn);
                sc[j][2 * r] = p0;
                sc[j][2 * r + 1] = p1;
                rs += p0 + p1;
            }
            rs += __shfl_xor_sync(0xffffffffu, rs, 1);
            rs += __shfl_xor_sync(0xffffffffu, rs, 2);
            if (t4 == 0)
                *(float*)(smem + OFF_SM + (half * 64 + row) * 4) = rs;
            // store P (bf16 hi/lo) to smem
#pragma unroll
            for (int j = 0; j < 4; j++) {
                uint32_t hh, ll;
                split2(sc[j][2 * r], sc[j][2 * r + 1], hh, ll);
                uint32_t pa = row * PPITCH + (half * 32 + j * 8 + 2 * t4) * 2;
                *(uint32_t*)(smem + OFF_P + pa) = hh;
                *(uint32_t*)(smem + OFF_P + PTILE + pa) = ll;
            }
            // rescale O
#pragma unroll
            for (int n = 0; n < 8; n++) {
                o[n][2 * r] *= corr[r];
                o[n][2 * r + 1] *= corr[r];
            }
        }
        __syncthreads();   // bar2: P + sums visible

#pragma unroll
        for (int r = 0; r < 2; r++) {
            int row = rw * 16 + g + 8 * r;
            float ls = *(float*)(smem + OFF_SM + row * 4) +
                       *(float*)(smem + OFF_SM + (64 + row) * 4);
            l[r] = l[r] * corr[r] + ls;
        }

        // ---- O += P V (full 64 kv, this warp's HD half) ----
#pragma unroll
        for (int j2 = 0; j2 < 4; j2++) {
            uint32_t ph[4], pl[4];
            uint32_t pa = sPh + (rw * 16 + rowA) * PPITCH + (j2 * 16 + khA) * 2;
            LDSM4(ph[0], ph[1], ph[2], ph[3], pa);
            LDSM4(pl[0], pl[1], pl[2], pl[3], pa + PTILE);
#pragma unroll
            for (int np = 0; np < 4; np++) {
                uint32_t vh0[2], vh1[2], vl0[2], vl1[2];
                uint32_t va = sVh + (j2 * 16 + kV) * APITCH +
                              (half * 64 + np * 16 + nVo) * 2;
                LDSM4T(vh0[0], vh0[1], vh1[0], vh1[1], va);
                LDSM4T(vl0[0], vl0[1], vl1[0], vl1[1], va + ATK);
                MMA_BF16(o[2 * np],     ph, vh0);
                MMA_BF16(o[2 * np + 1], ph, vh1);
                MMA_BF16(o[2 * np],     ph, vl0);
                MMA_BF16(o[2 * np + 1], ph, vl1);
                MMA_BF16(o[2 * np],     pl, vh0);
                MMA_BF16(o[2 * np + 1], pl, vh1);
            }
        }
        __syncthreads();   // protect P/stats/KV for next iteration
    }
#undef LOAD_KV

    // ---- finalize: normalize + hi/lo split + store (this warp's HD half) ----
    float inv0 = 1.f / l[0], inv1 = 1.f / l[1];
    size_t r0g = (size_t)(b * SS + q0 + rw * 16 + g) * QD + h * HD + half * 64;
    size_t r1g = r0g + 8 * QD;
#pragma unroll
    for (int n = 0; n < 8; n++) {
        int col = n * 8 + 2 * t4;
        uint32_t hh, ll;
        split2(o[n][0] * inv0, o[n][1] * inv0, hh, ll);
        *(uint32_t*)&Oh[r0g + col] = hh;
        *(uint32_t*)&Ol[r0g + col] = ll;
        split2(o[n][2] * inv1, o[n][3] * inv1, hh, ll);
        *(uint32_t*)&Oh[r1g + col] = hh;
        *(uint32_t*)&Ol[r1g + col] = ll;
    }
}

// ---------------------------------------------------------------------------
extern "C" void kernel_launch(void* const* d_in, const int* in_sizes, int n_in,
                              void* d_out, int out_size) {
    const float* hs  = (const float*)d_in[0];
    const float* Wq  = (const float*)d_in[2];
    const float* Wk  = (const float*)d_in[3];
    const float* Wv  = (const float*)d_in[4];
    const float* Wo  = (const float*)d_in[5];
    float*       out = (float*)d_out;

    float *qb, *kb, *vb;
    cudaGetSymbolAddress((void**)&qb, g_q);
    cudaGetSymbolAddress((void**)&kb, g_k);
    cudaGetSymbolAddress((void**)&vb, g_v);

    __nv_bfloat16 *hsh, *hsl, *wqh, *wql, *wkh, *wkl, *wvh, *wvl, *woh, *wol, *ath, *atl;
    __nv_bfloat16 *qrh, *qrl, *krh, *krl, *vrh, *vrl;
    cudaGetSymbolAddress((void**)&hsh, g_hs_h);
    cudaGetSymbolAddress((void**)&hsl, g_hs_l);
    cudaGetSymbolAddress((void**)&wqh, g_wqT_h);
    cudaGetSymbolAddress((void**)&wql, g_wqT_l);
    cudaGetSymbolAddress((void**)&wkh, g_wkT_h);
    cudaGetSymbolAddress((void**)&wkl, g_wkT_l);
    cudaGetSymbolAddress((void**)&wvh, g_wvT_h);
    cudaGetSymbolAddress((void**)&wvl, g_wvT_l);
    cudaGetSymbolAddress((void**)&woh, g_woT_h);
    cudaGetSymbolAddress((void**)&wol, g_woT_l);
    cudaGetSymbolAddress((void**)&ath, g_att_h);
    cudaGetSymbolAddress((void**)&atl, g_att_l);
    cudaGetSymbolAddress((void**)&qrh, g_qr_h);
    cudaGetSymbolAddress((void**)&qrl, g_qr_l);
    cudaGetSymbolAddress((void**)&krh, g_kr_h);
    cudaGetSymbolAddress((void**)&krl, g_kr_l);
    cudaGetSymbolAddress((void**)&vrh, g_vr_h);
    cudaGetSymbolAddress((void**)&vrl, g_vr_l);

    cudaFuncSetAttribute(mma_gemm, cudaFuncAttributeMaxDynamicSharedMemorySize, GEMM_SMEM);
    cudaFuncSetAttribute(attn_mma, cudaFuncAttributeMaxDynamicSharedMemorySize, ATTN_SMEM);

    // 0: fused prep (hs split + 4 weight transposes)
    prep_all<<<dim3(128, 128, 5), dim3(32, 8)>>>(hs, Wq, Wk, Wv, Wo,
                                                 hsh, hsl, wqh, wql, wkh, wkl,
                                                 wvh, wvl, woh, wol);

    // 1-3: QKV projections
    mma_gemm<<<dim3(QD / 128, MR / 128), 256, GEMM_SMEM>>>(hsh, hsl, wqh, wql, qb, QD, HH);
    mma_gemm<<<dim3(KVD / 128, MR / 128), 256, GEMM_SMEM>>>(hsh, hsl, wkh, wkl, kb, KVD, HH);
    mma_gemm<<<dim3(KVD / 128, MR / 128), 256, GEMM_SMEM>>>(hsh, hsl, wvh, wvl, vb, KVD, HH);

    // 4: RoPE(Q,K) + split(V), fused
    rope_all<<<(NQR + NKR + NV4 + 255) / 256, 256>>>(qb, kb, vb, qrh, qrl,
                                                     krh, krl, vrh, vrl);

    // 5: causal GQA attention (capture slot for ncu -s 5)
    attn_mma<<<dim3(SS / 64, NH, BB), 256, ATTN_SMEM>>>(qrh, qrl, krh, krl,
                                                         vrh, vrl, ath, atl);

    // 6: O projection
    mma_gemm<<<dim3(HH / 128, MR / 128), 256, GEMM_SMEM>>>(ath, atl, woh, wol, out, HH, QD);
}

// round 12
// speedup vs baseline: 1.7022x; 1.1214x over previous
#include <cuda_runtime.h>
#include <cuda_bf16.h>
#include <math.h>
#include <stdint.h>

#define BB  2
#define SS  2048
#define HH  4096
#define NH  32
#define NKV 8
#define HD  128
#define MR  (BB * SS)      // 4096 rows
#define QD  (NH * HD)      // 4096
#define KVD (NKV * HD)     // 1024

// ---------------- scratch (device globals; no runtime allocation) ----------
__device__ float g_q[MR * QD];
__device__ float g_k[MR * KVD];
__device__ float g_v[MR * KVD];

__device__ __nv_bfloat16 g_hs_h[MR * HH];
__device__ __nv_bfloat16 g_hs_l[MR * HH];
__device__ __nv_bfloat16 g_wqT_h[QD * HH];
__device__ __nv_bfloat16 g_wqT_l[QD * HH];
__device__ __nv_bfloat16 g_wkT_h[KVD * HH];
__device__ __nv_bfloat16 g_wkT_l[KVD * HH];
__device__ __nv_bfloat16 g_wvT_h[KVD * HH];
__device__ __nv_bfloat16 g_wvT_l[KVD * HH];
__device__ __nv_bfloat16 g_woT_h[HH * QD];
__device__ __nv_bfloat16 g_woT_l[HH * QD];
__device__ __nv_bfloat16 g_att_h[MR * QD];
__device__ __nv_bfloat16 g_att_l[MR * QD];

// attention operands (post-RoPE, hi/lo split)
__device__ __nv_bfloat16 g_qr_h[MR * QD];
__device__ __nv_bfloat16 g_qr_l[MR * QD];
__device__ __nv_bfloat16 g_kr_h[MR * KVD];
__device__ __nv_bfloat16 g_kr_l[MR * KVD];
__device__ __nv_bfloat16 g_vr_h[MR * KVD];
__device__ __nv_bfloat16 g_vr_l[MR * KVD];

// ---------------- PTX helpers ----------------------------------------------
__device__ __forceinline__ uint32_t smem_u32(const void* p) {
    uint32_t a;
    asm("{ .reg .u64 t; cvta.to.shared.u64 t, %1; cvt.u32.u64 %0, t; }"
        : "=r"(a) : "l"(p));
    return a;
}
__device__ __forceinline__ void cpasync16(uint32_t dst, const void* src) {
    asm volatile("cp.async.cg.shared.global [%0], [%1], 16;"
                 :: "r"(dst), "l"(src));
}
#define CP_COMMIT() asm volatile("cp.async.commit_group;" ::: "memory")
#define CP_WAIT0()  asm volatile("cp.async.wait_group 0;" ::: "memory")
#define CP_WAIT1()  asm volatile("cp.async.wait_group 1;" ::: "memory")

#define LDSM4(r0, r1, r2, r3, addr) \
    asm volatile("ldmatrix.sync.aligned.m8n8.x4.shared.b16 {%0,%1,%2,%3}, [%4];" \
                 : "=r"(r0), "=r"(r1), "=r"(r2), "=r"(r3) : "r"(addr))

#define LDSM4T(r0, r1, r2, r3, addr) \
    asm volatile("ldmatrix.sync.aligned.m8n8.x4.trans.shared.b16 {%0,%1,%2,%3}, [%4];" \
                 : "=r"(r0), "=r"(r1), "=r"(r2), "=r"(r3) : "r"(addr))

#define MMA_BF16(c, a, b) \
    asm volatile("mma.sync.aligned.m16n8k16.row.col.f32.bf16.bf16.f32 " \
                 "{%0,%1,%2,%3}, {%4,%5,%6,%7}, {%8,%9}, {%0,%1,%2,%3};" \
                 : "+f"((c)[0]), "+f"((c)[1]), "+f"((c)[2]), "+f"((c)[3]) \
                 : "r"((a)[0]), "r"((a)[1]), "r"((a)[2]), "r"((a)[3]), \
                   "r"((b)[0]), "r"((b)[1]))

__device__ __forceinline__ void split2(float x, float y, uint32_t& h, uint32_t& l) {
    __nv_bfloat162 hb = __floats2bfloat162_rn(x, y);
    float2 hf = __bfloat1622float2(hb);
    __nv_bfloat162 lb = __floats2bfloat162_rn(x - hf.x, y - hf.y);
    h = *reinterpret_cast<uint32_t*>(&hb);
    l = *reinterpret_cast<uint32_t*>(&lb);
}

// ---------------------------------------------------------------------------
// prep_all: z=0 hs hi/lo split; z=1..4 weight transpose+split
// ---------------------------------------------------------------------------
__global__ void prep_all(const float* __restrict__ hs,
                         const float* __restrict__ Wq, const float* __restrict__ Wk,
                         const float* __restrict__ Wv, const float* __restrict__ Wo,
                         __nv_bfloat16* __restrict__ hsh, __nv_bfloat16* __restrict__ hsl,
                         __nv_bfloat16* __restrict__ wqh, __nv_bfloat16* __restrict__ wql,
                         __nv_bfloat16* __restrict__ wkh, __nv_bfloat16* __restrict__ wkl,
                         __nv_bfloat16* __restrict__ wvh, __nv_bfloat16* __restrict__ wvl,
                         __nv_bfloat16* __restrict__ woh, __nv_bfloat16* __restrict__ wol) {
    int z = blockIdx.z;
    int tx = threadIdx.x, ty = threadIdx.y;
    if (z == 0) {
        int i = (blockIdx.y * 128 + blockIdx.x) * 256 + ty * 32 + tx;
        float4 s = ((const float4*)hs)[i];
        __nv_bfloat162 h01 = __floats2bfloat162_rn(s.x, s.y);
        __nv_bfloat162 h23 = __floats2bfloat162_rn(s.z, s.w);
        float2 f01 = __bfloat1622float2(h01);
        float2 f23 = __bfloat1622float2(h23);
        __nv_bfloat162 l01 = __floats2bfloat162_rn(s.x - f01.x, s.y - f01.y);
        __nv_bfloat162 l23 = __floats2bfloat162_rn(s.z - f23.x, s.w - f23.y);
        ((__nv_bfloat162*)hsh)[2 * i]     = h01;
        ((__nv_bfloat162*)hsh)[2 * i + 1] = h23;
        ((__nv_bfloat162*)hsl)[2 * i]     = l01;
        ((__nv_bfloat162*)hsl)[2 * i + 1] = l23;
        return;
    }
    const float* W;
    __nv_bfloat16 *hiT, *loT;
    int K, N;
    if (z == 1)      { W = Wq; hiT = wqh; loT = wql; K = HH; N = QD; }
    else if (z == 2) { W = Wk; hiT = wkh; loT = wkl; K = HH; N = KVD; }
    else if (z == 3) { W = Wv; hiT = wvh; loT = wvl; K = HH; N = KVD; }
    else             { W = Wo; hiT = woh; loT = wol; K = QD; N = HH; }
    if (blockIdx.x * 32 >= N || blockIdx.y * 32 >= K) return;

    __shared__ float t[32][33];
    int n0 = blockIdx.x * 32, k0 = blockIdx.y * 32;
#pragma unroll
    for (int i = 0; i < 32; i += 8)
        t[ty + i][tx] = W[(size_t)(k0 + ty + i) * N + n0 + tx];
    __syncthreads();
#pragma unroll
    for (int i = 0; i < 32; i += 8) {
        float v = t[tx][ty + i];
        __nv_bfloat16 h = __float2bfloat16_rn(v);
        __nv_bfloat16 l = __float2bfloat16_rn(v - __bfloat162float(h));
        size_t o = (size_t)(n0 + ty + i) * K + k0 + tx;
        hiT[o] = h;
        loT[o] = l;
    }
}

// ---------------------------------------------------------------------------
// mma.sync bf16x3 GEMM: C[M,N] = A[M,K] @ BT[N,K]^T  (fp32-accurate)
// __launch_bounds__(256, 2): cap regs at 128 so 2 CTAs/SM overlap
// (R10 ncu: 1 CTA/SM, tensor pipe only 48% busy).
// ---------------------------------------------------------------------------
#define TILE_B   10240
#define STAGE_B  (4 * TILE_B)
#define GEMM_SMEM (2 * STAGE_B)

__global__ __launch_bounds__(256, 2)
void mma_gemm(const __nv_bfloat16* __restrict__ Ahi,
              const __nv_bfloat16* __restrict__ Alo,
              const __nv_bfloat16* __restrict__ Bhi,
              const __nv_bfloat16* __restrict__ Blo,
              float* __restrict__ C, int Nd, int Kd) {
    extern __shared__ char smem[];
    const uint32_t sb = smem_u32(smem);
    const int tid = threadIdx.x;
    const int wid = tid >> 5, lid = tid & 31;
    const int wm = wid >> 2, wn = wid & 3;
    const int bn = blockIdx.x * 128, bm = blockIdx.y * 128;

    float c[4][4][4];
#pragma unroll
    for (int i = 0; i < 4; i++)
#pragma unroll
        for (int j = 0; j < 4; j++)
#pragma unroll
            for (int q = 0; q < 4; q++) c[i][j][q] = 0.f;

    const int rowA = lid & 15;
    const int khA  = (lid >> 4) << 3;
    const int nB   = ((lid >> 4) << 3) + (lid & 7);
    const int khB  = ((lid >> 3) & 1) << 3;

#define LOAD_STAGE(s, k0)                                                     \
    do {                                                                      \
        _Pragma("unroll")                                                     \
        for (int li = 0; li < 2; li++) {                                      \
            int id  = li * 256 + tid;                                         \
            int row = id >> 2, seg = id & 3;                                  \
            uint32_t so = sb + (s) * STAGE_B + row * 80 + seg * 16;           \
            size_t ga = (size_t)(bm + row) * Kd + (k0) + seg * 8;             \
            size_t gb = (size_t)(bn + row) * Kd + (k0) + seg * 8;             \
            cpasync16(so,              Ahi + ga);                             \
            cpasync16(so + TILE_B,     Alo + ga);                             \
            cpasync16(so + 2 * TILE_B, Bhi + gb);                             \
            cpasync16(so + 3 * TILE_B, Blo + gb);                             \
        }                                                                     \
        CP_COMMIT();                                                          \
    } while (0)

    const int nk = Kd >> 5;
    LOAD_STAGE(0, 0);

    for (int kt = 0; kt < nk; kt++) {
        CP_WAIT0();
        __syncthreads();
        if (kt + 1 < nk) LOAD_STAGE((kt + 1) & 1, (kt + 1) << 5);

        const uint32_t abase = sb + (kt & 1) * STAGE_B;
        const uint32_t bbase = abase + 2 * TILE_B;
#pragma unroll
        for (int kk = 0; kk < 32; kk += 16) {
            uint32_t bh[4][2], bl[4][2];
#pragma unroll
            for (int j2 = 0; j2 < 2; j2++) {
                uint32_t ba = bbase + (wn * 32 + j2 * 16 + nB) * 80 +
                              (kk + khB) * 2;
                LDSM4(bh[j2 * 2][0], bh[j2 * 2][1],
                      bh[j2 * 2 + 1][0], bh[j2 * 2 + 1][1], ba);
                LDSM4(bl[j2 * 2][0], bl[j2 * 2][1],
                      bl[j2 * 2 + 1][0], bl[j2 * 2 + 1][1], ba + TILE_B);
            }
#pragma unroll
            for (int i = 0; i < 4; i++) {
                uint32_t aa = abase + (wm * 64 + i * 16 + rowA) * 80 +
                              (kk + khA) * 2;
                uint32_t ah[4], al[4];
                LDSM4(ah[0], ah[1], ah[2], ah[3], aa);
                LDSM4(al[0], al[1], al[2], al[3], aa + TILE_B);
#pragma unroll
                for (int j = 0; j < 4; j++) {
                    MMA_BF16(c[i][j], ah, bh[j]);
                    MMA_BF16(c[i][j], ah, bl[j]);
                    MMA_BF16(c[i][j], al, bh[j]);
                }
            }
        }
        __syncthreads();
    }
#undef LOAD_STAGE

    const int g = lid >> 2, t4 = lid & 3;
#pragma unroll
    for (int i = 0; i < 4; i++) {
        int r0 = bm + wm * 64 + i * 16 + g;
#pragma unroll
        for (int j = 0; j < 4; j++) {
            int col = bn + wn * 32 + j * 8 + t4 * 2;
            *(float2*)&C[(size_t)r0 * Nd + col] =
                make_float2(c[i][j][0], c[i][j][1]);
            *(float2*)&C[(size_t)(r0 + 8) * Nd + col] =
                make_float2(c[i][j][2], c[i][j][3]);
        }
    }
}

// ---------------------------------------------------------------------------
// rope_all: RoPE+split for Q and K, plain split for V — one launch.
// ---------------------------------------------------------------------------
#define NQR (MR * NH * 64)
#define NKR (MR * NKV * 64)
#define NV4 (MR * KVD / 4)

__global__ void rope_all(const float* __restrict__ qs, const float* __restrict__ ks,
                         const float* __restrict__ vs,
                         __nv_bfloat16* __restrict__ qh, __nv_bfloat16* __restrict__ ql,
                         __nv_bfloat16* __restrict__ kh, __nv_bfloat16* __restrict__ kl,
                         __nv_bfloat16* __restrict__ vh, __nv_bfloat16* __restrict__ vl) {
    int idx = blockIdx.x * blockDim.x + threadIdx.x;
    if (idx < NQR + NKR) {
        const float* buf;
        __nv_bfloat16 *oh, *ol;
        int nheads;
        if (idx < NQR) { buf = qs; oh = qh; ol = ql; nheads = NH; }
        else { idx -= NQR; buf = ks; oh = kh; ol = kl; nheads = NKV; }
        int i    = idx & 63;
        int head = (idx >> 6) % nheads;
        int row  = idx / (nheads << 6);
        float p    = (float)(row % SS);
        float invf = expf(-(float)i * 0.14391156831212787f);
        float ang  = p * invf;
        float c, s;
        sincosf(ang, &s, &c);
        size_t base = (size_t)row * (nheads * HD) + head * HD + i;
        float x0 = buf[base];
        float x1 = buf[base + 64];
        float y0 = x0 * c - x1 * s;
        float y1 = x1 * c + x0 * s;
        __nv_bfloat16 h0 = __float2bfloat16_rn(y0);
        __nv_bfloat16 h1 = __float2bfloat16_rn(y1);
        oh[base]      = h0;
        oh[base + 64] = h1;
        ol[base]      = __float2bfloat16_rn(y0 - __bfloat162float(h0));
        ol[base + 64] = __float2bfloat16_rn(y1 - __bfloat162float(h1));
        return;
    }
    idx -= NQR + NKR;
    if (idx >= NV4) return;
    float4 s = ((const float4*)vs)[idx];
    __nv_bfloat162 h01 = __floats2bfloat162_rn(s.x, s.y);
    __nv_bfloat162 h23 = __floats2bfloat162_rn(s.z, s.w);
    float2 f01 = __bfloat1622float2(h01);
    float2 f23 = __bfloat1622float2(h23);
    ((__nv_bfloat162*)vh)[2 * idx]     = h01;
    ((__nv_bfloat162*)vh)[2 * idx + 1] = h23;
    ((__nv_bfloat162*)vl)[2 * idx]     = __floats2bfloat162_rn(s.x - f01.x, s.y - f01.y);
    ((__nv_bfloat162*)vl)[2 * idx + 1] = __floats2bfloat162_rn(s.z - f23.x, s.w - f23.y);
}

// ---------------------------------------------------------------------------
// Tensor-core causal flash attention, bf16x3, low register pressure.
// CTA: 64 q-rows, 256 threads = 8 warps. Warp w: row slab (w&3)*16,
// half = w>>2: S computes kv-col half (sc[4][4]); P via smem;
// PV computes HD half (o[8][4]). K/V double-buffered.
// ---------------------------------------------------------------------------
#define APITCH 272
#define ATK   (64 * APITCH)            // 17408
#define SKV   (4 * ATK)
#define PPITCH 144
#define PTILE (64 * PPITCH)            // 9216
#define OFF_KV (2 * ATK)
#define OFF_P  (OFF_KV + 2 * SKV)
#define OFF_MX (OFF_P + 2 * PTILE)
#define OFF_SM (OFF_MX + 2 * 64 * 4)
#define ATTN_SMEM (OFF_SM + 2 * 64 * 4)

__global__ __launch_bounds__(256, 1)
void attn_mma(const __nv_bfloat16* __restrict__ Qh, const __nv_bfloat16* __restrict__ Ql,
              const __nv_bfloat16* __restrict__ Kh, const __nv_bfloat16* __restrict__ Kl,
              const __nv_bfloat16* __restrict__ Vh, const __nv_bfloat16* __restrict__ Vl,
              __nv_bfloat16* __restrict__ Oh, __nv_bfloat16* __restrict__ Ol) {
    extern __shared__ char smem[];
    const uint32_t sb = smem_u32(smem);
    const int tid = threadIdx.x;
    const int wid = tid >> 5, lid = tid & 31;
    const int g = lid >> 2, t4 = lid & 3;
    const int half = wid >> 2, rw = wid & 3;
    const int qb = gridDim.x - 1 - blockIdx.x;   // big tiles first
    const int h = blockIdx.y, b = blockIdx.z;
    const int kvh = h >> 2;
    const int q0 = qb * 64;

    const uint32_t sQh = sb, sQl = sb + ATK;
    const uint32_t kvb = sb + OFF_KV;
    const uint32_t sPh = sb + OFF_P;

    // Q tile (64 rows), hi+lo
#pragma unroll
    for (int t = 0; t < 4; t++) {
        int id = t * 256 + tid;
        int row = id >> 4, seg = id & 15;
        uint32_t so = row * APITCH + seg * 16;
        size_t gq = (size_t)(b * SS + q0 + row) * QD + h * HD + seg * 8;
        cpasync16(sQh + so, Qh + gq);
        cpasync16(sQl + so, Ql + gq);
    }
    CP_COMMIT();

#define LOAD_KV(s, kt)                                                        \
    do {                                                                      \
        _Pragma("unroll")                                                     \
        for (int t = 0; t < 4; t++) {                                         \
            int id = t * 256 + tid;                                           \
            int row = id >> 4, seg = id & 15;                                 \
            uint32_t so = kvb + (s) * SKV + row * APITCH + seg * 16;          \
            size_t gk = (size_t)(b * SS + (kt) * 64 + row) * KVD +            \
                        kvh * HD + seg * 8;                                   \
            cpasync16(so,           Kh + gk);                                 \
            cpasync16(so + ATK,     Kl + gk);                                 \
            cpasync16(so + 2 * ATK, Vh + gk);                                 \
            cpasync16(so + 3 * ATK, Vl + gk);                                 \
        }                                                                     \
        CP_COMMIT();                                                          \
    } while (0)

    float o[8][4];
#pragma unroll
    for (int n = 0; n < 8; n++)
#pragma unroll
        for (int q = 0; q < 4; q++) o[n][q] = 0.f;
    float m[2] = {-1e30f, -1e30f}, l[2] = {0.f, 0.f};

    const int rowA = lid & 15, khA = (lid >> 4) << 3;
    const int nB = ((lid >> 4) << 3) + (lid & 7);
    const int khB = ((lid >> 3) & 1) << 3;
    const int kV = (((lid >> 3) & 1) << 3) + (lid & 7);
    const int nVo = (lid >> 4) << 3;

    const float scale = 0.08838834764831845f;
    const int nkt = qb + 1;

    LOAD_KV(0, 0);

    for (int kt = 0; kt < nkt; kt++) {
        if (kt + 1 < nkt) {
            LOAD_KV((kt + 1) & 1, kt + 1);
            CP_WAIT1();
        } else {
            CP_WAIT0();
        }
        __syncthreads();

        const uint32_t sKh = kvb + (kt & 1) * SKV;
        const uint32_t sVh = sKh + 2 * ATK;
        const int k0t = kt * 64;

        // ---- S (this warp: 32 kv cols at half*32) ----
        float sc[4][4];
#pragma unroll
        for (int j = 0; j < 4; j++)
#pragma unroll
            for (int q = 0; q < 4; q++) sc[j][q] = 0.f;

#pragma unroll
        for (int kk = 0; kk < 8; kk++) {
            uint32_t qhf[4], qlf[4];
            uint32_t qa = sQh + (rw * 16 + rowA) * APITCH + (kk * 16 + khA) * 2;
            LDSM4(qhf[0], qhf[1], qhf[2], qhf[3], qa);
            LDSM4(qlf[0], qlf[1], qlf[2], qlf[3], qa + ATK);
#pragma unroll
            for (int jp = 0; jp < 2; jp++) {
                uint32_t kh0[2], kh1[2], kl0[2], kl1[2];
                uint32_t ka = sKh + (half * 32 + jp * 16 + nB) * APITCH +
                              (kk * 16 + khB) * 2;
                LDSM4(kh0[0], kh0[1], kh1[0], kh1[1], ka);
                LDSM4(kl0[0], kl0[1], kl1[0], kl1[1], ka + ATK);
                MMA_BF16(sc[2 * jp],     qhf, kh0);
                MMA_BF16(sc[2 * jp + 1], qhf, kh1);
                MMA_BF16(sc[2 * jp],     qhf, kl0);
                MMA_BF16(sc[2 * jp + 1], qhf, kl1);
                MMA_BF16(sc[2 * jp],     qlf, kh0);
                MMA_BF16(sc[2 * jp + 1], qlf, kh1);
            }
        }

        // scale + causal mask (diagonal tile only)
#pragma unroll
        for (int j = 0; j < 4; j++)
#pragma unroll
            for (int q = 0; q < 4; q++) sc[j][q] *= scale;
        if (kt == qb) {
            int r0 = q0 + rw * 16 + g, r1 = r0 + 8;
#pragma unroll
            for (int j = 0; j < 4; j++) {
                int c0 = k0t + half * 32 + j * 8 + 2 * t4, c1 = c0 + 1;
                if (c0 > r0) sc[j][0] = -1e30f;
                if (c1 > r0) sc[j][1] = -1e30f;
                if (c0 > r1) sc[j][2] = -1e30f;
                if (c1 > r1) sc[j][3] = -1e30f;
            }
        }

        // ---- partial row max -> smem (generic pointer) ----
        float pm[2];
#pragma unroll
        for (int r = 0; r < 2; r++) {
            float mx = -1e30f;
#pragma unroll
            for (int j = 0; j < 4; j++)
                mx = fmaxf(mx, fmaxf(sc[j][2 * r], sc[j][2 * r + 1]));
            mx = fmaxf(mx, __shfl_xor_sync(0xffffffffu, mx, 1));
            mx = fmaxf(mx, __shfl_xor_sync(0xffffffffu, mx, 2));
            pm[r] = mx;
            if (t4 == 0)
                *(float*)(smem + OFF_MX + (half * 64 + rw * 16 + g + 8 * r) * 4) = mx;
        }
        __syncthreads();   // bar1: partial maxima visible

        // ---- combine max; P = exp; partial sums; P->smem ----
        float corr[2];
#pragma unroll
        for (int r = 0; r < 2; r++) {
            int row = rw * 16 + g + 8 * r;
            float po = *(float*)(smem + OFF_MX + ((1 - half) * 64 + row) * 4);
            float mn = fmaxf(m[r], fmaxf(pm[r], po));
            corr[r] = __expf(m[r] - mn);
            m[r] = mn;
            float rs = 0.f;
#pragma unroll
            for (int j = 0; j < 4; j++) {
                float p0 = __expf(sc[j][2 * r] - mn);
                float p1 = __expf(sc[j][2 * r + 1] - mn);
                sc[j][2 * r] = p0;
                sc[j][2 * r + 1] = p1;
                rs += p0 + p1;
            }
            rs += __shfl_xor_sync(0xffffffffu, rs, 1);
            rs += __shfl_xor_sync(0xffffffffu, rs, 2);
            if (t4 == 0)
                *(float*)(smem + OFF_SM + (half * 64 + row) * 4) = rs;
            // store P (bf16 hi/lo) to smem
#pragma unroll
            for (int j = 0; j < 4; j++) {
                uint32_t hh, ll;
                split2(sc[j][2 * r], sc[j][2 * r + 1], hh, ll);
                uint32_t pa = row * PPITCH + (half * 32 + j * 8 + 2 * t4) * 2;
                *(uint32_t*)(smem + OFF_P + pa) = hh;
                *(uint32_t*)(smem + OFF_P + PTILE + pa) = ll;
            }
            // rescale O
#pragma unroll
            for (int n = 0; n < 8; n++) {
                o[n][2 * r] *= corr[r];
                o[n][2 * r + 1] *= corr[r];
            }
        }
        __syncthreads();   // bar2: P + sums visible

#pragma unroll
        for (int r = 0; r < 2; r++) {
            int row = rw * 16 + g + 8 * r;
            float ls = *(float*)(smem + OFF_SM + row * 4) +
                       *(float*)(smem + OFF_SM + (64 + row) * 4);
            l[r] = l[r] * corr[r] + ls;
        }

        // ---- O += P V (full 64 kv, this warp's HD half) ----
#pragma unroll
        for (int j2 = 0; j2 < 4; j2++) {
            uint32_t ph[4], pl[4];
            uint32_t pa = sPh + (rw * 16 + rowA) * PPITCH + (j2 * 16 + khA) * 2;
            LDSM4(ph[0], ph[1], ph[2], ph[3], pa);
            LDSM4(pl[0], pl[1], pl[2], pl[3], pa + PTILE);
#pragma unroll
            for (int np = 0; np < 4; np++) {
                uint32_t vh0[2], vh1[2], vl0[2], vl1[2];
                uint32_t va = sVh + (j2 * 16 + kV) * APITCH +
                              (half * 64 + np * 16 + nVo) * 2;
                LDSM4T(vh0[0], vh0[1], vh1[0], vh1[1], va);
                LDSM4T(vl0[0], vl0[1], vl1[0], vl1[1], va + ATK);
                MMA_BF16(o[2 * np],     ph, vh0);
                MMA_BF16(o[2 * np + 1], ph, vh1);
                MMA_BF16(o[2 * np],     ph, vl0);
                MMA_BF16(o[2 * np + 1], ph, vl1);
                MMA_BF16(o[2 * np],     pl, vh0);
                MMA_BF16(o[2 * np + 1], pl, vh1);
            }
        }
        __syncthreads();   // protect P/stats/KV for next iteration
    }
#undef LOAD_KV

    // ---- finalize: normalize + hi/lo split + store (this warp's HD half) ----
    float inv0 = 1.f / l[0], inv1 = 1.f / l[1];
    size_t r0g = (size_t)(b * SS + q0 + rw * 16 + g) * QD + h * HD + half * 64;
    size_t r1g = r0g + 8 * QD;
#pragma unroll
    for (int n = 0; n < 8; n++) {
        int col = n * 8 + 2 * t4;
        uint32_t hh, ll;
        split2(o[n][0] * inv0, o[n][1] * inv0, hh, ll);
        *(uint32_t*)&Oh[r0g + col] = hh;
        *(uint32_t*)&Ol[r0g + col] = ll;
        split2(o[n][2] * inv1, o[n][3] * inv1, hh, ll);
        *(uint32_t*)&Oh[r1g + col] = hh;
        *(uint32_t*)&Ol[r1g + col] = ll;
    }
}

// ---------------------------------------------------------------------------
extern "C" void kernel_launch(void* const* d_in, const int* in_sizes, int n_in,
                              void* d_out, int out_size) {
    const float* hs  = (const float*)d_in[0];
    const float* Wq  = (const float*)d_in[2];
    const float* Wk  = (const float*)d_in[3];
    const float* Wv  = (const float*)d_in[4];
    const float* Wo  = (const float*)d_in[5];
    float*       out = (float*)d_out;

    float *qb, *kb, *vb;
    cudaGetSymbolAddress((void**)&qb, g_q);
    cudaGetSymbolAddress((void**)&kb, g_k);
    cudaGetSymbolAddress((void**)&vb, g_v);

    __nv_bfloat16 *hsh, *hsl, *wqh, *wql, *wkh, *wkl, *wvh, *wvl, *woh, *wol, *ath, *atl;
    __nv_bfloat16 *qrh, *qrl, *krh, *krl, *vrh, *vrl;
    cudaGetSymbolAddress((void**)&hsh, g_hs_h);
    cudaGetSymbolAddress((void**)&hsl, g_hs_l);
    cudaGetSymbolAddress((void**)&wqh, g_wqT_h);
    cudaGetSymbolAddress((void**)&wql, g_wqT_l);
    cudaGetSymbolAddress((void**)&wkh, g_wkT_h);
    cudaGetSymbolAddress((void**)&wkl, g_wkT_l);
    cudaGetSymbolAddress((void**)&wvh, g_wvT_h);
    cudaGetSymbolAddress((void**)&wvl, g_wvT_l);
    cudaGetSymbolAddress((void**)&woh, g_woT_h);
    cudaGetSymbolAddress((void**)&wol, g_woT_l);
    cudaGetSymbolAddress((void**)&ath, g_att_h);
    cudaGetSymbolAddress((void**)&atl, g_att_l);
    cudaGetSymbolAddress((void**)&qrh, g_qr_h);
    cudaGetSymbolAddress((void**)&qrl, g_qr_l);
    cudaGetSymbolAddress((void**)&krh, g_kr_h);
    cudaGetSymbolAddress((void**)&krl, g_kr_l);
    cudaGetSymbolAddress((void**)&vrh, g_vr_h);
    cudaGetSymbolAddress((void**)&vrl, g_vr_l);

    cudaFuncSetAttribute(mma_gemm, cudaFuncAttributeMaxDynamicSharedMemorySize, GEMM_SMEM);
    cudaFuncSetAttribute(attn_mma, cudaFuncAttributeMaxDynamicSharedMemorySize, ATTN_SMEM);

    // 0: fused prep (hs split + 4 weight transposes)
    prep_all<<<dim3(128, 128, 5), dim3(32, 8)>>>(hs, Wq, Wk, Wv, Wo,
                                                 hsh, hsl, wqh, wql, wkh, wkl,
                                                 wvh, wvl, woh, wol);

    // 1-3: QKV projections
    mma_gemm<<<dim3(QD / 128, MR / 128), 256, GEMM_SMEM>>>(hsh, hsl, wqh, wql, qb, QD, HH);
    mma_gemm<<<dim3(KVD / 128, MR / 128), 256, GEMM_SMEM>>>(hsh, hsl, wkh, wkl, kb, KVD, HH);
    mma_gemm<<<dim3(KVD / 128, MR / 128), 256, GEMM_SMEM>>>(hsh, hsl, wvh, wvl, vb, KVD, HH);

    // 4: RoPE(Q,K) + split(V), fused
    rope_all<<<(NQR + NKR + NV4 + 255) / 256, 256>>>(qb, kb, vb, qrh, qrl,
                                                     krh, krl, vrh, vrl);

    // 5: causal GQA attention (capture slot for ncu -s 5)
    attn_mma<<<dim3(SS / 64, NH, BB), 256, ATTN_SMEM>>>(qrh, qrl, krh, krl,
                                                         vrh, vrl, ath, atl);

    // 6: O projection
    mma_gemm<<<dim3(HH / 128, MR / 128), 256, GEMM_SMEM>>>(ath, atl, woh, wol, out, HH, QD);
}

// round 13
// speedup vs baseline: 1.7178x; 1.0092x over previous
#include <cuda_runtime.h>
#include <cuda_bf16.h>
#include <math.h>
#include <stdint.h>

#define BB  2
#define SS  2048
#define HH  4096
#define NH  32
#define NKV 8
#define HD  128
#define MR  (BB * SS)      // 4096 rows
#define QD  (NH * HD)      // 4096
#define KVD (NKV * HD)     // 1024

// ---------------- scratch (device globals; no runtime allocation) ----------
__device__ float g_q[MR * QD];
__device__ float g_k[MR * KVD];
__device__ float g_v[MR * KVD];

__device__ __nv_bfloat16 g_hs_h[MR * HH];
__device__ __nv_bfloat16 g_hs_l[MR * HH];
__device__ __nv_bfloat16 g_wqT_h[QD * HH];
__device__ __nv_bfloat16 g_wqT_l[QD * HH];
__device__ __nv_bfloat16 g_wkT_h[KVD * HH];
__device__ __nv_bfloat16 g_wkT_l[KVD * HH];
__device__ __nv_bfloat16 g_wvT_h[KVD * HH];
__device__ __nv_bfloat16 g_wvT_l[KVD * HH];
__device__ __nv_bfloat16 g_woT_h[HH * QD];
__device__ __nv_bfloat16 g_woT_l[HH * QD];
__device__ __nv_bfloat16 g_att_h[MR * QD];
__device__ __nv_bfloat16 g_att_l[MR * QD];

// attention operands (post-RoPE, hi/lo split)
__device__ __nv_bfloat16 g_qr_h[MR * QD];
__device__ __nv_bfloat16 g_qr_l[MR * QD];
__device__ __nv_bfloat16 g_kr_h[MR * KVD];
__device__ __nv_bfloat16 g_kr_l[MR * KVD];
__device__ __nv_bfloat16 g_vr_h[MR * KVD];
__device__ __nv_bfloat16 g_vr_l[MR * KVD];

// ---------------- PTX helpers ----------------------------------------------
__device__ __forceinline__ uint32_t smem_u32(const void* p) {
    uint32_t a;
    asm("{ .reg .u64 t; cvta.to.shared.u64 t, %1; cvt.u32.u64 %0, t; }"
        : "=r"(a) : "l"(p));
    return a;
}
__device__ __forceinline__ void cpasync16(uint32_t dst, const void* src) {
    asm volatile("cp.async.cg.shared.global [%0], [%1], 16;"
                 :: "r"(dst), "l"(src));
}
#define CP_COMMIT() asm volatile("cp.async.commit_group;" ::: "memory")
#define CP_WAIT0()  asm volatile("cp.async.wait_group 0;" ::: "memory")
#define CP_WAIT1()  asm volatile("cp.async.wait_group 1;" ::: "memory")

#define LDSM4(r0, r1, r2, r3, addr) \
    asm volatile("ldmatrix.sync.aligned.m8n8.x4.shared.b16 {%0,%1,%2,%3}, [%4];" \
                 : "=r"(r0), "=r"(r1), "=r"(r2), "=r"(r3) : "r"(addr))

#define LDSM4T(r0, r1, r2, r3, addr) \
    asm volatile("ldmatrix.sync.aligned.m8n8.x4.trans.shared.b16 {%0,%1,%2,%3}, [%4];" \
                 : "=r"(r0), "=r"(r1), "=r"(r2), "=r"(r3) : "r"(addr))

#define MMA_BF16(c, a, b) \
    asm volatile("mma.sync.aligned.m16n8k16.row.col.f32.bf16.bf16.f32 " \
                 "{%0,%1,%2,%3}, {%4,%5,%6,%7}, {%8,%9}, {%0,%1,%2,%3};" \
                 : "+f"((c)[0]), "+f"((c)[1]), "+f"((c)[2]), "+f"((c)[3]) \
                 : "r"((a)[0]), "r"((a)[1]), "r"((a)[2]), "r"((a)[3]), \
                   "r"((b)[0]), "r"((b)[1]))

__device__ __forceinline__ void split2(float x, float y, uint32_t& h, uint32_t& l) {
    __nv_bfloat162 hb = __floats2bfloat162_rn(x, y);
    float2 hf = __bfloat1622float2(hb);
    __nv_bfloat162 lb = __floats2bfloat162_rn(x - hf.x, y - hf.y);
    h = *reinterpret_cast<uint32_t*>(&hb);
    l = *reinterpret_cast<uint32_t*>(&lb);
}

// ---------------------------------------------------------------------------
// prep_all: z=0 hs hi/lo split; z=1..4 weight transpose+split
// ---------------------------------------------------------------------------
__global__ void prep_all(const float* __restrict__ hs,
                         const float* __restrict__ Wq, const float* __restrict__ Wk,
                         const float* __restrict__ Wv, const float* __restrict__ Wo,
                         __nv_bfloat16* __restrict__ hsh, __nv_bfloat16* __restrict__ hsl,
                         __nv_bfloat16* __restrict__ wqh, __nv_bfloat16* __restrict__ wql,
                         __nv_bfloat16* __restrict__ wkh, __nv_bfloat16* __restrict__ wkl,
                         __nv_bfloat16* __restrict__ wvh, __nv_bfloat16* __restrict__ wvl,
                         __nv_bfloat16* __restrict__ woh, __nv_bfloat16* __restrict__ wol) {
    int z = blockIdx.z;
    int tx = threadIdx.x, ty = threadIdx.y;
    if (z == 0) {
        int i = (blockIdx.y * 128 + blockIdx.x) * 256 + ty * 32 + tx;
        float4 s = ((const float4*)hs)[i];
        __nv_bfloat162 h01 = __floats2bfloat162_rn(s.x, s.y);
        __nv_bfloat162 h23 = __floats2bfloat162_rn(s.z, s.w);
        float2 f01 = __bfloat1622float2(h01);
        float2 f23 = __bfloat1622float2(h23);
        __nv_bfloat162 l01 = __floats2bfloat162_rn(s.x - f01.x, s.y - f01.y);
        __nv_bfloat162 l23 = __floats2bfloat162_rn(s.z - f23.x, s.w - f23.y);
        ((__nv_bfloat162*)hsh)[2 * i]     = h01;
        ((__nv_bfloat162*)hsh)[2 * i + 1] = h23;
        ((__nv_bfloat162*)hsl)[2 * i]     = l01;
        ((__nv_bfloat162*)hsl)[2 * i + 1] = l23;
        return;
    }
    const float* W;
    __nv_bfloat16 *hiT, *loT;
    int K, N;
    if (z == 1)      { W = Wq; hiT = wqh; loT = wql; K = HH; N = QD; }
    else if (z == 2) { W = Wk; hiT = wkh; loT = wkl; K = HH; N = KVD; }
    else if (z == 3) { W = Wv; hiT = wvh; loT = wvl; K = HH; N = KVD; }
    else             { W = Wo; hiT = woh; loT = wol; K = QD; N = HH; }
    if (blockIdx.x * 32 >= N || blockIdx.y * 32 >= K) return;

    __shared__ float t[32][33];
    int n0 = blockIdx.x * 32, k0 = blockIdx.y * 32;
#pragma unroll
    for (int i = 0; i < 32; i += 8)
        t[ty + i][tx] = W[(size_t)(k0 + ty + i) * N + n0 + tx];
    __syncthreads();
#pragma unroll
    for (int i = 0; i < 32; i += 8) {
        float v = t[tx][ty + i];
        __nv_bfloat16 h = __float2bfloat16_rn(v);
        __nv_bfloat16 l = __float2bfloat16_rn(v - __bfloat162float(h));
        size_t o = (size_t)(n0 + ty + i) * K + k0 + tx;
        hiT[o] = h;
        loT[o] = l;
    }
}

// ---------------------------------------------------------------------------
// mma.sync bf16x3 GEMM body, dependency-spread pass ordering:
// per kk: load all A frags (i=0..3) + all B frags, then issue
// 16x hh, 16x hl, 16x lh MMAs (RAW distance 16 >> pipe latency).
// ---------------------------------------------------------------------------
#define TILE_B   10240
#define STAGE_B  (4 * TILE_B)
#define GEMM_SMEM (2 * STAGE_B)

__device__ __forceinline__ void gemm_body(
    const __nv_bfloat16* __restrict__ Ahi, const __nv_bfloat16* __restrict__ Alo,
    const __nv_bfloat16* __restrict__ Bhi, const __nv_bfloat16* __restrict__ Blo,
    float* __restrict__ C, int Nd, int Kd, int bm, int bn, char* smem) {
    const uint32_t sb = smem_u32(smem);
    const int tid = threadIdx.x;
    const int wid = tid >> 5, lid = tid & 31;
    const int wm = wid >> 2, wn = wid & 3;

    float c[4][4][4];
#pragma unroll
    for (int i = 0; i < 4; i++)
#pragma unroll
        for (int j = 0; j < 4; j++)
#pragma unroll
            for (int q = 0; q < 4; q++) c[i][j][q] = 0.f;

    const int rowA = lid & 15;
    const int khA  = (lid >> 4) << 3;
    const int nB   = ((lid >> 4) << 3) + (lid & 7);
    const int khB  = ((lid >> 3) & 1) << 3;

#define LOAD_STAGE(s, k0)                                                     \
    do {                                                                      \
        _Pragma("unroll")                                                     \
        for (int li = 0; li < 2; li++) {                                      \
            int id  = li * 256 + tid;                                         \
            int row = id >> 2, seg = id & 3;                                  \
            uint32_t so = sb + (s) * STAGE_B + row * 80 + seg * 16;           \
            size_t ga = (size_t)(bm + row) * Kd + (k0) + seg * 8;             \
            size_t gb = (size_t)(bn + row) * Kd + (k0) + seg * 8;             \
            cpasync16(so,              Ahi + ga);                             \
            cpasync16(so + TILE_B,     Alo + ga);                             \
            cpasync16(so + 2 * TILE_B, Bhi + gb);                             \
            cpasync16(so + 3 * TILE_B, Blo + gb);                             \
        }                                                                     \
        CP_COMMIT();                                                          \
    } while (0)

    const int nk = Kd >> 5;
    LOAD_STAGE(0, 0);

    for (int kt = 0; kt < nk; kt++) {
        CP_WAIT0();
        __syncthreads();
        if (kt + 1 < nk) LOAD_STAGE((kt + 1) & 1, (kt + 1) << 5);

        const uint32_t abase = sb + (kt & 1) * STAGE_B;
        const uint32_t bbase = abase + 2 * TILE_B;
#pragma unroll
        for (int kk = 0; kk < 32; kk += 16) {
            uint32_t bh[4][2], bl[4][2];
#pragma unroll
            for (int j2 = 0; j2 < 2; j2++) {
                uint32_t ba = bbase + (wn * 32 + j2 * 16 + nB) * 80 +
                              (kk + khB) * 2;
                LDSM4(bh[j2 * 2][0], bh[j2 * 2][1],
                      bh[j2 * 2 + 1][0], bh[j2 * 2 + 1][1], ba);
                LDSM4(bl[j2 * 2][0], bl[j2 * 2][1],
                      bl[j2 * 2 + 1][0], bl[j2 * 2 + 1][1], ba + TILE_B);
            }
            uint32_t ah[4][4], al[4][4];
#pragma unroll
            for (int i = 0; i < 4; i++) {
                uint32_t aa = abase + (wm * 64 + i * 16 + rowA) * 80 +
                              (kk + khA) * 2;
                LDSM4(ah[i][0], ah[i][1], ah[i][2], ah[i][3], aa);
                LDSM4(al[i][0], al[i][1], al[i][2], al[i][3], aa + TILE_B);
            }
            // pass 1: hi*hi (16 independent MMAs)
#pragma unroll
            for (int i = 0; i < 4; i++)
#pragma unroll
                for (int j = 0; j < 4; j++) MMA_BF16(c[i][j], ah[i], bh[j]);
            // pass 2: hi*lo
#pragma unroll
            for (int i = 0; i < 4; i++)
#pragma unroll
                for (int j = 0; j < 4; j++) MMA_BF16(c[i][j], ah[i], bl[j]);
            // pass 3: lo*hi
#pragma unroll
            for (int i = 0; i < 4; i++)
#pragma unroll
                for (int j = 0; j < 4; j++) MMA_BF16(c[i][j], al[i], bh[j]);
        }
        __syncthreads();
    }
#undef LOAD_STAGE

    const int g = lid >> 2, t4 = lid & 3;
#pragma unroll
    for (int i = 0; i < 4; i++) {
        int r0 = bm + wm * 64 + i * 16 + g;
#pragma unroll
        for (int j = 0; j < 4; j++) {
            int col = bn + wn * 32 + j * 8 + t4 * 2;
            *(float2*)&C[(size_t)r0 * Nd + col] =
                make_float2(c[i][j][0], c[i][j][1]);
            *(float2*)&C[(size_t)(r0 + 8) * Nd + col] =
                make_float2(c[i][j][2], c[i][j][3]);
        }
    }
}

// Generic GEMM (used for O projection)
__global__ __launch_bounds__(256, 2)
void mma_gemm(const __nv_bfloat16* __restrict__ Ahi,
              const __nv_bfloat16* __restrict__ Alo,
              const __nv_bfloat16* __restrict__ Bhi,
              const __nv_bfloat16* __restrict__ Blo,
              float* __restrict__ C, int Nd, int Kd) {
    extern __shared__ char smem[];
    gemm_body(Ahi, Alo, Bhi, Blo, C, Nd, Kd,
              blockIdx.y * 128, blockIdx.x * 128, smem);
}

// Fused QKV projection: grid (48, 32); bx selects target matrix.
__global__ __launch_bounds__(256, 2)
void mma_gemm_qkv(const __nv_bfloat16* __restrict__ Ahi,
                  const __nv_bfloat16* __restrict__ Alo,
                  const __nv_bfloat16* __restrict__ wqh, const __nv_bfloat16* __restrict__ wql,
                  const __nv_bfloat16* __restrict__ wkh, const __nv_bfloat16* __restrict__ wkl,
                  const __nv_bfloat16* __restrict__ wvh, const __nv_bfloat16* __restrict__ wvl,
                  float* __restrict__ Cq, float* __restrict__ Ck, float* __restrict__ Cv) {
    extern __shared__ char smem[];
    int bx = blockIdx.x;
    const __nv_bfloat16 *Bh, *Bl;
    float* C;
    int Nd, bn;
    if (bx < 32)      { Bh = wqh; Bl = wql; C = Cq; Nd = QD;  bn = bx * 128; }
    else if (bx < 40) { Bh = wkh; Bl = wkl; C = Ck; Nd = KVD; bn = (bx - 32) * 128; }
    else              { Bh = wvh; Bl = wvl; C = Cv; Nd = KVD; bn = (bx - 40) * 128; }
    gemm_body(Ahi, Alo, Bh, Bl, C, Nd, HH, blockIdx.y * 128, bn, smem);
}

// ---------------------------------------------------------------------------
// rope_all: RoPE+split for Q and K, plain split for V — one launch.
// ---------------------------------------------------------------------------
#define NQR (MR * NH * 64)
#define NKR (MR * NKV * 64)
#define NV4 (MR * KVD / 4)

__global__ void rope_all(const float* __restrict__ qs, const float* __restrict__ ks,
                         const float* __restrict__ vs,
                         __nv_bfloat16* __restrict__ qh, __nv_bfloat16* __restrict__ ql,
                         __nv_bfloat16* __restrict__ kh, __nv_bfloat16* __restrict__ kl,
                         __nv_bfloat16* __restrict__ vh, __nv_bfloat16* __restrict__ vl) {
    int idx = blockIdx.x * blockDim.x + threadIdx.x;
    if (idx < NQR + NKR) {
        const float* buf;
        __nv_bfloat16 *oh, *ol;
        int nheads;
        if (idx < NQR) { buf = qs; oh = qh; ol = ql; nheads = NH; }
        else { idx -= NQR; buf = ks; oh = kh; ol = kl; nheads = NKV; }
        int i    = idx & 63;
        int head = (idx >> 6) % nheads;
        int row  = idx / (nheads << 6);
        float p    = (float)(row % SS);
        float invf = expf(-(float)i * 0.14391156831212787f);
        float ang  = p * invf;
        float c, s;
        sincosf(ang, &s, &c);
        size_t base = (size_t)row * (nheads * HD) + head * HD + i;
        float x0 = buf[base];
        float x1 = buf[base + 64];
        float y0 = x0 * c - x1 * s;
        float y1 = x1 * c + x0 * s;
        __nv_bfloat16 h0 = __float2bfloat16_rn(y0);
        __nv_bfloat16 h1 = __float2bfloat16_rn(y1);
        oh[base]      = h0;
        oh[base + 64] = h1;
        ol[base]      = __float2bfloat16_rn(y0 - __bfloat162float(h0));
        ol[base + 64] = __float2bfloat16_rn(y1 - __bfloat162float(h1));
        return;
    }
    idx -= NQR + NKR;
    if (idx >= NV4) return;
    float4 s = ((const float4*)vs)[idx];
    __nv_bfloat162 h01 = __floats2bfloat162_rn(s.x, s.y);
    __nv_bfloat162 h23 = __floats2bfloat162_rn(s.z, s.w);
    float2 f01 = __bfloat1622float2(h01);
    float2 f23 = __bfloat1622float2(h23);
    ((__nv_bfloat162*)vh)[2 * idx]     = h01;
    ((__nv_bfloat162*)vh)[2 * idx + 1] = h23;
    ((__nv_bfloat162*)vl)[2 * idx]     = __floats2bfloat162_rn(s.x - f01.x, s.y - f01.y);
    ((__nv_bfloat162*)vl)[2 * idx + 1] = __floats2bfloat162_rn(s.z - f23.x, s.w - f23.y);
}

// ---------------------------------------------------------------------------
// Tensor-core causal flash attention, bf16x3, low register pressure.
// (unchanged from R12 — 0.5-0.6 ms, not the bottleneck)
// ---------------------------------------------------------------------------
#define APITCH 272
#define ATK   (64 * APITCH)            // 17408
#define SKV   (4 * ATK)
#define PPITCH 144
#define PTILE (64 * PPITCH)            // 9216
#define OFF_KV (2 * ATK)
#define OFF_P  (OFF_KV + 2 * SKV)
#define OFF_MX (OFF_P + 2 * PTILE)
#define OFF_SM (OFF_MX + 2 * 64 * 4)
#define ATTN_SMEM (OFF_SM + 2 * 64 * 4)

__global__ __launch_bounds__(256, 1)
void attn_mma(const __nv_bfloat16* __restrict__ Qh, const __nv_bfloat16* __restrict__ Ql,
              const __nv_bfloat16* __restrict__ Kh, const __nv_bfloat16* __restrict__ Kl,
              const __nv_bfloat16* __restrict__ Vh, const __nv_bfloat16* __restrict__ Vl,
              __nv_bfloat16* __restrict__ Oh, __nv_bfloat16* __restrict__ Ol) {
    extern __shared__ char smem[];
    const uint32_t sb = smem_u32(smem);
    const int tid = threadIdx.x;
    const int wid = tid >> 5, lid = tid & 31;
    const int g = lid >> 2, t4 = lid & 3;
    const int half = wid >> 2, rw = wid & 3;
    const int qb = gridDim.x - 1 - blockIdx.x;   // big tiles first
    const int h = blockIdx.y, b = blockIdx.z;
    const int kvh = h >> 2;
    const int q0 = qb * 64;

    const uint32_t sQh = sb, sQl = sb + ATK;
    const uint32_t kvb = sb + OFF_KV;
    const uint32_t sPh = sb + OFF_P;

    // Q tile (64 rows), hi+lo
#pragma unroll
    for (int t = 0; t < 4; t++) {
        int id = t * 256 + tid;
        int row = id >> 4, seg = id & 15;
        uint32_t so = row * APITCH + seg * 16;
        size_t gq = (size_t)(b * SS + q0 + row) * QD + h * HD + seg * 8;
        cpasync16(sQh + so, Qh + gq);
        cpasync16(sQl + so, Ql + gq);
    }
    CP_COMMIT();

#define LOAD_KV(s, kt)                                                        \
    do {                                                                      \
        _Pragma("unroll")                                                     \
        for (int t = 0; t < 4; t++) {                                         \
            int id = t * 256 + tid;                                           \
            int row = id >> 4, seg = id & 15;                                 \
            uint32_t so = kvb + (s) * SKV + row * APITCH + seg * 16;          \
            size_t gk = (size_t)(b * SS + (kt) * 64 + row) * KVD +            \
                        kvh * HD + seg * 8;                                   \
            cpasync16(so,           Kh + gk);                                 \
            cpasync16(so + ATK,     Kl + gk);                                 \
            cpasync16(so + 2 * ATK, Vh + gk);                                 \
            cpasync16(so + 3 * ATK, Vl + gk);                                 \
        }                                                                     \
        CP_COMMIT();                                                          \
    } while (0)

    float o[8][4];
#pragma unroll
    for (int n = 0; n < 8; n++)
#pragma unroll
        for (int q = 0; q < 4; q++) o[n][q] = 0.f;
    float m[2] = {-1e30f, -1e30f}, l[2] = {0.f, 0.f};

    const int rowA = lid & 15, khA = (lid >> 4) << 3;
    const int nB = ((lid >> 4) << 3) + (lid & 7);
    const int khB = ((lid >> 3) & 1) << 3;
    const int kV = (((lid >> 3) & 1) << 3) + (lid & 7);
    const int nVo = (lid >> 4) << 3;

    const float scale = 0.08838834764831845f;
    const int nkt = qb + 1;

    LOAD_KV(0, 0);

    for (int kt = 0; kt < nkt; kt++) {
        if (kt + 1 < nkt) {
            LOAD_KV((kt + 1) & 1, kt + 1);
            CP_WAIT1();
        } else {
            CP_WAIT0();
        }
        __syncthreads();

        const uint32_t sKh = kvb + (kt & 1) * SKV;
        const uint32_t sVh = sKh + 2 * ATK;
        const int k0t = kt * 64;

        // ---- S (this warp: 32 kv cols at half*32) ----
        float sc[4][4];
#pragma unroll
        for (int j = 0; j < 4; j++)
#pragma unroll
            for (int q = 0; q < 4; q++) sc[j][q] = 0.f;

#pragma unroll
        for (int kk = 0; kk < 8; kk++) {
            uint32_t qhf[4], qlf[4];
            uint32_t qa = sQh + (rw * 16 + rowA) * APITCH + (kk * 16 + khA) * 2;
            LDSM4(qhf[0], qhf[1], qhf[2], qhf[3], qa);
            LDSM4(qlf[0], qlf[1], qlf[2], qlf[3], qa + ATK);
#pragma unroll
            for (int jp = 0; jp < 2; jp++) {
                uint32_t kh0[2], kh1[2], kl0[2], kl1[2];
                uint32_t ka = sKh + (half * 32 + jp * 16 + nB) * APITCH +
                              (kk * 16 + khB) * 2;
                LDSM4(kh0[0], kh0[1], kh1[0], kh1[1], ka);
                LDSM4(kl0[0], kl0[1], kl1[0], kl1[1], ka + ATK);
                MMA_BF16(sc[2 * jp],     qhf, kh0);
                MMA_BF16(sc[2 * jp + 1], qhf, kh1);
                MMA_BF16(sc[2 * jp],     qhf, kl0);
                MMA_BF16(sc[2 * jp + 1], qhf, kl1);
                MMA_BF16(sc[2 * jp],     qlf, kh0);
                MMA_BF16(sc[2 * jp + 1], qlf, kh1);
            }
        }

        // scale + causal mask (diagonal tile only)
#pragma unroll
        for (int j = 0; j < 4; j++)
#pragma unroll
            for (int q = 0; q < 4; q++) sc[j][q] *= scale;
        if (kt == qb) {
            int r0 = q0 + rw * 16 + g, r1 = r0 + 8;
#pragma unroll
            for (int j = 0; j < 4; j++) {
                int c0 = k0t + half * 32 + j * 8 + 2 * t4, c1 = c0 + 1;
                if (c0 > r0) sc[j][0] = -1e30f;
                if (c1 > r0) sc[j][1] = -1e30f;
                if (c0 > r1) sc[j][2] = -1e30f;
                if (c1 > r1) sc[j][3] = -1e30f;
            }
        }

        // ---- partial row max -> smem ----
        float pm[2];
#pragma unroll
        for (int r = 0; r < 2; r++) {
            float mx = -1e30f;
#pragma unroll
            for (int j = 0; j < 4; j++)
                mx = fmaxf(mx, fmaxf(sc[j][2 * r], sc[j][2 * r + 1]));
            mx = fmaxf(mx, __shfl_xor_sync(0xffffffffu, mx, 1));
            mx = fmaxf(mx, __shfl_xor_sync(0xffffffffu, mx, 2));
            pm[r] = mx;
            if (t4 == 0)
                *(float*)(smem + OFF_MX + (half * 64 + rw * 16 + g + 8 * r) * 4) = mx;
        }
        __syncthreads();   // bar1: partial maxima visible

        // ---- combine max; P = exp; partial sums; P->smem ----
        float corr[2];
#pragma unroll
        for (int r = 0; r < 2; r++) {
            int row = rw * 16 + g + 8 * r;
            float po = *(float*)(smem + OFF_MX + ((1 - half) * 64 + row) * 4);
            float mn = fmaxf(m[r], fmaxf(pm[r], po));
            corr[r] = __expf(m[r] - mn);
            m[r] = mn;
            float rs = 0.f;
#pragma unroll
            for (int j = 0; j < 4; j++) {
                float p0 = __expf(sc[j][2 * r] - mn);
                float p1 = __expf(sc[j][2 * r + 1] - mn);
                sc[j][2 * r] = p0;
                sc[j][2 * r + 1] = p1;
                rs += p0 + p1;
            }
            rs += __shfl_xor_sync(0xffffffffu, rs, 1);
            rs += __shfl_xor_sync(0xffffffffu, rs, 2);
            if (t4 == 0)
                *(float*)(smem + OFF_SM + (half * 64 + row) * 4) = rs;
            // store P (bf16 hi/lo) to smem
#pragma unroll
            for (int j = 0; j < 4; j++) {
                uint32_t hh, ll;
                split2(sc[j][2 * r], sc[j][2 * r + 1], hh, ll);
                uint32_t pa = row * PPITCH + (half * 32 + j * 8 + 2 * t4) * 2;
                *(uint32_t*)(smem + OFF_P + pa) = hh;
                *(uint32_t*)(smem + OFF_P + PTILE + pa) = ll;
            }
            // rescale O
#pragma unroll
            for (int n = 0; n < 8; n++) {
                o[n][2 * r] *= corr[r];
                o[n][2 * r + 1] *= corr[r];
            }
        }
        __syncthreads();   // bar2: P + sums visible

#pragma unroll
        for (int r = 0; r < 2; r++) {
            int row = rw * 16 + g + 8 * r;
            float ls = *(float*)(smem + OFF_SM + row * 4) +
                       *(float*)(smem + OFF_SM + (64 + row) * 4);
            l[r] = l[r] * corr[r] + ls;
        }

        // ---- O += P V (full 64 kv, this warp's HD half) ----
#pragma unroll
        for (int j2 = 0; j2 < 4; j2++) {
            uint32_t ph[4], pl[4];
            uint32_t pa = sPh + (rw * 16 + rowA) * PPITCH + (j2 * 16 + khA) * 2;
            LDSM4(ph[0], ph[1], ph[2], ph[3], pa);
            LDSM4(pl[0], pl[1], pl[2], pl[3], pa + PTILE);
#pragma unroll
            for (int np = 0; np < 4; np++) {
                uint32_t vh0[2], vh1[2], vl0[2], vl1[2];
                uint32_t va = sVh + (j2 * 16 + kV) * APITCH +
                              (half * 64 + np * 16 + nVo) * 2;
                LDSM4T(vh0[0], vh0[1], vh1[0], vh1[1], va);
                LDSM4T(vl0[0], vl0[1], vl1[0], vl1[1], va + ATK);
                MMA_BF16(o[2 * np],     ph, vh0);
                MMA_BF16(o[2 * np + 1], ph, vh1);
                MMA_BF16(o[2 * np],     ph, vl0);
                MMA_BF16(o[2 * np + 1], ph, vl1);
                MMA_BF16(o[2 * np],     pl, vh0);
                MMA_BF16(o[2 * np + 1], pl, vh1);
            }
        }
        __syncthreads();   // protect P/stats/KV for next iteration
    }
#undef LOAD_KV

    // ---- finalize: normalize + hi/lo split + store ----
    float inv0 = 1.f / l[0], inv1 = 1.f / l[1];
    size_t r0g = (size_t)(b * SS + q0 + rw * 16 + g) * QD + h * HD + half * 64;
    size_t r1g = r0g + 8 * QD;
#pragma unroll
    for (int n = 0; n < 8; n++) {
        int col = n * 8 + 2 * t4;
        uint32_t hh, ll;
        split2(o[n][0] * inv0, o[n][1] * inv0, hh, ll);
        *(uint32_t*)&Oh[r0g + col] = hh;
        *(uint32_t*)&Ol[r0g + col] = ll;
        split2(o[n][2] * inv1, o[n][3] * inv1, hh, ll);
        *(uint32_t*)&Oh[r1g + col] = hh;
        *(uint32_t*)&Ol[r1g + col] = ll;
    }
}

// ---------------------------------------------------------------------------
extern "C" void kernel_launch(void* const* d_in, const int* in_sizes, int n_in,
                              void* d_out, int out_size) {
    const float* hs  = (const float*)d_in[0];
    const float* Wq  = (const float*)d_in[2];
    const float* Wk  = (const float*)d_in[3];
    const float* Wv  = (const float*)d_in[4];
    const float* Wo  = (const float*)d_in[5];
    float*       out = (float*)d_out;

    float *qb, *kb, *vb;
    cudaGetSymbolAddress((void**)&qb, g_q);
    cudaGetSymbolAddress((void**)&kb, g_k);
    cudaGetSymbolAddress((void**)&vb, g_v);

    __nv_bfloat16 *hsh, *hsl, *wqh, *wql, *wkh, *wkl, *wvh, *wvl, *woh, *wol, *ath, *atl;
    __nv_bfloat16 *qrh, *qrl, *krh, *krl, *vrh, *vrl;
    cudaGetSymbolAddress((void**)&hsh, g_hs_h);
    cudaGetSymbolAddress((void**)&hsl, g_hs_l);
    cudaGetSymbolAddress((void**)&wqh, g_wqT_h);
    cudaGetSymbolAddress((void**)&wql, g_wqT_l);
    cudaGetSymbolAddress((void**)&wkh, g_wkT_h);
    cudaGetSymbolAddress((void**)&wkl, g_wkT_l);
    cudaGetSymbolAddress((void**)&wvh, g_wvT_h);
    cudaGetSymbolAddress((void**)&wvl, g_wvT_l);
    cudaGetSymbolAddress((void**)&woh, g_woT_h);
    cudaGetSymbolAddress((void**)&wol, g_woT_l);
    cudaGetSymbolAddress((void**)&ath, g_att_h);
    cudaGetSymbolAddress((void**)&atl, g_att_l);
    cudaGetSymbolAddress((void**)&qrh, g_qr_h);
    cudaGetSymbolAddress((void**)&qrl, g_qr_l);
    cudaGetSymbolAddress((void**)&krh, g_kr_h);
    cudaGetSymbolAddress((void**)&krl, g_kr_l);
    cudaGetSymbolAddress((void**)&vrh, g_vr_h);
    cudaGetSymbolAddress((void**)&vrl, g_vr_l);

    cudaFuncSetAttribute(mma_gemm, cudaFuncAttributeMaxDynamicSharedMemorySize, GEMM_SMEM);
    cudaFuncSetAttribute(mma_gemm_qkv, cudaFuncAttributeMaxDynamicSharedMemorySize, GEMM_SMEM);
    cudaFuncSetAttribute(attn_mma, cudaFuncAttributeMaxDynamicSharedMemorySize, ATTN_SMEM);

    // 0: fused prep (hs split + 4 weight transposes)
    prep_all<<<dim3(128, 128, 5), dim3(32, 8)>>>(hs, Wq, Wk, Wv, Wo,
                                                 hsh, hsl, wqh, wql, wkh, wkl,
                                                 wvh, wvl, woh, wol);

    // 1: fused QKV projection (one launch, merged tails)
    mma_gemm_qkv<<<dim3(48, MR / 128), 256, GEMM_SMEM>>>(hsh, hsl,
                                                          wqh, wql, wkh, wkl,
                                                          wvh, wvl, qb, kb, vb);

    // 2: RoPE(Q,K) + split(V), fused
    rope_all<<<(NQR + NKR + NV4 + 255) / 256, 256>>>(qb, kb, vb, qrh, qrl,
                                                     krh, krl, vrh, vrl);

    // 3: causal GQA attention
    attn_mma<<<dim3(SS / 64, NH, BB), 256, ATTN_SMEM>>>(qrh, qrl, krh, krl,
                                                         vrh, vrl, ath, atl);

    // 4: O projection
    mma_gemm<<<dim3(HH / 128, MR / 128), 256, GEMM_SMEM>>>(ath, atl, woh, wol, out, HH, QD);
}

// round 14
// speedup vs baseline: 1.7487x; 1.0180x over previous
#include <cuda_runtime.h>
#include <cuda_bf16.h>
#include <math.h>
#include <stdint.h>

#define BB  2
#define SS  2048
#define HH  4096
#define NH  32
#define NKV 8
#define HD  128
#define MR  (BB * SS)      // 4096 rows
#define QD  (NH * HD)      // 4096
#define KVD (NKV * HD)     // 1024

// ---------------- scratch (device globals; no runtime allocation) ----------
__device__ float g_q[MR * QD];
__device__ float g_k[MR * KVD];
__device__ float g_v[MR * KVD];

__device__ __nv_bfloat16 g_hs_h[MR * HH];
__device__ __nv_bfloat16 g_hs_l[MR * HH];
__device__ __nv_bfloat16 g_wqT_h[QD * HH];
__device__ __nv_bfloat16 g_wqT_l[QD * HH];
__device__ __nv_bfloat16 g_wkT_h[KVD * HH];
__device__ __nv_bfloat16 g_wkT_l[KVD * HH];
__device__ __nv_bfloat16 g_wvT_h[KVD * HH];
__device__ __nv_bfloat16 g_wvT_l[KVD * HH];
__device__ __nv_bfloat16 g_woT_h[HH * QD];
__device__ __nv_bfloat16 g_woT_l[HH * QD];
__device__ __nv_bfloat16 g_att_h[MR * QD];
__device__ __nv_bfloat16 g_att_l[MR * QD];

// attention operands (post-RoPE, hi/lo split)
__device__ __nv_bfloat16 g_qr_h[MR * QD];
__device__ __nv_bfloat16 g_qr_l[MR * QD];
__device__ __nv_bfloat16 g_kr_h[MR * KVD];
__device__ __nv_bfloat16 g_kr_l[MR * KVD];
__device__ __nv_bfloat16 g_vr_h[MR * KVD];
__device__ __nv_bfloat16 g_vr_l[MR * KVD];

// ---------------- PTX helpers ----------------------------------------------
__device__ __forceinline__ uint32_t smem_u32(const void* p) {
    uint32_t a;
    asm("{ .reg .u64 t; cvta.to.shared.u64 t, %1; cvt.u32.u64 %0, t; }"
        : "=r"(a) : "l"(p));
    return a;
}
__device__ __forceinline__ void cpasync16(uint32_t dst, const void* src) {
    asm volatile("cp.async.cg.shared.global [%0], [%1], 16;"
                 :: "r"(dst), "l"(src));
}
#define CP_COMMIT() asm volatile("cp.async.commit_group;" ::: "memory")
#define CP_WAIT0()  asm volatile("cp.async.wait_group 0;" ::: "memory")

#define LDSM4(r0, r1, r2, r3, addr) \
    asm volatile("ldmatrix.sync.aligned.m8n8.x4.shared.b16 {%0,%1,%2,%3}, [%4];" \
                 : "=r"(r0), "=r"(r1), "=r"(r2), "=r"(r3) : "r"(addr))

#define LDSM4T(r0, r1, r2, r3, addr) \
    asm volatile("ldmatrix.sync.aligned.m8n8.x4.trans.shared.b16 {%0,%1,%2,%3}, [%4];" \
                 : "=r"(r0), "=r"(r1), "=r"(r2), "=r"(r3) : "r"(addr))

#define MMA_BF16(c, a, b) \
    asm volatile("mma.sync.aligned.m16n8k16.row.col.f32.bf16.bf16.f32 " \
                 "{%0,%1,%2,%3}, {%4,%5,%6,%7}, {%8,%9}, {%0,%1,%2,%3};" \
                 : "+f"((c)[0]), "+f"((c)[1]), "+f"((c)[2]), "+f"((c)[3]) \
                 : "r"((a)[0]), "r"((a)[1]), "r"((a)[2]), "r"((a)[3]), \
                   "r"((b)[0]), "r"((b)[1]))

__device__ __forceinline__ void split2(float x, float y, uint32_t& h, uint32_t& l) {
    __nv_bfloat162 hb = __floats2bfloat162_rn(x, y);
    float2 hf = __bfloat1622float2(hb);
    __nv_bfloat162 lb = __floats2bfloat162_rn(x - hf.x, y - hf.y);
    h = *reinterpret_cast<uint32_t*>(&hb);
    l = *reinterpret_cast<uint32_t*>(&lb);
}

// ---------------------------------------------------------------------------
// prep_all: z=0 hs hi/lo split; z=1..4 weight transpose+split
// ---------------------------------------------------------------------------
__global__ void prep_all(const float* __restrict__ hs,
                         const float* __restrict__ Wq, const float* __restrict__ Wk,
                         const float* __restrict__ Wv, const float* __restrict__ Wo,
                         __nv_bfloat16* __restrict__ hsh, __nv_bfloat16* __restrict__ hsl,
                         __nv_bfloat16* __restrict__ wqh, __nv_bfloat16* __restrict__ wql,
                         __nv_bfloat16* __restrict__ wkh, __nv_bfloat16* __restrict__ wkl,
                         __nv_bfloat16* __restrict__ wvh, __nv_bfloat16* __restrict__ wvl,
                         __nv_bfloat16* __restrict__ woh, __nv_bfloat16* __restrict__ wol) {
    int z = blockIdx.z;
    int tx = threadIdx.x, ty = threadIdx.y;
    if (z == 0) {
        int i = (blockIdx.y * 128 + blockIdx.x) * 256 + ty * 32 + tx;
        float4 s = ((const float4*)hs)[i];
        __nv_bfloat162 h01 = __floats2bfloat162_rn(s.x, s.y);
        __nv_bfloat162 h23 = __floats2bfloat162_rn(s.z, s.w);
        float2 f01 = __bfloat1622float2(h01);
        float2 f23 = __bfloat1622float2(h23);
        __nv_bfloat162 l01 = __floats2bfloat162_rn(s.x - f01.x, s.y - f01.y);
        __nv_bfloat162 l23 = __floats2bfloat162_rn(s.z - f23.x, s.w - f23.y);
        ((__nv_bfloat162*)hsh)[2 * i]     = h01;
        ((__nv_bfloat162*)hsh)[2 * i + 1] = h23;
        ((__nv_bfloat162*)hsl)[2 * i]     = l01;
        ((__nv_bfloat162*)hsl)[2 * i + 1] = l23;
        return;
    }
    const float* W;
    __nv_bfloat16 *hiT, *loT;
    int K, N;
    if (z == 1)      { W = Wq; hiT = wqh; loT = wql; K = HH; N = QD; }
    else if (z == 2) { W = Wk; hiT = wkh; loT = wkl; K = HH; N = KVD; }
    else if (z == 3) { W = Wv; hiT = wvh; loT = wvl; K = HH; N = KVD; }
    else             { W = Wo; hiT = woh; loT = wol; K = QD; N = HH; }
    if (blockIdx.x * 32 >= N || blockIdx.y * 32 >= K) return;

    __shared__ float t[32][33];
    int n0 = blockIdx.x * 32, k0 = blockIdx.y * 32;
#pragma unroll
    for (int i = 0; i < 32; i += 8)
        t[ty + i][tx] = W[(size_t)(k0 + ty + i) * N + n0 + tx];
    __syncthreads();
#pragma unroll
    for (int i = 0; i < 32; i += 8) {
        float v = t[tx][ty + i];
        __nv_bfloat16 h = __float2bfloat16_rn(v);
        __nv_bfloat16 l = __float2bfloat16_rn(v - __bfloat162float(h));
        size_t o = (size_t)(n0 + ty + i) * K + k0 + tx;
        hiT[o] = h;
        loT[o] = l;
    }
}

// ---------------------------------------------------------------------------
// mma.sync bf16x3 GEMM body (R13 version — unchanged)
// ---------------------------------------------------------------------------
#define TILE_B   10240
#define STAGE_B  (4 * TILE_B)
#define GEMM_SMEM (2 * STAGE_B)

__device__ __forceinline__ void gemm_body(
    const __nv_bfloat16* __restrict__ Ahi, const __nv_bfloat16* __restrict__ Alo,
    const __nv_bfloat16* __restrict__ Bhi, const __nv_bfloat16* __restrict__ Blo,
    float* __restrict__ C, int Nd, int Kd, int bm, int bn, char* smem) {
    const uint32_t sb = smem_u32(smem);
    const int tid = threadIdx.x;
    const int wid = tid >> 5, lid = tid & 31;
    const int wm = wid >> 2, wn = wid & 3;

    float c[4][4][4];
#pragma unroll
    for (int i = 0; i < 4; i++)
#pragma unroll
        for (int j = 0; j < 4; j++)
#pragma unroll
            for (int q = 0; q < 4; q++) c[i][j][q] = 0.f;

    const int rowA = lid & 15;
    const int khA  = (lid >> 4) << 3;
    const int nB   = ((lid >> 4) << 3) + (lid & 7);
    const int khB  = ((lid >> 3) & 1) << 3;

#define LOAD_STAGE(s, k0)                                                     \
    do {                                                                      \
        _Pragma("unroll")                                                     \
        for (int li = 0; li < 2; li++) {                                      \
            int id  = li * 256 + tid;                                         \
            int row = id >> 2, seg = id & 3;                                  \
            uint32_t so = sb + (s) * STAGE_B + row * 80 + seg * 16;           \
            size_t ga = (size_t)(bm + row) * Kd + (k0) + seg * 8;             \
            size_t gb = (size_t)(bn + row) * Kd + (k0) + seg * 8;             \
            cpasync16(so,              Ahi + ga);                             \
            cpasync16(so + TILE_B,     Alo + ga);                             \
            cpasync16(so + 2 * TILE_B, Bhi + gb);                             \
            cpasync16(so + 3 * TILE_B, Blo + gb);                             \
        }                                                                     \
        CP_COMMIT();                                                          \
    } while (0)

    const int nk = Kd >> 5;
    LOAD_STAGE(0, 0);

    for (int kt = 0; kt < nk; kt++) {
        CP_WAIT0();
        __syncthreads();
        if (kt + 1 < nk) LOAD_STAGE((kt + 1) & 1, (kt + 1) << 5);

        const uint32_t abase = sb + (kt & 1) * STAGE_B;
        const uint32_t bbase = abase + 2 * TILE_B;
#pragma unroll
        for (int kk = 0; kk < 32; kk += 16) {
            uint32_t bh[4][2], bl[4][2];
#pragma unroll
            for (int j2 = 0; j2 < 2; j2++) {
                uint32_t ba = bbase + (wn * 32 + j2 * 16 + nB) * 80 +
                              (kk + khB) * 2;
                LDSM4(bh[j2 * 2][0], bh[j2 * 2][1],
                      bh[j2 * 2 + 1][0], bh[j2 * 2 + 1][1], ba);
                LDSM4(bl[j2 * 2][0], bl[j2 * 2][1],
                      bl[j2 * 2 + 1][0], bl[j2 * 2 + 1][1], ba + TILE_B);
            }
            uint32_t ah[4][4], al[4][4];
#pragma unroll
            for (int i = 0; i < 4; i++) {
                uint32_t aa = abase + (wm * 64 + i * 16 + rowA) * 80 +
                              (kk + khA) * 2;
                LDSM4(ah[i][0], ah[i][1], ah[i][2], ah[i][3], aa);
                LDSM4(al[i][0], al[i][1], al[i][2], al[i][3], aa + TILE_B);
            }
#pragma unroll
            for (int i = 0; i < 4; i++)
#pragma unroll
                for (int j = 0; j < 4; j++) MMA_BF16(c[i][j], ah[i], bh[j]);
#pragma unroll
            for (int i = 0; i < 4; i++)
#pragma unroll
                for (int j = 0; j < 4; j++) MMA_BF16(c[i][j], ah[i], bl[j]);
#pragma unroll
            for (int i = 0; i < 4; i++)
#pragma unroll
                for (int j = 0; j < 4; j++) MMA_BF16(c[i][j], al[i], bh[j]);
        }
        __syncthreads();
    }
#undef LOAD_STAGE

    const int g = lid >> 2, t4 = lid & 3;
#pragma unroll
    for (int i = 0; i < 4; i++) {
        int r0 = bm + wm * 64 + i * 16 + g;
#pragma unroll
        for (int j = 0; j < 4; j++) {
            int col = bn + wn * 32 + j * 8 + t4 * 2;
            *(float2*)&C[(size_t)r0 * Nd + col] =
                make_float2(c[i][j][0], c[i][j][1]);
            *(float2*)&C[(size_t)(r0 + 8) * Nd + col] =
                make_float2(c[i][j][2], c[i][j][3]);
        }
    }
}

__global__ __launch_bounds__(256, 2)
void mma_gemm(const __nv_bfloat16* __restrict__ Ahi,
              const __nv_bfloat16* __restrict__ Alo,
              const __nv_bfloat16* __restrict__ Bhi,
              const __nv_bfloat16* __restrict__ Blo,
              float* __restrict__ C, int Nd, int Kd) {
    extern __shared__ char smem[];
    gemm_body(Ahi, Alo, Bhi, Blo, C, Nd, Kd,
              blockIdx.y * 128, blockIdx.x * 128, smem);
}

__global__ __launch_bounds__(256, 2)
void mma_gemm_qkv(const __nv_bfloat16* __restrict__ Ahi,
                  const __nv_bfloat16* __restrict__ Alo,
                  const __nv_bfloat16* __restrict__ wqh, const __nv_bfloat16* __restrict__ wql,
                  const __nv_bfloat16* __restrict__ wkh, const __nv_bfloat16* __restrict__ wkl,
                  const __nv_bfloat16* __restrict__ wvh, const __nv_bfloat16* __restrict__ wvl,
                  float* __restrict__ Cq, float* __restrict__ Ck, float* __restrict__ Cv) {
    extern __shared__ char smem[];
    int bx = blockIdx.x;
    const __nv_bfloat16 *Bh, *Bl;
    float* C;
    int Nd, bn;
    if (bx < 32)      { Bh = wqh; Bl = wql; C = Cq; Nd = QD;  bn = bx * 128; }
    else if (bx < 40) { Bh = wkh; Bl = wkl; C = Ck; Nd = KVD; bn = (bx - 32) * 128; }
    else              { Bh = wvh; Bl = wvl; C = Cv; Nd = KVD; bn = (bx - 40) * 128; }
    gemm_body(Ahi, Alo, Bh, Bl, C, Nd, HH, blockIdx.y * 128, bn, smem);
}

// ---------------------------------------------------------------------------
// rope_all: RoPE+split for Q and K, plain split for V — one launch.
// ---------------------------------------------------------------------------
#define NQR (MR * NH * 64)
#define NKR (MR * NKV * 64)
#define NV4 (MR * KVD / 4)

__global__ void rope_all(const float* __restrict__ qs, const float* __restrict__ ks,
                         const float* __restrict__ vs,
                         __nv_bfloat16* __restrict__ qh, __nv_bfloat16* __restrict__ ql,
                         __nv_bfloat16* __restrict__ kh, __nv_bfloat16* __restrict__ kl,
                         __nv_bfloat16* __restrict__ vh, __nv_bfloat16* __restrict__ vl) {
    int idx = blockIdx.x * blockDim.x + threadIdx.x;
    if (idx < NQR + NKR) {
        const float* buf;
        __nv_bfloat16 *oh, *ol;
        int nheads;
        if (idx < NQR) { buf = qs; oh = qh; ol = ql; nheads = NH; }
        else { idx -= NQR; buf = ks; oh = kh; ol = kl; nheads = NKV; }
        int i    = idx & 63;
        int head = (idx >> 6) % nheads;
        int row  = idx / (nheads << 6);
        float p    = (float)(row % SS);
        float invf = expf(-(float)i * 0.14391156831212787f);
        float ang  = p * invf;
        float c, s;
        sincosf(ang, &s, &c);
        size_t base = (size_t)row * (nheads * HD) + head * HD + i;
        float x0 = buf[base];
        float x1 = buf[base + 64];
        float y0 = x0 * c - x1 * s;
        float y1 = x1 * c + x0 * s;
        __nv_bfloat16 h0 = __float2bfloat16_rn(y0);
        __nv_bfloat16 h1 = __float2bfloat16_rn(y1);
        oh[base]      = h0;
        oh[base + 64] = h1;
        ol[base]      = __float2bfloat16_rn(y0 - __bfloat162float(h0));
        ol[base + 64] = __float2bfloat16_rn(y1 - __bfloat162float(h1));
        return;
    }
    idx -= NQR + NKR;
    if (idx >= NV4) return;
    float4 s = ((const float4*)vs)[idx];
    __nv_bfloat162 h01 = __floats2bfloat162_rn(s.x, s.y);
    __nv_bfloat162 h23 = __floats2bfloat162_rn(s.z, s.w);
    float2 f01 = __bfloat1622float2(h01);
    float2 f23 = __bfloat1622float2(h23);
    ((__nv_bfloat162*)vh)[2 * idx]     = h01;
    ((__nv_bfloat162*)vh)[2 * idx + 1] = h23;
    ((__nv_bfloat162*)vl)[2 * idx]     = __floats2bfloat162_rn(s.x - f01.x, s.y - f01.y);
    ((__nv_bfloat162*)vl)[2 * idx + 1] = __floats2bfloat162_rn(s.z - f23.x, s.w - f23.y);
}

// ---------------------------------------------------------------------------
// Tensor-core causal flash attention, bf16x3 — 2 CTAs/SM version.
// CTA: 64 q-rows, 256 threads = 8 warps. Warp w: rows (w&3)*16..+16,
// kv-col half = w>>2 (32 cols). S per warp: sc[4][4]. P STAYS IN REGISTERS
// (accumulator->A-fragment trick); each warp does PV for its 32 kv rows x
// FULL HD into o[16][4]. Halves summed once at the end via smem.
// Single-stage KV (cross-CTA overlap at occ=2 replaces double buffering).
// Smem: Q 34816 + KV 69632 + stats 1024 = 105472 <= 113664 (2 CTAs/SM).
// ---------------------------------------------------------------------------
#define APITCH 272
#define ATK   (64 * APITCH)            // 17408
#define SKV   (4 * ATK)                // 69632: Kh Kl Vh Vl
#define OFF_KV (2 * ATK)               // 34816
#define OFF_MX (OFF_KV + SKV)          // 104448
#define OFF_SM (OFF_MX + 2 * 64 * 4)   // 104960
#define ATTN_SMEM (OFF_SM + 2 * 64 * 4)  // 105472
#define ORP 132                        // fp32 O-reduction pitch (pad vs banks)

__global__ __launch_bounds__(256, 2)
void attn_mma(const __nv_bfloat16* __restrict__ Qh, const __nv_bfloat16* __restrict__ Ql,
              const __nv_bfloat16* __restrict__ Kh, const __nv_bfloat16* __restrict__ Kl,
              const __nv_bfloat16* __restrict__ Vh, const __nv_bfloat16* __restrict__ Vl,
              __nv_bfloat16* __restrict__ Oh, __nv_bfloat16* __restrict__ Ol) {
    extern __shared__ char smem[];
    const uint32_t sb = smem_u32(smem);
    const int tid = threadIdx.x;
    const int wid = tid >> 5, lid = tid & 31;
    const int g = lid >> 2, t4 = lid & 3;
    const int half = wid >> 2, rw = wid & 3;
    const int qb = gridDim.x - 1 - blockIdx.x;   // big tiles first
    const int h = blockIdx.y, b = blockIdx.z;
    const int kvh = h >> 2;
    const int q0 = qb * 64;

    const uint32_t sQh = sb;
    const uint32_t kvb = sb + OFF_KV;

    // Q tile (64 rows), hi+lo
#pragma unroll
    for (int t = 0; t < 4; t++) {
        int id = t * 256 + tid;
        int row = id >> 4, seg = id & 15;
        uint32_t so = row * APITCH + seg * 16;
        size_t gq = (size_t)(b * SS + q0 + row) * QD + h * HD + seg * 8;
        cpasync16(sQh + so, Qh + gq);
        cpasync16(sQh + ATK + so, Ql + gq);
    }
    CP_COMMIT();

#define LOAD_KV(kt)                                                           \
    do {                                                                      \
        _Pragma("unroll")                                                     \
        for (int t = 0; t < 4; t++) {                                         \
            int id = t * 256 + tid;                                           \
            int row = id >> 4, seg = id & 15;                                 \
            uint32_t so = kvb + row * APITCH + seg * 16;                      \
            size_t gk = (size_t)(b * SS + (kt) * 64 + row) * KVD +            \
                        kvh * HD + seg * 8;                                   \
            cpasync16(so,           Kh + gk);                                 \
            cpasync16(so + ATK,     Kl + gk);                                 \
            cpasync16(so + 2 * ATK, Vh + gk);                                 \
            cpasync16(so + 3 * ATK, Vl + gk);                                 \
        }                                                                     \
        CP_COMMIT();                                                          \
    } while (0)

    float o[16][4];
#pragma unroll
    for (int n = 0; n < 16; n++)
#pragma unroll
        for (int q = 0; q < 4; q++) o[n][q] = 0.f;
    float m[2] = {-1e30f, -1e30f}, l[2] = {0.f, 0.f};

    const int rowA = lid & 15, khA = (lid >> 4) << 3;
    const int nB = ((lid >> 4) << 3) + (lid & 7);
    const int khB = ((lid >> 3) & 1) << 3;
    const int kV = (((lid >> 3) & 1) << 3) + (lid & 7);
    const int nVo = (lid >> 4) << 3;

    const float scale = 0.08838834764831845f;
    const int nkt = qb + 1;

    for (int kt = 0; kt < nkt; kt++) {
        LOAD_KV(kt);
        CP_WAIT0();
        __syncthreads();

        const uint32_t sKh = kvb;
        const uint32_t sVh = kvb + 2 * ATK;
        const int k0t = kt * 64;

        // ---- S (this warp: 32 kv cols at half*32) ----
        float sc[4][4];
#pragma unroll
        for (int j = 0; j < 4; j++)
#pragma unroll
            for (int q = 0; q < 4; q++) sc[j][q] = 0.f;

#pragma unroll
        for (int kk = 0; kk < 8; kk++) {
            uint32_t qhf[4], qlf[4];
            uint32_t qa = sQh + (rw * 16 + rowA) * APITCH + (kk * 16 + khA) * 2;
            LDSM4(qhf[0], qhf[1], qhf[2], qhf[3], qa);
            LDSM4(qlf[0], qlf[1], qlf[2], qlf[3], qa + ATK);
#pragma unroll
            for (int jp = 0; jp < 2; jp++) {
                uint32_t kh0[2], kh1[2], kl0[2], kl1[2];
                uint32_t ka = sKh + (half * 32 + jp * 16 + nB) * APITCH +
                              (kk * 16 + khB) * 2;
                LDSM4(kh0[0], kh0[1], kh1[0], kh1[1], ka);
                LDSM4(kl0[0], kl0[1], kl1[0], kl1[1], ka + ATK);
                MMA_BF16(sc[2 * jp],     qhf, kh0);
                MMA_BF16(sc[2 * jp + 1], qhf, kh1);
                MMA_BF16(sc[2 * jp],     qhf, kl0);
                MMA_BF16(sc[2 * jp + 1], qhf, kl1);
                MMA_BF16(sc[2 * jp],     qlf, kh0);
                MMA_BF16(sc[2 * jp + 1], qlf, kh1);
            }
        }

        // scale + causal mask (diagonal tile only)
#pragma unroll
        for (int j = 0; j < 4; j++)
#pragma unroll
            for (int q = 0; q < 4; q++) sc[j][q] *= scale;
        if (kt == qb) {
            int r0 = q0 + rw * 16 + g, r1 = r0 + 8;
#pragma unroll
            for (int j = 0; j < 4; j++) {
                int c0 = k0t + half * 32 + j * 8 + 2 * t4, c1 = c0 + 1;
                if (c0 > r0) sc[j][0] = -1e30f;
                if (c1 > r0) sc[j][1] = -1e30f;
                if (c0 > r1) sc[j][2] = -1e30f;
                if (c1 > r1) sc[j][3] = -1e30f;
            }
        }

        // ---- partial row max -> smem ----
        float pm[2];
#pragma unroll
        for (int r = 0; r < 2; r++) {
            float mx = -1e30f;
#pragma unroll
            for (int j = 0; j < 4; j++)
                mx = fmaxf(mx, fmaxf(sc[j][2 * r], sc[j][2 * r + 1]));
            mx = fmaxf(mx, __shfl_xor_sync(0xffffffffu, mx, 1));
            mx = fmaxf(mx, __shfl_xor_sync(0xffffffffu, mx, 2));
            pm[r] = mx;
            if (t4 == 0)
                *(float*)(smem + OFF_MX + (half * 64 + rw * 16 + g + 8 * r) * 4) = mx;
        }
        __syncthreads();   // partial maxima visible

        // ---- combine max; P = exp; partial sums ----
        float corr[2];
#pragma unroll
        for (int r = 0; r < 2; r++) {
            int row = rw * 16 + g + 8 * r;
            float po = *(float*)(smem + OFF_MX + ((1 - half) * 64 + row) * 4);
            float mn = fmaxf(m[r], fmaxf(pm[r], po));
            corr[r] = __expf(m[r] - mn);
            m[r] = mn;
            float rs = 0.f;
#pragma unroll
            for (int j = 0; j < 4; j++) {
                float p0 = __expf(sc[j][2 * r] - mn);
                float p1 = __expf(sc[j][2 * r + 1] - mn);
                sc[j][2 * r] = p0;
                sc[j][2 * r + 1] = p1;
                rs += p0 + p1;
            }
            rs += __shfl_xor_sync(0xffffffffu, rs, 1);
            rs += __shfl_xor_sync(0xffffffffu, rs, 2);
            if (t4 == 0)
                *(float*)(smem + OFF_SM + (half * 64 + row) * 4) = rs;
            // rescale O
#pragma unroll
            for (int n = 0; n < 16; n++) {
                o[n][2 * r] *= corr[r];
                o[n][2 * r + 1] *= corr[r];
            }
        }
        __syncthreads();   // sums visible

#pragma unroll
        for (int r = 0; r < 2; r++) {
            int row = rw * 16 + g + 8 * r;
            float ls = *(float*)(smem + OFF_SM + row * 4) +
                       *(float*)(smem + OFF_SM + (64 + row) * 4);
            l[r] = l[r] * corr[r] + ls;
        }

        // ---- O += P V (this warp's 32 kv rows, FULL HD; P in registers) ----
#pragma unroll
        for (int kc = 0; kc < 2; kc++) {
            uint32_t ah[4], al[4];
            split2(sc[2 * kc][0],     sc[2 * kc][1],     ah[0], al[0]);
            split2(sc[2 * kc][2],     sc[2 * kc][3],     ah[1], al[1]);
            split2(sc[2 * kc + 1][0], sc[2 * kc + 1][1], ah[2], al[2]);
            split2(sc[2 * kc + 1][2], sc[2 * kc + 1][3], ah[3], al[3]);
#pragma unroll
            for (int np = 0; np < 8; np++) {
                uint32_t vh0[2], vh1[2], vl0[2], vl1[2];
                uint32_t va = sVh + (half * 32 + kc * 16 + kV) * APITCH +
                              (np * 16 + nVo) * 2;
                LDSM4T(vh0[0], vh0[1], vh1[0], vh1[1], va);
                LDSM4T(vl0[0], vl0[1], vl1[0], vl1[1], va + ATK);
                MMA_BF16(o[2 * np],     ah, vh0);
                MMA_BF16(o[2 * np + 1], ah, vh1);
                MMA_BF16(o[2 * np],     ah, vl0);
                MMA_BF16(o[2 * np + 1], ah, vl1);
                MMA_BF16(o[2 * np],     al, vh0);
                MMA_BF16(o[2 * np + 1], al, vh1);
            }
        }
        __syncthreads();   // protect KV buffer before next overwrite
    }
#undef LOAD_KV

    // ---- combine halves via smem (reuse KV area), normalize, store ----
    float* ored = (float*)(smem + OFF_KV);
    if (half == 0) {
#pragma unroll
        for (int n = 0; n < 16; n++) {
            int col = n * 8 + 2 * t4;
            int r0 = rw * 16 + g;
            *(float2*)&ored[r0 * ORP + col]       = make_float2(o[n][0], o[n][1]);
            *(float2*)&ored[(r0 + 8) * ORP + col] = make_float2(o[n][2], o[n][3]);
        }
    }
    __syncthreads();
    if (half == 1) {
        float inv0 = 1.f / l[0], inv1 = 1.f / l[1];
        int r0 = rw * 16 + g;
        size_t r0g = (size_t)(b * SS + q0 + r0) * QD + h * HD;
        size_t r1g = r0g + 8 * QD;
#pragma unroll
        for (int n = 0; n < 16; n++) {
            int col = n * 8 + 2 * t4;
            float2 p0 = *(float2*)&ored[r0 * ORP + col];
            float2 p1 = *(float2*)&ored[(r0 + 8) * ORP + col];
            uint32_t hh, ll;
            split2((o[n][0] + p0.x) * inv0, (o[n][1] + p0.y) * inv0, hh, ll);
            *(uint32_t*)&Oh[r0g + col] = hh;
            *(uint32_t*)&Ol[r0g + col] = ll;
            split2((o[n][2] + p1.x) * inv1, (o[n][3] + p1.y) * inv1, hh, ll);
            *(uint32_t*)&Oh[r1g + col] = hh;
            *(uint32_t*)&Ol[r1g + col] = ll;
        }
    }
}

// ---------------------------------------------------------------------------
extern "C" void kernel_launch(void* const* d_in, const int* in_sizes, int n_in,
                              void* d_out, int out_size) {
    const float* hs  = (const float*)d_in[0];
    const float* Wq  = (const float*)d_in[2];
    const float* Wk  = (const float*)d_in[3];
    const float* Wv  = (const float*)d_in[4];
    const float* Wo  = (const float*)d_in[5];
    float*       out = (float*)d_out;

    float *qb, *kb, *vb;
    cudaGetSymbolAddress((void**)&qb, g_q);
    cudaGetSymbolAddress((void**)&kb, g_k);
    cudaGetSymbolAddress((void**)&vb, g_v);

    __nv_bfloat16 *hsh, *hsl, *wqh, *wql, *wkh, *wkl, *wvh, *wvl, *woh, *wol, *ath, *atl;
    __nv_bfloat16 *qrh, *qrl, *krh, *krl, *vrh, *vrl;
    cudaGetSymbolAddress((void**)&hsh, g_hs_h);
    cudaGetSymbolAddress((void**)&hsl, g_hs_l);
    cudaGetSymbolAddress((void**)&wqh, g_wqT_h);
    cudaGetSymbolAddress((void**)&wql, g_wqT_l);
    cudaGetSymbolAddress((void**)&wkh, g_wkT_h);
    cudaGetSymbolAddress((void**)&wkl, g_wkT_l);
    cudaGetSymbolAddress((void**)&wvh, g_wvT_h);
    cudaGetSymbolAddress((void**)&wvl, g_wvT_l);
    cudaGetSymbolAddress((void**)&woh, g_woT_h);
    cudaGetSymbolAddress((void**)&wol, g_woT_l);
    cudaGetSymbolAddress((void**)&ath, g_att_h);
    cudaGetSymbolAddress((void**)&atl, g_att_l);
    cudaGetSymbolAddress((void**)&qrh, g_qr_h);
    cudaGetSymbolAddress((void**)&qrl, g_qr_l);
    cudaGetSymbolAddress((void**)&krh, g_kr_h);
    cudaGetSymbolAddress((void**)&krl, g_kr_l);
    cudaGetSymbolAddress((void**)&vrh, g_vr_h);
    cudaGetSymbolAddress((void**)&vrl, g_vr_l);

    cudaFuncSetAttribute(mma_gemm, cudaFuncAttributeMaxDynamicSharedMemorySize, GEMM_SMEM);
    cudaFuncSetAttribute(mma_gemm_qkv, cudaFuncAttributeMaxDynamicSharedMemorySize, GEMM_SMEM);
    cudaFuncSetAttribute(attn_mma, cudaFuncAttributeMaxDynamicSharedMemorySize, ATTN_SMEM);

    // 0: fused prep (hs split + 4 weight transposes)
    prep_all<<<dim3(128, 128, 5), dim3(32, 8)>>>(hs, Wq, Wk, Wv, Wo,
                                                 hsh, hsl, wqh, wql, wkh, wkl,
                                                 wvh, wvl, woh, wol);

    // 1: fused QKV projection
    mma_gemm_qkv<<<dim3(48, MR / 128), 256, GEMM_SMEM>>>(hsh, hsl,
                                                          wqh, wql, wkh, wkl,
                                                          wvh, wvl, qb, kb, vb);

    // 2: RoPE(Q,K) + split(V), fused
    rope_all<<<(NQR + NKR + NV4 + 255) / 256, 256>>>(qb, kb, vb, qrh, qrl,
                                                     krh, krl, vrh, vrl);

    // 3: causal GQA attention (2 CTAs/SM)
    attn_mma<<<dim3(SS / 64, NH, BB), 256, ATTN_SMEM>>>(qrh, qrl, krh, krl,
                                                         vrh, vrl, ath, atl);

    // 4: O projection
    mma_gemm<<<dim3(HH / 128, MR / 128), 256, GEMM_SMEM>>>(ath, atl, woh, wol, out, HH, QD);
}

// round 15
// speedup vs baseline: 1.7543x; 1.0032x over previous
#include <cuda_runtime.h>
#include <cuda_bf16.h>
#include <math.h>
#include <stdint.h>

#define BB  2
#define SS  2048
#define HH  4096
#define NH  32
#define NKV 8
#define HD  128
#define MR  (BB * SS)      // 4096 rows
#define QD  (NH * HD)      // 4096
#define KVD (NKV * HD)     // 1024

// ---------------- scratch (device globals; no runtime allocation) ----------
__device__ float g_q[MR * QD];
__device__ float g_k[MR * KVD];
__device__ float g_v[MR * KVD];

__device__ __nv_bfloat16 g_hs_h[MR * HH];
__device__ __nv_bfloat16 g_hs_l[MR * HH];
__device__ __nv_bfloat16 g_wqT_h[QD * HH];
__device__ __nv_bfloat16 g_wqT_l[QD * HH];
__device__ __nv_bfloat16 g_wkT_h[KVD * HH];
__device__ __nv_bfloat16 g_wkT_l[KVD * HH];
__device__ __nv_bfloat16 g_wvT_h[KVD * HH];
__device__ __nv_bfloat16 g_wvT_l[KVD * HH];
__device__ __nv_bfloat16 g_woT_h[HH * QD];
__device__ __nv_bfloat16 g_woT_l[HH * QD];
__device__ __nv_bfloat16 g_att_h[MR * QD];
__device__ __nv_bfloat16 g_att_l[MR * QD];

// attention operands (post-RoPE, hi/lo split)
__device__ __nv_bfloat16 g_qr_h[MR * QD];
__device__ __nv_bfloat16 g_qr_l[MR * QD];
__device__ __nv_bfloat16 g_kr_h[MR * KVD];
__device__ __nv_bfloat16 g_kr_l[MR * KVD];
__device__ __nv_bfloat16 g_vr_h[MR * KVD];
__device__ __nv_bfloat16 g_vr_l[MR * KVD];

// ---------------- PTX helpers ----------------------------------------------
__device__ __forceinline__ uint32_t smem_u32(const void* p) {
    uint32_t a;
    asm("{ .reg .u64 t; cvta.to.shared.u64 t, %1; cvt.u32.u64 %0, t; }"
        : "=r"(a) : "l"(p));
    return a;
}
__device__ __forceinline__ void cpasync16(uint32_t dst, const void* src) {
    asm volatile("cp.async.cg.shared.global [%0], [%1], 16;"
                 :: "r"(dst), "l"(src));
}
#define CP_COMMIT() asm volatile("cp.async.commit_group;" ::: "memory")
#define CP_WAIT0()  asm volatile("cp.async.wait_group 0;" ::: "memory")

#define LDSM4(r0, r1, r2, r3, addr) \
    asm volatile("ldmatrix.sync.aligned.m8n8.x4.shared.b16 {%0,%1,%2,%3}, [%4];" \
                 : "=r"(r0), "=r"(r1), "=r"(r2), "=r"(r3) : "r"(addr))

#define LDSM4T(r0, r1, r2, r3, addr) \
    asm volatile("ldmatrix.sync.aligned.m8n8.x4.trans.shared.b16 {%0,%1,%2,%3}, [%4];" \
                 : "=r"(r0), "=r"(r1), "=r"(r2), "=r"(r3) : "r"(addr))

#define MMA_BF16(c, a, b) \
    asm volatile("mma.sync.aligned.m16n8k16.row.col.f32.bf16.bf16.f32 " \
                 "{%0,%1,%2,%3}, {%4,%5,%6,%7}, {%8,%9}, {%0,%1,%2,%3};" \
                 : "+f"((c)[0]), "+f"((c)[1]), "+f"((c)[2]), "+f"((c)[3]) \
                 : "r"((a)[0]), "r"((a)[1]), "r"((a)[2]), "r"((a)[3]), \
                   "r"((b)[0]), "r"((b)[1]))

__device__ __forceinline__ void split2(float x, float y, uint32_t& h, uint32_t& l) {
    __nv_bfloat162 hb = __floats2bfloat162_rn(x, y);
    float2 hf = __bfloat1622float2(hb);
    __nv_bfloat162 lb = __floats2bfloat162_rn(x - hf.x, y - hf.y);
    h = *reinterpret_cast<uint32_t*>(&hb);
    l = *reinterpret_cast<uint32_t*>(&lb);
}

// ---------------------------------------------------------------------------
// prep_all: z=0 hs hi/lo split; z=1..4 weight transpose+split
// ---------------------------------------------------------------------------
__global__ void prep_all(const float* __restrict__ hs,
                         const float* __restrict__ Wq, const float* __restrict__ Wk,
                         const float* __restrict__ Wv, const float* __restrict__ Wo,
                         __nv_bfloat16* __restrict__ hsh, __nv_bfloat16* __restrict__ hsl,
                         __nv_bfloat16* __restrict__ wqh, __nv_bfloat16* __restrict__ wql,
                         __nv_bfloat16* __restrict__ wkh, __nv_bfloat16* __restrict__ wkl,
                         __nv_bfloat16* __restrict__ wvh, __nv_bfloat16* __restrict__ wvl,
                         __nv_bfloat16* __restrict__ woh, __nv_bfloat16* __restrict__ wol) {
    int z = blockIdx.z;
    int tx = threadIdx.x, ty = threadIdx.y;
    if (z == 0) {
        int i = (blockIdx.y * 128 + blockIdx.x) * 256 + ty * 32 + tx;
        float4 s = ((const float4*)hs)[i];
        __nv_bfloat162 h01 = __floats2bfloat162_rn(s.x, s.y);
        __nv_bfloat162 h23 = __floats2bfloat162_rn(s.z, s.w);
        float2 f01 = __bfloat1622float2(h01);
        float2 f23 = __bfloat1622float2(h23);
        __nv_bfloat162 l01 = __floats2bfloat162_rn(s.x - f01.x, s.y - f01.y);
        __nv_bfloat162 l23 = __floats2bfloat162_rn(s.z - f23.x, s.w - f23.y);
        ((__nv_bfloat162*)hsh)[2 * i]     = h01;
        ((__nv_bfloat162*)hsh)[2 * i + 1] = h23;
        ((__nv_bfloat162*)hsl)[2 * i]     = l01;
        ((__nv_bfloat162*)hsl)[2 * i + 1] = l23;
        return;
    }
    const float* W;
    __nv_bfloat16 *hiT, *loT;
    int K, N;
    if (z == 1)      { W = Wq; hiT = wqh; loT = wql; K = HH; N = QD; }
    else if (z == 2) { W = Wk; hiT = wkh; loT = wkl; K = HH; N = KVD; }
    else if (z == 3) { W = Wv; hiT = wvh; loT = wvl; K = HH; N = KVD; }
    else             { W = Wo; hiT = woh; loT = wol; K = QD; N = HH; }
    if (blockIdx.x * 32 >= N || blockIdx.y * 32 >= K) return;

    __shared__ float t[32][33];
    int n0 = blockIdx.x * 32, k0 = blockIdx.y * 32;
#pragma unroll
    for (int i = 0; i < 32; i += 8)
        t[ty + i][tx] = W[(size_t)(k0 + ty + i) * N + n0 + tx];
    __syncthreads();
#pragma unroll
    for (int i = 0; i < 32; i += 8) {
        float v = t[tx][ty + i];
        __nv_bfloat16 h = __float2bfloat16_rn(v);
        __nv_bfloat16 l = __float2bfloat16_rn(v - __bfloat162float(h));
        size_t o = (size_t)(n0 + ty + i) * K + k0 + tx;
        hiT[o] = h;
        loT[o] = l;
    }
}

// ---------------------------------------------------------------------------
// mma.sync bf16x3 GEMM body (unchanged)
// ---------------------------------------------------------------------------
#define TILE_B   10240
#define STAGE_B  (4 * TILE_B)
#define GEMM_SMEM (2 * STAGE_B)

__device__ __forceinline__ void gemm_body(
    const __nv_bfloat16* __restrict__ Ahi, const __nv_bfloat16* __restrict__ Alo,
    const __nv_bfloat16* __restrict__ Bhi, const __nv_bfloat16* __restrict__ Blo,
    float* __restrict__ C, int Nd, int Kd, int bm, int bn, char* smem) {
    const uint32_t sb = smem_u32(smem);
    const int tid = threadIdx.x;
    const int wid = tid >> 5, lid = tid & 31;
    const int wm = wid >> 2, wn = wid & 3;

    float c[4][4][4];
#pragma unroll
    for (int i = 0; i < 4; i++)
#pragma unroll
        for (int j = 0; j < 4; j++)
#pragma unroll
            for (int q = 0; q < 4; q++) c[i][j][q] = 0.f;

    const int rowA = lid & 15;
    const int khA  = (lid >> 4) << 3;
    const int nB   = ((lid >> 4) << 3) + (lid & 7);
    const int khB  = ((lid >> 3) & 1) << 3;

#define LOAD_STAGE(s, k0)                                                     \
    do {                                                                      \
        _Pragma("unroll")                                                     \
        for (int li = 0; li < 2; li++) {                                      \
            int id  = li * 256 + tid;                                         \
            int row = id >> 2, seg = id & 3;                                  \
            uint32_t so = sb + (s) * STAGE_B + row * 80 + seg * 16;           \
            size_t ga = (size_t)(bm + row) * Kd + (k0) + seg * 8;             \
            size_t gb = (size_t)(bn + row) * Kd + (k0) + seg * 8;             \
            cpasync16(so,              Ahi + ga);                             \
            cpasync16(so + TILE_B,     Alo + ga);                             \
            cpasync16(so + 2 * TILE_B, Bhi + gb);                             \
            cpasync16(so + 3 * TILE_B, Blo + gb);                             \
        }                                                                     \
        CP_COMMIT();                                                          \
    } while (0)

    const int nk = Kd >> 5;
    LOAD_STAGE(0, 0);

    for (int kt = 0; kt < nk; kt++) {
        CP_WAIT0();
        __syncthreads();
        if (kt + 1 < nk) LOAD_STAGE((kt + 1) & 1, (kt + 1) << 5);

        const uint32_t abase = sb + (kt & 1) * STAGE_B;
        const uint32_t bbase = abase + 2 * TILE_B;
#pragma unroll
        for (int kk = 0; kk < 32; kk += 16) {
            uint32_t bh[4][2], bl[4][2];
#pragma unroll
            for (int j2 = 0; j2 < 2; j2++) {
                uint32_t ba = bbase + (wn * 32 + j2 * 16 + nB) * 80 +
                              (kk + khB) * 2;
                LDSM4(bh[j2 * 2][0], bh[j2 * 2][1],
                      bh[j2 * 2 + 1][0], bh[j2 * 2 + 1][1], ba);
                LDSM4(bl[j2 * 2][0], bl[j2 * 2][1],
                      bl[j2 * 2 + 1][0], bl[j2 * 2 + 1][1], ba + TILE_B);
            }
            uint32_t ah[4][4], al[4][4];
#pragma unroll
            for (int i = 0; i < 4; i++) {
                uint32_t aa = abase + (wm * 64 + i * 16 + rowA) * 80 +
                              (kk + khA) * 2;
                LDSM4(ah[i][0], ah[i][1], ah[i][2], ah[i][3], aa);
                LDSM4(al[i][0], al[i][1], al[i][2], al[i][3], aa + TILE_B);
            }
#pragma unroll
            for (int i = 0; i < 4; i++)
#pragma unroll
                for (int j = 0; j < 4; j++) MMA_BF16(c[i][j], ah[i], bh[j]);
#pragma unroll
            for (int i = 0; i < 4; i++)
#pragma unroll
                for (int j = 0; j < 4; j++) MMA_BF16(c[i][j], ah[i], bl[j]);
#pragma unroll
            for (int i = 0; i < 4; i++)
#pragma unroll
                for (int j = 0; j < 4; j++) MMA_BF16(c[i][j], al[i], bh[j]);
        }
        __syncthreads();
    }
#undef LOAD_STAGE

    const int g = lid >> 2, t4 = lid & 3;
#pragma unroll
    for (int i = 0; i < 4; i++) {
        int r0 = bm + wm * 64 + i * 16 + g;
#pragma unroll
        for (int j = 0; j < 4; j++) {
            int col = bn + wn * 32 + j * 8 + t4 * 2;
            *(float2*)&C[(size_t)r0 * Nd + col] =
                make_float2(c[i][j][0], c[i][j][1]);
            *(float2*)&C[(size_t)(r0 + 8) * Nd + col] =
                make_float2(c[i][j][2], c[i][j][3]);
        }
    }
}

__global__ __launch_bounds__(256, 2)
void mma_gemm(const __nv_bfloat16* __restrict__ Ahi,
              const __nv_bfloat16* __restrict__ Alo,
              const __nv_bfloat16* __restrict__ Bhi,
              const __nv_bfloat16* __restrict__ Blo,
              float* __restrict__ C, int Nd, int Kd) {
    extern __shared__ char smem[];
    gemm_body(Ahi, Alo, Bhi, Blo, C, Nd, Kd,
              blockIdx.y * 128, blockIdx.x * 128, smem);
}

__global__ __launch_bounds__(256, 2)
void mma_gemm_qkv(const __nv_bfloat16* __restrict__ Ahi,
                  const __nv_bfloat16* __restrict__ Alo,
                  const __nv_bfloat16* __restrict__ wqh, const __nv_bfloat16* __restrict__ wql,
                  const __nv_bfloat16* __restrict__ wkh, const __nv_bfloat16* __restrict__ wkl,
                  const __nv_bfloat16* __restrict__ wvh, const __nv_bfloat16* __restrict__ wvl,
                  float* __restrict__ Cq, float* __restrict__ Ck, float* __restrict__ Cv) {
    extern __shared__ char smem[];
    int bx = blockIdx.x;
    const __nv_bfloat16 *Bh, *Bl;
    float* C;
    int Nd, bn;
    if (bx < 32)      { Bh = wqh; Bl = wql; C = Cq; Nd = QD;  bn = bx * 128; }
    else if (bx < 40) { Bh = wkh; Bl = wkl; C = Ck; Nd = KVD; bn = (bx - 32) * 128; }
    else              { Bh = wvh; Bl = wvl; C = Cv; Nd = KVD; bn = (bx - 40) * 128; }
    gemm_body(Ahi, Alo, Bh, Bl, C, Nd, HH, blockIdx.y * 128, bn, smem);
}

// ---------------------------------------------------------------------------
// rope_all: RoPE+split for Q and K, plain split for V — one launch.
// ---------------------------------------------------------------------------
#define NQR (MR * NH * 64)
#define NKR (MR * NKV * 64)
#define NV4 (MR * KVD / 4)

__global__ void rope_all(const float* __restrict__ qs, const float* __restrict__ ks,
                         const float* __restrict__ vs,
                         __nv_bfloat16* __restrict__ qh, __nv_bfloat16* __restrict__ ql,
                         __nv_bfloat16* __restrict__ kh, __nv_bfloat16* __restrict__ kl,
                         __nv_bfloat16* __restrict__ vh, __nv_bfloat16* __restrict__ vl) {
    int idx = blockIdx.x * blockDim.x + threadIdx.x;
    if (idx < NQR + NKR) {
        const float* buf;
        __nv_bfloat16 *oh, *ol;
        int nheads;
        if (idx < NQR) { buf = qs; oh = qh; ol = ql; nheads = NH; }
        else { idx -= NQR; buf = ks; oh = kh; ol = kl; nheads = NKV; }
        int i    = idx & 63;
        int head = (idx >> 6) % nheads;
        int row  = idx / (nheads << 6);
        float p    = (float)(row % SS);
        float invf = expf(-(float)i * 0.14391156831212787f);
        float ang  = p * invf;
        float c, s;
        sincosf(ang, &s, &c);
        size_t base = (size_t)row * (nheads * HD) + head * HD + i;
        float x0 = buf[base];
        float x1 = buf[base + 64];
        float y0 = x0 * c - x1 * s;
        float y1 = x1 * c + x0 * s;
        __nv_bfloat16 h0 = __float2bfloat16_rn(y0);
        __nv_bfloat16 h1 = __float2bfloat16_rn(y1);
        oh[base]      = h0;
        oh[base + 64] = h1;
        ol[base]      = __float2bfloat16_rn(y0 - __bfloat162float(h0));
        ol[base + 64] = __float2bfloat16_rn(y1 - __bfloat162float(h1));
        return;
    }
    idx -= NQR + NKR;
    if (idx >= NV4) return;
    float4 s = ((const float4*)vs)[idx];
    __nv_bfloat162 h01 = __floats2bfloat162_rn(s.x, s.y);
    __nv_bfloat162 h23 = __floats2bfloat162_rn(s.z, s.w);
    float2 f01 = __bfloat1622float2(h01);
    float2 f23 = __bfloat1622float2(h23);
    ((__nv_bfloat162*)vh)[2 * idx]     = h01;
    ((__nv_bfloat162*)vh)[2 * idx + 1] = h23;
    ((__nv_bfloat162*)vl)[2 * idx]     = __floats2bfloat162_rn(s.x - f01.x, s.y - f01.y);
    ((__nv_bfloat162*)vl)[2 * idx + 1] = __floats2bfloat162_rn(s.z - f23.x, s.w - f23.y);
}

// ---------------------------------------------------------------------------
// Tensor-core causal flash attention, bf16x3, 2 CTAs/SM, WARP-LOCAL softmax.
// Each kv-col half keeps its own running (m, l); no per-tile cross-half
// exchange (no smem, no barriers in softmax). Halves merged exactly once at
// the end: O = (e^{m0-M} O0 + e^{m1-M} O1) / (e^{m0-M} l0 + e^{m1-M} l1).
// 2 syncs per kv tile (load-visible, KV-protect).
// Smem: Q 34816 + KV 69632 + final stats 512 = 104960 (2 CTAs/SM).
// ---------------------------------------------------------------------------
#define APITCH 272
#define ATK   (64 * APITCH)            // 17408
#define SKV   (4 * ATK)                // 69632: Kh Kl Vh Vl
#define OFF_KV (2 * ATK)               // 34816
#define OFF_ST (OFF_KV + SKV)          // 104448 (final m/l exchange, 512 B)
#define ATTN_SMEM (OFF_ST + 64 * 8)    // 104960
#define ORP 132                        // fp32 O-reduction pitch

__global__ __launch_bounds__(256, 2)
void attn_mma(const __nv_bfloat16* __restrict__ Qh, const __nv_bfloat16* __restrict__ Ql,
              const __nv_bfloat16* __restrict__ Kh, const __nv_bfloat16* __restrict__ Kl,
              const __nv_bfloat16* __restrict__ Vh, const __nv_bfloat16* __restrict__ Vl,
              __nv_bfloat16* __restrict__ Oh, __nv_bfloat16* __restrict__ Ol) {
    extern __shared__ char smem[];
    const uint32_t sb = smem_u32(smem);
    const int tid = threadIdx.x;
    const int wid = tid >> 5, lid = tid & 31;
    const int g = lid >> 2, t4 = lid & 3;
    const int half = wid >> 2, rw = wid & 3;
    const int qb = gridDim.x - 1 - blockIdx.x;   // big tiles first
    const int h = blockIdx.y, b = blockIdx.z;
    const int kvh = h >> 2;
    const int q0 = qb * 64;

    const uint32_t sQh = sb;
    const uint32_t kvb = sb + OFF_KV;

    // Q tile (64 rows), hi+lo
#pragma unroll
    for (int t = 0; t < 4; t++) {
        int id = t * 256 + tid;
        int row = id >> 4, seg = id & 15;
        uint32_t so = row * APITCH + seg * 16;
        size_t gq = (size_t)(b * SS + q0 + row) * QD + h * HD + seg * 8;
        cpasync16(sQh + so, Qh + gq);
        cpasync16(sQh + ATK + so, Ql + gq);
    }
    CP_COMMIT();

#define LOAD_KV(kt)                                                           \
    do {                                                                      \
        _Pragma("unroll")                                                     \
        for (int t = 0; t < 4; t++) {                                         \
            int id = t * 256 + tid;                                           \
            int row = id >> 4, seg = id & 15;                                 \
            uint32_t so = kvb + row * APITCH + seg * 16;                      \
            size_t gk = (size_t)(b * SS + (kt) * 64 + row) * KVD +            \
                        kvh * HD + seg * 8;                                   \
            cpasync16(so,           Kh + gk);                                 \
            cpasync16(so + ATK,     Kl + gk);                                 \
            cpasync16(so + 2 * ATK, Vh + gk);                                 \
            cpasync16(so + 3 * ATK, Vl + gk);                                 \
        }                                                                     \
        CP_COMMIT();                                                          \
    } while (0)

    float o[16][4];
#pragma unroll
    for (int n = 0; n < 16; n++)
#pragma unroll
        for (int q = 0; q < 4; q++) o[n][q] = 0.f;
    float m[2] = {-1e30f, -1e30f}, l[2] = {0.f, 0.f};

    const int rowA = lid & 15, khA = (lid >> 4) << 3;
    const int nB = ((lid >> 4) << 3) + (lid & 7);
    const int khB = ((lid >> 3) & 1) << 3;
    const int kV = (((lid >> 3) & 1) << 3) + (lid & 7);
    const int nVo = (lid >> 4) << 3;

    const float scale = 0.08838834764831845f;
    const int nkt = qb + 1;

    for (int kt = 0; kt < nkt; kt++) {
        LOAD_KV(kt);
        CP_WAIT0();
        __syncthreads();

        const uint32_t sKh = kvb;
        const uint32_t sVh = kvb + 2 * ATK;
        const int k0t = kt * 64;

        // ---- S (this warp: 32 kv cols at half*32) ----
        float sc[4][4];
#pragma unroll
        for (int j = 0; j < 4; j++)
#pragma unroll
            for (int q = 0; q < 4; q++) sc[j][q] = 0.f;

#pragma unroll
        for (int kk = 0; kk < 8; kk++) {
            uint32_t qhf[4], qlf[4];
            uint32_t qa = sQh + (rw * 16 + rowA) * APITCH + (kk * 16 + khA) * 2;
            LDSM4(qhf[0], qhf[1], qhf[2], qhf[3], qa);
            LDSM4(qlf[0], qlf[1], qlf[2], qlf[3], qa + ATK);
#pragma unroll
            for (int jp = 0; jp < 2; jp++) {
                uint32_t kh0[2], kh1[2], kl0[2], kl1[2];
                uint32_t ka = sKh + (half * 32 + jp * 16 + nB) * APITCH +
                              (kk * 16 + khB) * 2;
                LDSM4(kh0[0], kh0[1], kh1[0], kh1[1], ka);
                LDSM4(kl0[0], kl0[1], kl1[0], kl1[1], ka + ATK);
                MMA_BF16(sc[2 * jp],     qhf, kh0);
                MMA_BF16(sc[2 * jp + 1], qhf, kh1);
                MMA_BF16(sc[2 * jp],     qhf, kl0);
                MMA_BF16(sc[2 * jp + 1], qhf, kl1);
                MMA_BF16(sc[2 * jp],     qlf, kh0);
                MMA_BF16(sc[2 * jp + 1], qlf, kh1);
            }
        }

        // scale + causal mask (diagonal tile only)
#pragma unroll
        for (int j = 0; j < 4; j++)
#pragma unroll
            for (int q = 0; q < 4; q++) sc[j][q] *= scale;
        if (kt == qb) {
            int r0 = q0 + rw * 16 + g, r1 = r0 + 8;
#pragma unroll
            for (int j = 0; j < 4; j++) {
                int c0 = k0t + half * 32 + j * 8 + 2 * t4, c1 = c0 + 1;
                if (c0 > r0) sc[j][0] = -1e30f;
                if (c1 > r0) sc[j][1] = -1e30f;
                if (c0 > r1) sc[j][2] = -1e30f;
                if (c1 > r1) sc[j][3] = -1e30f;
            }
        }

        // ---- warp-local online softmax (no smem, no barriers) ----
#pragma unroll
        for (int r = 0; r < 2; r++) {
            float mx = -1e30f;
#pragma unroll
            for (int j = 0; j < 4; j++)
                mx = fmaxf(mx, fmaxf(sc[j][2 * r], sc[j][2 * r + 1]));
            mx = fmaxf(mx, __shfl_xor_sync(0xffffffffu, mx, 1));
            mx = fmaxf(mx, __shfl_xor_sync(0xffffffffu, mx, 2));
            float mn = fmaxf(m[r], mx);
            float safe = (mn > -1e29f) ? 1.f : 0.f;   // all-masked guard
            float corr = __expf(m[r] - mn);
            m[r] = mn;
            float rs = 0.f;
#pragma unroll
            for (int j = 0; j < 4; j++) {
                float p0 = safe * __expf(sc[j][2 * r] - mn);
                float p1 = safe * __expf(sc[j][2 * r + 1] - mn);
                sc[j][2 * r] = p0;
                sc[j][2 * r + 1] = p1;
                rs += p0 + p1;
            }
            rs += __shfl_xor_sync(0xffffffffu, rs, 1);
            rs += __shfl_xor_sync(0xffffffffu, rs, 2);
            l[r] = l[r] * corr + rs;
#pragma unroll
            for (int n = 0; n < 16; n++) {
                o[n][2 * r] *= corr;
                o[n][2 * r + 1] *= corr;
            }
        }

        // ---- O += P V (this warp's 32 kv rows, FULL HD; P in registers) ----
#pragma unroll
        for (int kc = 0; kc < 2; kc++) {
            uint32_t ah[4], al[4];
            split2(sc[2 * kc][0],     sc[2 * kc][1],     ah[0], al[0]);
            split2(sc[2 * kc][2],     sc[2 * kc][3],     ah[1], al[1]);
            split2(sc[2 * kc + 1][0], sc[2 * kc + 1][1], ah[2], al[2]);
            split2(sc[2 * kc + 1][2], sc[2 * kc + 1][3], ah[3], al[3]);
#pragma unroll
            for (int np = 0; np < 8; np++) {
                uint32_t vh0[2], vh1[2], vl0[2], vl1[2];
                uint32_t va = sVh + (half * 32 + kc * 16 + kV) * APITCH +
                              (np * 16 + nVo) * 2;
                LDSM4T(vh0[0], vh0[1], vh1[0], vh1[1], va);
                LDSM4T(vl0[0], vl0[1], vl1[0], vl1[1], va + ATK);
                MMA_BF16(o[2 * np],     ah, vh0);
                MMA_BF16(o[2 * np + 1], ah, vh1);
                MMA_BF16(o[2 * np],     ah, vl0);
                MMA_BF16(o[2 * np + 1], ah, vl1);
                MMA_BF16(o[2 * np],     al, vh0);
                MMA_BF16(o[2 * np + 1], al, vh1);
            }
        }
        __syncthreads();   // protect KV buffer before next overwrite
    }
#undef LOAD_KV

    // ---- final merge: half0 writes raw (m,l,O); half1 combines & stores ----
    float* ored = (float*)(smem + OFF_KV);
    float* st   = (float*)(smem + OFF_ST);   // [row*2]: m0, [row*2+1]: l0
    if (half == 0) {
        if (t4 == 0) {
#pragma unroll
            for (int r = 0; r < 2; r++) {
                int row = rw * 16 + g + 8 * r;
                st[row * 2]     = m[r];
                st[row * 2 + 1] = l[r];
            }
        }
#pragma unroll
        for (int n = 0; n < 16; n++) {
            int col = n * 8 + 2 * t4;
            int r0 = rw * 16 + g;
            *(float2*)&ored[r0 * ORP + col]       = make_float2(o[n][0], o[n][1]);
            *(float2*)&ored[(r0 + 8) * ORP + col] = make_float2(o[n][2], o[n][3]);
        }
    }
    __syncthreads();
    if (half == 1) {
        float s0[2], s1[2], inv[2];
#pragma unroll
        for (int r = 0; r < 2; r++) {
            int row = rw * 16 + g + 8 * r;
            float m0 = st[row * 2], l0 = st[row * 2 + 1];
            float M = fmaxf(m0, m[r]);
            s0[r] = __expf(m0 - M);
            s1[r] = __expf(m[r] - M);
            inv[r] = 1.f / (l0 * s0[r] + l[r] * s1[r]);
        }
        int r0 = rw * 16 + g;
        size_t r0g = (size_t)(b * SS + q0 + r0) * QD + h * HD;
        size_t r1g = r0g + 8 * QD;
#pragma unroll
        for (int n = 0; n < 16; n++) {
            int col = n * 8 + 2 * t4;
            float2 p0 = *(float2*)&ored[r0 * ORP + col];
            float2 p1 = *(float2*)&ored[(r0 + 8) * ORP + col];
            uint32_t hh, ll;
            split2((p0.x * s0[0] + o[n][0] * s1[0]) * inv[0],
                   (p0.y * s0[0] + o[n][1] * s1[0]) * inv[0], hh, ll);
            *(uint32_t*)&Oh[r0g + col] = hh;
            *(uint32_t*)&Ol[r0g + col] = ll;
            split2((p1.x * s0[1] + o[n][2] * s1[1]) * inv[1],
                   (p1.y * s0[1] + o[n][3] * s1[1]) * inv[1], hh, ll);
            *(uint32_t*)&Oh[r1g + col] = hh;
            *(uint32_t*)&Ol[r1g + col] = ll;
        }
    }
}

// ---------------------------------------------------------------------------
extern "C" void kernel_launch(void* const* d_in, const int* in_sizes, int n_in,
                              void* d_out, int out_size) {
    const float* hs  = (const float*)d_in[0];
    const float* Wq  = (const float*)d_in[2];
    const float* Wk  = (const float*)d_in[3];
    const float* Wv  = (const float*)d_in[4];
    const float* Wo  = (const float*)d_in[5];
    float*       out = (float*)d_out;

    float *qb, *kb, *vb;
    cudaGetSymbolAddress((void**)&qb, g_q);
    cudaGetSymbolAddress((void**)&kb, g_k);
    cudaGetSymbolAddress((void**)&vb, g_v);

    __nv_bfloat16 *hsh, *hsl, *wqh, *wql, *wkh, *wkl, *wvh, *wvl, *woh, *wol, *ath, *atl;
    __nv_bfloat16 *qrh, *qrl, *krh, *krl, *vrh, *vrl;
    cudaGetSymbolAddress((void**)&hsh, g_hs_h);
    cudaGetSymbolAddress((void**)&hsl, g_hs_l);
    cudaGetSymbolAddress((void**)&wqh, g_wqT_h);
    cudaGetSymbolAddress((void**)&wql, g_wqT_l);
    cudaGetSymbolAddress((void**)&wkh, g_wkT_h);
    cudaGetSymbolAddress((void**)&wkl, g_wkT_l);
    cudaGetSymbolAddress((void**)&wvh, g_wvT_h);
    cudaGetSymbolAddress((void**)&wvl, g_wvT_l);
    cudaGetSymbolAddress((void**)&woh, g_woT_h);
    cudaGetSymbolAddress((void**)&wol, g_woT_l);
    cudaGetSymbolAddress((void**)&ath, g_att_h);
    cudaGetSymbolAddress((void**)&atl, g_att_l);
    cudaGetSymbolAddress((void**)&qrh, g_qr_h);
    cudaGetSymbolAddress((void**)&qrl, g_qr_l);
    cudaGetSymbolAddress((void**)&krh, g_kr_h);
    cudaGetSymbolAddress((void**)&krl, g_kr_l);
    cudaGetSymbolAddress((void**)&vrh, g_vr_h);
    cudaGetSymbolAddress((void**)&vrl, g_vr_l);

    cudaFuncSetAttribute(mma_gemm, cudaFuncAttributeMaxDynamicSharedMemorySize, GEMM_SMEM);
    cudaFuncSetAttribute(mma_gemm_qkv, cudaFuncAttributeMaxDynamicSharedMemorySize, GEMM_SMEM);
    cudaFuncSetAttribute(attn_mma, cudaFuncAttributeMaxDynamicSharedMemorySize, ATTN_SMEM);

    // 0: fused prep (hs split + 4 weight transposes)
    prep_all<<<dim3(128, 128, 5), dim3(32, 8)>>>(hs, Wq, Wk, Wv, Wo,
                                                 hsh, hsl, wqh, wql, wkh, wkl,
                                                 wvh, wvl, woh, wol);

    // 1: fused QKV projection
    mma_gemm_qkv<<<dim3(48, MR / 128), 256, GEMM_SMEM>>>(hsh, hsl,
                                                          wqh, wql, wkh, wkl,
                                                          wvh, wvl, qb, kb, vb);

    // 2: RoPE(Q,K) + split(V), fused
    rope_all<<<(NQR + NKR + NV4 + 255) / 256, 256>>>(qb, kb, vb, qrh, qrl,
                                                     krh, krl, vrh, vrl);

    // 3: causal GQA attention (2 CTAs/SM, warp-local softmax)
    attn_mma<<<dim3(SS / 64, NH, BB), 256, ATTN_SMEM>>>(qrh, qrl, krh, krl,
                                                         vrh, vrl, ath, atl);

    // 4: O projection
    mma_gemm<<<dim3(HH / 128, MR / 128), 256, GEMM_SMEM>>>(ath, atl, woh, wol, out, HH, QD);
}

// round 17
// speedup vs baseline: 1.8061x; 1.0295x over previous
#include <cuda_runtime.h>
#include <cuda_bf16.h>
#include <math.h>
#include <stdint.h>

#define BB  2
#define SS  2048
#define HH  4096
#define NH  32
#define NKV 8
#define HD  128
#define MR  (BB * SS)      // 4096 rows
#define QD  (NH * HD)      // 4096
#define KVD (NKV * HD)     // 1024

// ---------------- scratch (device globals; no runtime allocation) ----------
__device__ float g_q[MR * QD];
__device__ float g_k[MR * KVD];
__device__ float g_v[MR * KVD];

__device__ __nv_bfloat16 g_hs_h[MR * HH];
__device__ __nv_bfloat16 g_hs_l[MR * HH];
__device__ __nv_bfloat16 g_wqT_h[QD * HH];
__device__ __nv_bfloat16 g_wqT_l[QD * HH];
__device__ __nv_bfloat16 g_wkT_h[KVD * HH];
__device__ __nv_bfloat16 g_wkT_l[KVD * HH];
__device__ __nv_bfloat16 g_wvT_h[KVD * HH];
__device__ __nv_bfloat16 g_wvT_l[KVD * HH];
__device__ __nv_bfloat16 g_woT_h[HH * QD];
__device__ __nv_bfloat16 g_woT_l[HH * QD];
__device__ __nv_bfloat16 g_att_h[MR * QD];
__device__ __nv_bfloat16 g_att_l[MR * QD];

// attention operands (post-RoPE, hi/lo split)
__device__ __nv_bfloat16 g_qr_h[MR * QD];
__device__ __nv_bfloat16 g_qr_l[MR * QD];
__device__ __nv_bfloat16 g_kr_h[MR * KVD];
__device__ __nv_bfloat16 g_kr_l[MR * KVD];
__device__ __nv_bfloat16 g_vr_h[MR * KVD];
__device__ __nv_bfloat16 g_vr_l[MR * KVD];

// ---------------- PTX helpers ----------------------------------------------
__device__ __forceinline__ uint32_t smem_u32(const void* p) {
    uint32_t a;
    asm("{ .reg .u64 t; cvta.to.shared.u64 t, %1; cvt.u32.u64 %0, t; }"
        : "=r"(a) : "l"(p));
    return a;
}
// L1-allocating async copy: co-resident CTAs share A row-blocks (GEMM) and
// K/V tiles (attention), so .ca lets the second CTA hit L1 instead of L2.
__device__ __forceinline__ void cpasync16(uint32_t dst, const void* src) {
    asm volatile("cp.async.ca.shared.global [%0], [%1], 16;"
                 :: "r"(dst), "l"(src));
}
#define CP_COMMIT() asm volatile("cp.async.commit_group;" ::: "memory")
#define CP_WAIT0()  asm volatile("cp.async.wait_group 0;" ::: "memory")

#define LDSM4(r0, r1, r2, r3, addr) \
    asm volatile("ldmatrix.sync.aligned.m8n8.x4.shared.b16 {%0,%1,%2,%3}, [%4];" \
                 : "=r"(r0), "=r"(r1), "=r"(r2), "=r"(r3) : "r"(addr))

#define LDSM4T(r0, r1, r2, r3, addr) \
    asm volatile("ldmatrix.sync.aligned.m8n8.x4.trans.shared.b16 {%0,%1,%2,%3}, [%4];" \
                 : "=r"(r0), "=r"(r1), "=r"(r2), "=r"(r3) : "r"(addr))

#define MMA_BF16(c, a, b) \
    asm volatile("mma.sync.aligned.m16n8k16.row.col.f32.bf16.bf16.f32 " \
                 "{%0,%1,%2,%3}, {%4,%5,%6,%7}, {%8,%9}, {%0,%1,%2,%3};" \
                 : "+f"((c)[0]), "+f"((c)[1]), "+f"((c)[2]), "+f"((c)[3]) \
                 : "r"((a)[0]), "r"((a)[1]), "r"((a)[2]), "r"((a)[3]), \
                   "r"((b)[0]), "r"((b)[1]))

__device__ __forceinline__ void split2(float x, float y, uint32_t& h, uint32_t& l) {
    __nv_bfloat162 hb = __floats2bfloat162_rn(x, y);
    float2 hf = __bfloat1622float2(hb);
    __nv_bfloat162 lb = __floats2bfloat162_rn(x - hf.x, y - hf.y);
    h = *reinterpret_cast<uint32_t*>(&hb);
    l = *reinterpret_cast<uint32_t*>(&lb);
}

// ---------------------------------------------------------------------------
// prep_all: z=0 hs hi/lo split; z=1..4 weight transpose+split
// ---------------------------------------------------------------------------
__global__ void prep_all(const float* __restrict__ hs,
                         const float* __restrict__ Wq, const float* __restrict__ Wk,
                         const float* __restrict__ Wv, const float* __restrict__ Wo,
                         __nv_bfloat16* __restrict__ hsh, __nv_bfloat16* __restrict__ hsl,
                         __nv_bfloat16* __restrict__ wqh, __nv_bfloat16* __restrict__ wql,
                         __nv_bfloat16* __restrict__ wkh, __nv_bfloat16* __restrict__ wkl,
                         __nv_bfloat16* __restrict__ wvh, __nv_bfloat16* __restrict__ wvl,
                         __nv_bfloat16* __restrict__ woh, __nv_bfloat16* __restrict__ wol) {
    int z = blockIdx.z;
    int tx = threadIdx.x, ty = threadIdx.y;
    if (z == 0) {
        int i = (blockIdx.y * 128 + blockIdx.x) * 256 + ty * 32 + tx;
        float4 s = ((const float4*)hs)[i];
        __nv_bfloat162 h01 = __floats2bfloat162_rn(s.x, s.y);
        __nv_bfloat162 h23 = __floats2bfloat162_rn(s.z, s.w);
        float2 f01 = __bfloat1622float2(h01);
        float2 f23 = __bfloat1622float2(h23);
        __nv_bfloat162 l01 = __floats2bfloat162_rn(s.x - f01.x, s.y - f01.y);
        __nv_bfloat162 l23 = __floats2bfloat162_rn(s.z - f23.x, s.w - f23.y);
        ((__nv_bfloat162*)hsh)[2 * i]     = h01;
        ((__nv_bfloat162*)hsh)[2 * i + 1] = h23;
        ((__nv_bfloat162*)hsl)[2 * i]     = l01;
        ((__nv_bfloat162*)hsl)[2 * i + 1] = l23;
        return;
    }
    const float* W;
    __nv_bfloat16 *hiT, *loT;
    int K, N;
    if (z == 1)      { W = Wq; hiT = wqh; loT = wql; K = HH; N = QD; }
    else if (z == 2) { W = Wk; hiT = wkh; loT = wkl; K = HH; N = KVD; }
    else if (z == 3) { W = Wv; hiT = wvh; loT = wvl; K = HH; N = KVD; }
    else             { W = Wo; hiT = woh; loT = wol; K = QD; N = HH; }
    if (blockIdx.x * 32 >= N || blockIdx.y * 32 >= K) return;

    __shared__ float t[32][33];
    int n0 = blockIdx.x * 32, k0 = blockIdx.y * 32;
#pragma unroll
    for (int i = 0; i < 32; i += 8)
        t[ty + i][tx] = W[(size_t)(k0 + ty + i) * N + n0 + tx];
    __syncthreads();
#pragma unroll
    for (int i = 0; i < 32; i += 8) {
        float v = t[tx][ty + i];
        __nv_bfloat16 h = __float2bfloat16_rn(v);
        __nv_bfloat16 l = __float2bfloat16_rn(v - __bfloat162float(h));
        size_t o = (size_t)(n0 + ty + i) * K + k0 + tx;
        hiT[o] = h;
        loT[o] = l;
    }
}

// ---------------------------------------------------------------------------
// mma.sync bf16x3 GEMM body (unchanged except .ca loads)
// ---------------------------------------------------------------------------
#define TILE_B   10240
#define STAGE_B  (4 * TILE_B)
#define GEMM_SMEM (2 * STAGE_B)

__device__ __forceinline__ void gemm_body(
    const __nv_bfloat16* __restrict__ Ahi, const __nv_bfloat16* __restrict__ Alo,
    const __nv_bfloat16* __restrict__ Bhi, const __nv_bfloat16* __restrict__ Blo,
    float* __restrict__ C, int Nd, int Kd, int bm, int bn, char* smem) {
    const uint32_t sb = smem_u32(smem);
    const int tid = threadIdx.x;
    const int wid = tid >> 5, lid = tid & 31;
    const int wm = wid >> 2, wn = wid & 3;

    float c[4][4][4];
#pragma unroll
    for (int i = 0; i < 4; i++)
#pragma unroll
        for (int j = 0; j < 4; j++)
#pragma unroll
            for (int q = 0; q < 4; q++) c[i][j][q] = 0.f;

    const int rowA = lid & 15;
    const int khA  = (lid >> 4) << 3;
    const int nB   = ((lid >> 4) << 3) + (lid & 7);
    const int khB  = ((lid >> 3) & 1) << 3;

#define LOAD_STAGE(s, k0)                                                     \
    do {                                                                      \
        _Pragma("unroll")                                                     \
        for (int li = 0; li < 2; li++) {                                      \
            int id  = li * 256 + tid;                                         \
            int row = id >> 2, seg = id & 3;                                  \
            uint32_t so = sb + (s) * STAGE_B + row * 80 + seg * 16;           \
            size_t ga = (size_t)(bm + row) * Kd + (k0) + seg * 8;             \
            size_t gb = (size_t)(bn + row) * Kd + (k0) + seg * 8;             \
            cpasync16(so,              Ahi + ga);                             \
            cpasync16(so + TILE_B,     Alo + ga);                             \
            cpasync16(so + 2 * TILE_B, Bhi + gb);                             \
            cpasync16(so + 3 * TILE_B, Blo + gb);                             \
        }                                                                     \
        CP_COMMIT();                                                          \
    } while (0)

    const int nk = Kd >> 5;
    LOAD_STAGE(0, 0);

    for (int kt = 0; kt < nk; kt++) {
        CP_WAIT0();
        __syncthreads();
        if (kt + 1 < nk) LOAD_STAGE((kt + 1) & 1, (kt + 1) << 5);

        const uint32_t abase = sb + (kt & 1) * STAGE_B;
        const uint32_t bbase = abase + 2 * TILE_B;
#pragma unroll
        for (int kk = 0; kk < 32; kk += 16) {
            uint32_t bh[4][2], bl[4][2];
#pragma unroll
            for (int j2 = 0; j2 < 2; j2++) {
                uint32_t ba = bbase + (wn * 32 + j2 * 16 + nB) * 80 +
                              (kk + khB) * 2;
                LDSM4(bh[j2 * 2][0], bh[j2 * 2][1],
                      bh[j2 * 2 + 1][0], bh[j2 * 2 + 1][1], ba);
                LDSM4(bl[j2 * 2][0], bl[j2 * 2][1],
                      bl[j2 * 2 + 1][0], bl[j2 * 2 + 1][1], ba + TILE_B);
            }
            uint32_t ah[4][4], al[4][4];
#pragma unroll
            for (int i = 0; i < 4; i++) {
                uint32_t aa = abase + (wm * 64 + i * 16 + rowA) * 80 +
                              (kk + khA) * 2;
                LDSM4(ah[i][0], ah[i][1], ah[i][2], ah[i][3], aa);
                LDSM4(al[i][0], al[i][1], al[i][2], al[i][3], aa + TILE_B);
            }
#pragma unroll
            for (int i = 0; i < 4; i++)
#pragma unroll
                for (int j = 0; j < 4; j++) MMA_BF16(c[i][j], ah[i], bh[j]);
#pragma unroll
            for (int i = 0; i < 4; i++)
#pragma unroll
                for (int j = 0; j < 4; j++) MMA_BF16(c[i][j], ah[i], bl[j]);
#pragma unroll
            for (int i = 0; i < 4; i++)
#pragma unroll
                for (int j = 0; j < 4; j++) MMA_BF16(c[i][j], al[i], bh[j]);
        }
        __syncthreads();
    }
#undef LOAD_STAGE

    const int g = lid >> 2, t4 = lid & 3;
#pragma unroll
    for (int i = 0; i < 4; i++) {
        int r0 = bm + wm * 64 + i * 16 + g;
#pragma unroll
        for (int j = 0; j < 4; j++) {
            int col = bn + wn * 32 + j * 8 + t4 * 2;
            *(float2*)&C[(size_t)r0 * Nd + col] =
                make_float2(c[i][j][0], c[i][j][1]);
            *(float2*)&C[(size_t)(r0 + 8) * Nd + col] =
                make_float2(c[i][j][2], c[i][j][3]);
        }
    }
}

__global__ __launch_bounds__(256, 2)
void mma_gemm(const __nv_bfloat16* __restrict__ Ahi,
              const __nv_bfloat16* __restrict__ Alo,
              const __nv_bfloat16* __restrict__ Bhi,
              const __nv_bfloat16* __restrict__ Blo,
              float* __restrict__ C, int Nd, int Kd) {
    extern __shared__ char smem[];
    gemm_body(Ahi, Alo, Bhi, Blo, C, Nd, Kd,
              blockIdx.y * 128, blockIdx.x * 128, smem);
}

__global__ __launch_bounds__(256, 2)
void mma_gemm_qkv(const __nv_bfloat16* __restrict__ Ahi,
                  const __nv_bfloat16* __restrict__ Alo,
                  const __nv_bfloat16* __restrict__ wqh, const __nv_bfloat16* __restrict__ wql,
                  const __nv_bfloat16* __restrict__ wkh, const __nv_bfloat16* __restrict__ wkl,
                  const __nv_bfloat16* __restrict__ wvh, const __nv_bfloat16* __restrict__ wvl,
                  float* __restrict__ Cq, float* __restrict__ Ck, float* __restrict__ Cv) {
    extern __shared__ char smem[];
    int bx = blockIdx.x;
    const __nv_bfloat16 *Bh, *Bl;
    float* C;
    int Nd, bn;
    if (bx < 32)      { Bh = wqh; Bl = wql; C = Cq; Nd = QD;  bn = bx * 128; }
    else if (bx < 40) { Bh = wkh; Bl = wkl; C = Ck; Nd = KVD; bn = (bx - 32) * 128; }
    else              { Bh = wvh; Bl = wvl; C = Cv; Nd = KVD; bn = (bx - 40) * 128; }
    gemm_body(Ahi, Alo, Bh, Bl, C, Nd, HH, blockIdx.y * 128, bn, smem);
}

// ---------------------------------------------------------------------------
// rope_all: RoPE+split for Q and K, plain split for V — one launch.
// ---------------------------------------------------------------------------
#define NQR (MR * NH * 64)
#define NKR (MR * NKV * 64)
#define NV4 (MR * KVD / 4)

__global__ void rope_all(const float* __restrict__ qs, const float* __restrict__ ks,
                         const float* __restrict__ vs,
                         __nv_bfloat16* __restrict__ qh, __nv_bfloat16* __restrict__ ql,
                         __nv_bfloat16* __restrict__ kh, __nv_bfloat16* __restrict__ kl,
                         __nv_bfloat16* __restrict__ vh, __nv_bfloat16* __restrict__ vl) {
    int idx = blockIdx.x * blockDim.x + threadIdx.x;
    if (idx < NQR + NKR) {
        const float* buf;
        __nv_bfloat16 *oh, *ol;
        int nheads;
        if (idx < NQR) { buf = qs; oh = qh; ol = ql; nheads = NH; }
        else { idx -= NQR; buf = ks; oh = kh; ol = kl; nheads = NKV; }
        int i    = idx & 63;
        int head = (idx >> 6) % nheads;
        int row  = idx / (nheads << 6);
        float p    = (float)(row % SS);
        float invf = expf(-(float)i * 0.14391156831212787f);
        float ang  = p * invf;
        float c, s;
        sincosf(ang, &s, &c);
        size_t base = (size_t)row * (nheads * HD) + head * HD + i;
        float x0 = buf[base];
        float x1 = buf[base + 64];
        float y0 = x0 * c - x1 * s;
        float y1 = x1 * c + x0 * s;
        __nv_bfloat16 h0 = __float2bfloat16_rn(y0);
        __nv_bfloat16 h1 = __float2bfloat16_rn(y1);
        oh[base]      = h0;
        oh[base + 64] = h1;
        ol[base]      = __float2bfloat16_rn(y0 - __bfloat162float(h0));
        ol[base + 64] = __float2bfloat16_rn(y1 - __bfloat162float(h1));
        return;
    }
    idx -= NQR + NKR;
    if (idx >= NV4) return;
    float4 s = ((const float4*)vs)[idx];
    __nv_bfloat162 h01 = __floats2bfloat162_rn(s.x, s.y);
    __nv_bfloat162 h23 = __floats2bfloat162_rn(s.z, s.w);
    float2 f01 = __bfloat1622float2(h01);
    float2 f23 = __bfloat1622float2(h23);
    ((__nv_bfloat162*)vh)[2 * idx]     = h01;
    ((__nv_bfloat162*)vh)[2 * idx + 1] = h23;
    ((__nv_bfloat162*)vl)[2 * idx]     = __floats2bfloat162_rn(s.x - f01.x, s.y - f01.y);
    ((__nv_bfloat162*)vl)[2 * idx + 1] = __floats2bfloat162_rn(s.z - f23.x, s.w - f23.y);
}

// ---------------------------------------------------------------------------
// Tensor-core causal flash attention, bf16x3, 2 CTAs/SM, warp-local softmax.
// (unchanged from R15 except .ca loads — adjacent q-tile CTAs of the same
// head share K/V tiles, so .ca turns the second CTA's loads into L1 hits)
// ---------------------------------------------------------------------------
#define APITCH 272
#define ATK   (64 * APITCH)            // 17408
#define SKV   (4 * ATK)                // 69632: Kh Kl Vh Vl
#define OFF_KV (2 * ATK)               // 34816
#define OFF_ST (OFF_KV + SKV)          // 104448
#define ATTN_SMEM (OFF_ST + 64 * 8)    // 104960
#define ORP 132

__global__ __launch_bounds__(256, 2)
void attn_mma(const __nv_bfloat16* __restrict__ Qh, const __nv_bfloat16* __restrict__ Ql,
              const __nv_bfloat16* __restrict__ Kh, const __nv_bfloat16* __restrict__ Kl,
              const __nv_bfloat16* __restrict__ Vh, const __nv_bfloat16* __restrict__ Vl,
              __nv_bfloat16* __restrict__ Oh, __nv_bfloat16* __restrict__ Ol) {
    extern __shared__ char smem[];
    const uint32_t sb = smem_u32(smem);
    const int tid = threadIdx.x;
    const int wid = tid >> 5, lid = tid & 31;
    const int g = lid >> 2, t4 = lid & 3;
    const int half = wid >> 2, rw = wid & 3;
    const int qb = gridDim.x - 1 - blockIdx.x;   // big tiles first
    const int h = blockIdx.y, b = blockIdx.z;
    const int kvh = h >> 2;
    const int q0 = qb * 64;

    const uint32_t sQh = sb;
    const uint32_t kvb = sb + OFF_KV;

    // Q tile (64 rows), hi+lo
#pragma unroll
    for (int t = 0; t < 4; t++) {
        int id = t * 256 + tid;
        int row = id >> 4, seg = id & 15;
        uint32_t so = row * APITCH + seg * 16;
        size_t gq = (size_t)(b * SS + q0 + row) * QD + h * HD + seg * 8;
        cpasync16(sQh + so, Qh + gq);
        cpasync16(sQh + ATK + so, Ql + gq);
    }
    CP_COMMIT();

#define LOAD_KV(kt)                                                           \
    do {                                                                      \
        _Pragma("unroll")                                                     \
        for (int t = 0; t < 4; t++) {                                         \
            int id = t * 256 + tid;                                           \
            int row = id >> 4, seg = id & 15;                                 \
            uint32_t so = kvb + row * APITCH + seg * 16;                      \
            size_t gk = (size_t)(b * SS + (kt) * 64 + row) * KVD +            \
                        kvh * HD + seg * 8;                                   \
            cpasync16(so,           Kh + gk);                                 \
            cpasync16(so + ATK,     Kl + gk);                                 \
            cpasync16(so + 2 * ATK, Vh + gk);                                 \
            cpasync16(so + 3 * ATK, Vl + gk);                                 \
        }                                                                     \
        CP_COMMIT();                                                          \
    } while (0)

    float o[16][4];
#pragma unroll
    for (int n = 0; n < 16; n++)
#pragma unroll
        for (int q = 0; q < 4; q++) o[n][q] = 0.f;
    float m[2] = {-1e30f, -1e30f}, l[2] = {0.f, 0.f};

    const int rowA = lid & 15, khA = (lid >> 4) << 3;
    const int nB = ((lid >> 4) << 3) + (lid & 7);
    const int khB = ((lid >> 3) & 1) << 3;
    const int kV = (((lid >> 3) & 1) << 3) + (lid & 7);
    const int nVo = (lid >> 4) << 3;

    const float scale = 0.08838834764831845f;
    const int nkt = qb + 1;

    for (int kt = 0; kt < nkt; kt++) {
        LOAD_KV(kt);
        CP_WAIT0();
        __syncthreads();

        const uint32_t sKh = kvb;
        const uint32_t sVh = kvb + 2 * ATK;
        const int k0t = kt * 64;

        // ---- S (this warp: 32 kv cols at half*32) ----
        float sc[4][4];
#pragma unroll
        for (int j = 0; j < 4; j++)
#pragma unroll
            for (int q = 0; q < 4; q++) sc[j][q] = 0.f;

#pragma unroll
        for (int kk = 0; kk < 8; kk++) {
            uint32_t qhf[4], qlf[4];
            uint32_t qa = sQh + (rw * 16 + rowA) * APITCH + (kk * 16 + khA) * 2;
            LDSM4(qhf[0], qhf[1], qhf[2], qhf[3], qa);
            LDSM4(qlf[0], qlf[1], qlf[2], qlf[3], qa + ATK);
#pragma unroll
            for (int jp = 0; jp < 2; jp++) {
                uint32_t kh0[2], kh1[2], kl0[2], kl1[2];
                uint32_t ka = sKh + (half * 32 + jp * 16 + nB) * APITCH +
                              (kk * 16 + khB) * 2;
                LDSM4(kh0[0], kh0[1], kh1[0], kh1[1], ka);
                LDSM4(kl0[0], kl0[1], kl1[0], kl1[1], ka + ATK);
                MMA_BF16(sc[2 * jp],     qhf, kh0);
                MMA_BF16(sc[2 * jp + 1], qhf, kh1);
                MMA_BF16(sc[2 * jp],     qhf, kl0);
                MMA_BF16(sc[2 * jp + 1], qhf, kl1);
                MMA_BF16(sc[2 * jp],     qlf, kh0);
                MMA_BF16(sc[2 * jp + 1], qlf, kh1);
            }
        }

        // scale + causal mask (diagonal tile only)
#pragma unroll
        for (int j = 0; j < 4; j++)
#pragma unroll
            for (int q = 0; q < 4; q++) sc[j][q] *= scale;
        if (kt == qb) {
            int r0 = q0 + rw * 16 + g, r1 = r0 + 8;
#pragma unroll
            for (int j = 0; j < 4; j++) {
                int c0 = k0t + half * 32 + j * 8 + 2 * t4, c1 = c0 + 1;
                if (c0 > r0) sc[j][0] = -1e30f;
                if (c1 > r0) sc[j][1] = -1e30f;
                if (c0 > r1) sc[j][2] = -1e30f;
                if (c1 > r1) sc[j][3] = -1e30f;
            }
        }

        // ---- warp-local online softmax ----
#pragma unroll
        for (int r = 0; r < 2; r++) {
            float mx = -1e30f;
#pragma unroll
            for (int j = 0; j < 4; j++)
                mx = fmaxf(mx, fmaxf(sc[j][2 * r], sc[j][2 * r + 1]));
            mx = fmaxf(mx, __shfl_xor_sync(0xffffffffu, mx, 1));
            mx = fmaxf(mx, __shfl_xor_sync(0xffffffffu, mx, 2));
            float mn = fmaxf(m[r], mx);
            float safe = (mn > -1e29f) ? 1.f : 0.f;
            float corr = __expf(m[r] - mn);
            m[r] = mn;
            float rs = 0.f;
#pragma unroll
            for (int j = 0; j < 4; j++) {
                float p0 = safe * __expf(sc[j][2 * r] - mn);
                float p1 = safe * __expf(sc[j][2 * r + 1] - mn);
                sc[j][2 * r] = p0;
                sc[j][2 * r + 1] = p1;
                rs += p0 + p1;
            }
            rs += __shfl_xor_sync(0xffffffffu, rs, 1);
            rs += __shfl_xor_sync(0xffffffffu, rs, 2);
            l[r] = l[r] * corr + rs;
#pragma unroll
            for (int n = 0; n < 16; n++) {
                o[n][2 * r] *= corr;
                o[n][2 * r + 1] *= corr;
            }
        }

        // ---- O += P V ----
#pragma unroll
        for (int kc = 0; kc < 2; kc++) {
            uint32_t ah[4], al[4];
            split2(sc[2 * kc][0],     sc[2 * kc][1],     ah[0], al[0]);
            split2(sc[2 * kc][2],     sc[2 * kc][3],     ah[1], al[1]);
            split2(sc[2 * kc + 1][0], sc[2 * kc + 1][1], ah[2], al[2]);
            split2(sc[2 * kc + 1][2], sc[2 * kc + 1][3], ah[3], al[3]);
#pragma unroll
            for (int np = 0; np < 8; np++) {
                uint32_t vh0[2], vh1[2], vl0[2], vl1[2];
                uint32_t va = sVh + (half * 32 + kc * 16 + kV) * APITCH +
                              (np * 16 + nVo) * 2;
                LDSM4T(vh0[0], vh0[1], vh1[0], vh1[1], va);
                LDSM4T(vl0[0], vl0[1], vl1[0], vl1[1], va + ATK);
                MMA_BF16(o[2 * np],     ah, vh0);
                MMA_BF16(o[2 * np + 1], ah, vh1);
                MMA_BF16(o[2 * np],     ah, vl0);
                MMA_BF16(o[2 * np + 1], ah, vl1);
                MMA_BF16(o[2 * np],     al, vh0);
                MMA_BF16(o[2 * np + 1], al, vh1);
            }
        }
        __syncthreads();   // protect KV buffer before next overwrite
    }
#undef LOAD_KV

    // ---- final merge: half0 writes raw (m,l,O); half1 combines & stores ----
    float* ored = (float*)(smem + OFF_KV);
    float* st   = (float*)(smem + OFF_ST);
    if (half == 0) {
        if (t4 == 0) {
#pragma unroll
            for (int r = 0; r < 2; r++) {
                int row = rw * 16 + g + 8 * r;
                st[row * 2]     = m[r];
                st[row * 2 + 1] = l[r];
            }
        }
#pragma unroll
        for (int n = 0; n < 16; n++) {
            int col = n * 8 + 2 * t4;
            int r0 = rw * 16 + g;
            *(float2*)&ored[r0 * ORP + col]       = make_float2(o[n][0], o[n][1]);
            *(float2*)&ored[(r0 + 8) * ORP + col] = make_float2(o[n][2], o[n][3]);
        }
    }
    __syncthreads();
    if (half == 1) {
        float s0[2], s1[2], inv[2];
#pragma unroll
        for (int r = 0; r < 2; r++) {
            int row = rw * 16 + g + 8 * r;
            float m0 = st[row * 2], l0 = st[row * 2 + 1];
            float M = fmaxf(m0, m[r]);
            s0[r] = __expf(m0 - M);
            s1[r] = __expf(m[r] - M);
            inv[r] = 1.f / (l0 * s0[r] + l[r] * s1[r]);
        }
        int r0 = rw * 16 + g;
        size_t r0g = (size_t)(b * SS + q0 + r0) * QD + h * HD;
        size_t r1g = r0g + 8 * QD;
#pragma unroll
        for (int n = 0; n < 16; n++) {
            int col = n * 8 + 2 * t4;
            float2 p0 = *(float2*)&ored[r0 * ORP + col];
            float2 p1 = *(float2*)&ored[(r0 + 8) * ORP + col];
            uint32_t hh, ll;
            split2((p0.x * s0[0] + o[n][0] * s1[0]) * inv[0],
                   (p0.y * s0[0] + o[n][1] * s1[0]) * inv[0], hh, ll);
            *(uint32_t*)&Oh[r0g + col] = hh;
            *(uint32_t*)&Ol[r0g + col] = ll;
            split2((p1.x * s0[1] + o[n][2] * s1[1]) * inv[1],
                   (p1.y * s0[1] + o[n][3] * s1[1]) * inv[1], hh, ll);
            *(uint32_t*)&Oh[r1g + col] = hh;
            *(uint32_t*)&Ol[r1g + col] = ll;
        }
    }
}

// ---------------------------------------------------------------------------
extern "C" void kernel_launch(void* const* d_in, const int* in_sizes, int n_in,
                              void* d_out, int out_size) {
    const float* hs  = (const float*)d_in[0];
    const float* Wq  = (const float*)d_in[2];
    const float* Wk  = (const float*)d_in[3];
    const float* Wv  = (const float*)d_in[4];
    const float* Wo  = (const float*)d_in[5];
    float*       out = (float*)d_out;

    float *qb, *kb, *vb;
    cudaGetSymbolAddress((void**)&qb, g_q);
    cudaGetSymbolAddress((void**)&kb, g_k);
    cudaGetSymbolAddress((void**)&vb, g_v);

    __nv_bfloat16 *hsh, *hsl, *wqh, *wql, *wkh, *wkl, *wvh, *wvl, *woh, *wol, *ath, *atl;
    __nv_bfloat16 *qrh, *qrl, *krh, *krl, *vrh, *vrl;
    cudaGetSymbolAddress((void**)&hsh, g_hs_h);
    cudaGetSymbolAddress((void**)&hsl, g_hs_l);
    cudaGetSymbolAddress((void**)&wqh, g_wqT_h);
    cudaGetSymbolAddress((void**)&wql, g_wqT_l);
    cudaGetSymbolAddress((void**)&wkh, g_wkT_h);
    cudaGetSymbolAddress((void**)&wkl, g_wkT_l);
    cudaGetSymbolAddress((void**)&wvh, g_wvT_h);
    cudaGetSymbolAddress((void**)&wvl, g_wvT_l);
    cudaGetSymbolAddress((void**)&woh, g_woT_h);
    cudaGetSymbolAddress((void**)&wol, g_woT_l);
    cudaGetSymbolAddress((void**)&ath, g_att_h);
    cudaGetSymbolAddress((void**)&atl, g_att_l);
    cudaGetSymbolAddress((void**)&qrh, g_qr_h);
    cudaGetSymbolAddress((void**)&qrl, g_qr_l);
    cudaGetSymbolAddress((void**)&krh, g_kr_h);
    cudaGetSymbolAddress((void**)&krl, g_kr_l);
    cudaGetSymbolAddress((void**)&vrh, g_vr_h);
    cudaGetSymbolAddress((void**)&vrl, g_vr_l);

    cudaFuncSetAttribute(mma_gemm, cudaFuncAttributeMaxDynamicSharedMemorySize, GEMM_SMEM);
    cudaFuncSetAttribute(mma_gemm_qkv, cudaFuncAttributeMaxDynamicSharedMemorySize, GEMM_SMEM);
    cudaFuncSetAttribute(attn_mma, cudaFuncAttributeMaxDynamicSharedMemorySize, ATTN_SMEM);

    // 0: fused prep (hs split + 4 weight transposes)
    prep_all<<<dim3(128, 128, 5), dim3(32, 8)>>>(hs, Wq, Wk, Wv, Wo,
                                                 hsh, hsl, wqh, wql, wkh, wkl,
                                                 wvh, wvl, woh, wol);

    // 1: fused QKV projection
    mma_gemm_qkv<<<dim3(48, MR / 128), 256, GEMM_SMEM>>>(hsh, hsl,
                                                          wqh, wql, wkh, wkl,
                                                          wvh, wvl, qb, kb, vb);

    // 2: RoPE(Q,K) + split(V), fused
    rope_all<<<(NQR + NKR + NV4 + 255) / 256, 256>>>(qb, kb, vb, qrh, qrl,
                                                     krh, krl, vrh, vrl);

    // 3: causal GQA attention (2 CTAs/SM, warp-local softmax, .ca KV loads)
    attn_mma<<<dim3(SS / 64, NH, BB), 256, ATTN_SMEM>>>(qrh, qrl, krh, krl,
                                                         vrh, vrl, ath, atl);

    // 4: O projection
    mma_gemm<<<dim3(HH / 128, MR / 128), 256, GEMM_SMEM>>>(ath, atl, woh, wol, out, HH, QD);
}